// round 1
// baseline (speedup 1.0000x reference)
#include <cuda_runtime.h>
#include <math.h>

// Problem constants
#define B_    32
#define C_    1536
#define HW_   1024      // 32*32
#define HID_  512
#define LDIM_ 128
#define MCL_  64
#define GDIM_ 256
#define OUTD_ (GDIM_ + LDIM_*MCL_)   // 8448
#define EPSV  1e-12f

// -------------------------------------------------------------------------
// Scratch (static __device__ globals: allocation-free, graph-capture safe)
// -------------------------------------------------------------------------
__device__ float g_H[(size_t)B_ * 2 * HID_ * HW_];   // [B, 1024, 1024]  134 MB
__device__ float g_F[(size_t)B_ * LDIM_ * HW_];      // [B, 128, 1024]
__device__ float g_P[(size_t)B_ * MCL_  * HW_];      // [B,  64, 1024]

// -------------------------------------------------------------------------
// Tiled SIMT fp32 GEMM:  C[z] = act(A[M,K] * B[z][K,N] + bias)
// A row-major shared across batch; B/C batched via strides; ldb = ldc = N.
// -------------------------------------------------------------------------
template<int BM, int BN, int BK, int TM, int TN, bool RELU>
__global__ void __launch_bounds__((BM/TM)*(BN/TN))
sgemm_bias(const float* __restrict__ A, const float* __restrict__ Bg,
           const float* __restrict__ bias, float* __restrict__ Cg,
           int K, int N, size_t strideB, size_t strideC)
{
    constexpr int NT = (BM/TM)*(BN/TN);
    const int tid = threadIdx.x;
    const int bn  = blockIdx.x * BN;
    const int bm  = blockIdx.y * BM;
    const float* Bp = Bg + (size_t)blockIdx.z * strideB;
    float*       Cp = Cg + (size_t)blockIdx.z * strideC;

    __shared__ float As[BK][BM];
    __shared__ float Bs[BK][BN];

    // A tile load mapping (float4 along K, then transpose into As[k][m])
    constexpr int A_F4   = (BM*BK)/(4*NT);
    constexpr int A_RSTR = NT/(BK/4);
    const int a_r = tid / (BK/4);
    const int a_c = (tid % (BK/4)) * 4;
    // B tile load mapping (float4 along N)
    constexpr int B_F4   = (BK*BN)/(4*NT);
    constexpr int B_RSTR = NT/(BN/4);
    const int b_r = tid / (BN/4);
    const int b_c = (tid % (BN/4)) * 4;

    const int tr = tid / (BN/TN);
    const int tc = tid % (BN/TN);

    float acc[TM][TN];
    #pragma unroll
    for (int i = 0; i < TM; i++)
        #pragma unroll
        for (int j = 0; j < TN; j++) acc[i][j] = 0.f;

    for (int k0 = 0; k0 < K; k0 += BK) {
        #pragma unroll
        for (int q = 0; q < A_F4; q++) {
            int r = a_r + q * A_RSTR;
            float4 v = *(const float4*)(A + (size_t)(bm + r) * K + k0 + a_c);
            As[a_c + 0][r] = v.x;
            As[a_c + 1][r] = v.y;
            As[a_c + 2][r] = v.z;
            As[a_c + 3][r] = v.w;
        }
        #pragma unroll
        for (int q = 0; q < B_F4; q++) {
            int r = b_r + q * B_RSTR;
            float4 v = *(const float4*)(Bp + (size_t)(k0 + r) * N + bn + b_c);
            *(float4*)(&Bs[r][b_c]) = v;
        }
        __syncthreads();

        #pragma unroll
        for (int kk = 0; kk < BK; kk++) {
            float ra[TM], rb[TN];
            #pragma unroll
            for (int i = 0; i < TM; i++) ra[i] = As[kk][tr*TM + i];
            #pragma unroll
            for (int j = 0; j < TN; j++) rb[j] = Bs[kk][tc*TN + j];
            #pragma unroll
            for (int i = 0; i < TM; i++)
                #pragma unroll
                for (int j = 0; j < TN; j++)
                    acc[i][j] = fmaf(ra[i], rb[j], acc[i][j]);
        }
        __syncthreads();
    }

    #pragma unroll
    for (int i = 0; i < TM; i++) {
        const int row = bm + tr*TM + i;
        const float bv = bias[row];
        #pragma unroll
        for (int j = 0; j < TN; j++) {
            float v = acc[i][j] + bv;
            if (RELU) v = fmaxf(v, 0.f);
            Cp[(size_t)row * N + bn + tc*TN + j] = v;
        }
    }
}

// -------------------------------------------------------------------------
// Token MLP:  tk = relu(t @ w1^T + b1) @ w2^T + b2 ; out[b, :256] = l2norm(tk)
// One CTA per batch row. Warp-cooperative dot products (coalesced weight reads).
// -------------------------------------------------------------------------
__global__ void __launch_bounds__(256)
token_kernel(const float* __restrict__ t,
             const float* __restrict__ w1, const float* __restrict__ b1,
             const float* __restrict__ w2, const float* __restrict__ b2,
             float* __restrict__ out)
{
    const int b = blockIdx.x;
    const int tid = threadIdx.x, warp = tid >> 5, lane = tid & 31;

    __shared__ float ts[C_];
    __shared__ float h[HID_];
    __shared__ float tk[GDIM_];
    __shared__ float red[8];

    for (int i = tid; i < C_; i += 256) ts[i] = t[(size_t)b * C_ + i];
    __syncthreads();

    for (int j = warp; j < HID_; j += 8) {
        const float* wr = w1 + (size_t)j * C_;
        float s = 0.f;
        for (int k = lane * 4; k < C_; k += 128) {
            float4 w4 = *(const float4*)(wr + k);
            float4 t4 = *(const float4*)(ts + k);
            s += w4.x*t4.x + w4.y*t4.y + w4.z*t4.z + w4.w*t4.w;
        }
        #pragma unroll
        for (int o = 16; o; o >>= 1) s += __shfl_xor_sync(0xffffffffu, s, o);
        if (lane == 0) h[j] = fmaxf(s + b1[j], 0.f);
    }
    __syncthreads();

    for (int j = warp; j < GDIM_; j += 8) {
        const float* wr = w2 + (size_t)j * HID_;
        float s = 0.f;
        for (int k = lane * 4; k < HID_; k += 128) {
            float4 w4 = *(const float4*)(wr + k);
            float4 h4 = *(const float4*)(h + k);
            s += w4.x*h4.x + w4.y*h4.y + w4.z*h4.z + w4.w*h4.w;
        }
        #pragma unroll
        for (int o = 16; o; o >>= 1) s += __shfl_xor_sync(0xffffffffu, s, o);
        if (lane == 0) tk[j] = s + b2[j];
    }
    __syncthreads();

    // l2 norm over 256 values (one per thread)
    float v = tk[tid];
    float sq = v * v;
    #pragma unroll
    for (int o = 16; o; o >>= 1) sq += __shfl_xor_sync(0xffffffffu, sq, o);
    if (lane == 0) red[warp] = sq;
    __syncthreads();
    if (warp == 0) {
        float r = (lane < 8) ? red[lane] : 0.f;
        #pragma unroll
        for (int o = 4; o; o >>= 1) r += __shfl_xor_sync(0xffffffffu, r, o);
        if (lane == 0) red[0] = r;
    }
    __syncthreads();
    const float inv = 1.f / fmaxf(sqrtf(red[0]), EPSV);
    out[(size_t)b * OUTD_ + tid] = v * inv;
}

// -------------------------------------------------------------------------
// Log-space Sinkhorn with dustbin. In-place on P (scores -> exp assignment).
// One 1024-thread CTA per batch. m=64, n=1024, +dustbin row (constant alpha).
// -------------------------------------------------------------------------
__global__ void __launch_bounds__(1024)
sinkhorn_kernel(float* __restrict__ Pg, const float* __restrict__ dust)
{
    const int b = blockIdx.x;
    float* Z = Pg + (size_t)b * MCL_ * HW_;
    const int tid = threadIdx.x, warp = tid >> 5, lane = tid & 31;

    __shared__ float u[MCL_ + 1];
    __shared__ float v[HW_];

    const float alpha = dust[0];
    const float norm_c     = -logf((float)(MCL_ + HW_));        // -log(1088)
    const float log_mu     = norm_c;
    const float log_mu_bin = logf((float)(HW_ - MCL_)) + norm_c; // log(960)+norm
    const float log_nu     = norm_c;

    v[tid] = 0.f;
    __syncthreads();

    for (int it = 0; it < 3; it++) {
        // ---- u update: rows of Z (+v) logsumexp over n ----
        for (int i = warp; i < MCL_; i += 32) {
            const float* zr = Z + (size_t)i * HW_;
            float mx = -3.0e38f, s = 0.f;
            for (int j = lane; j < HW_; j += 32) {
                float zv = zr[j] + v[j];
                if (zv > mx) { s = s * __expf(mx - zv) + 1.f; mx = zv; }
                else           s += __expf(zv - mx);
            }
            #pragma unroll
            for (int o = 16; o; o >>= 1) {
                float mo = __shfl_xor_sync(0xffffffffu, mx, o);
                float so = __shfl_xor_sync(0xffffffffu, s,  o);
                float m2 = fmaxf(mx, mo);
                s  = s * __expf(mx - m2) + so * __expf(mo - m2);
                mx = m2;
            }
            if (lane == 0) u[i] = log_mu - (mx + __logf(s));
        }
        if (warp == 0) {  // dustbin row: Z[64,j] = alpha (constant)
            float mx = -3.0e38f, s = 0.f;
            for (int j = lane; j < HW_; j += 32) {
                float zv = v[j];
                if (zv > mx) { s = s * __expf(mx - zv) + 1.f; mx = zv; }
                else           s += __expf(zv - mx);
            }
            #pragma unroll
            for (int o = 16; o; o >>= 1) {
                float mo = __shfl_xor_sync(0xffffffffu, mx, o);
                float so = __shfl_xor_sync(0xffffffffu, s,  o);
                float m2 = fmaxf(mx, mo);
                s  = s * __expf(mx - m2) + so * __expf(mo - m2);
                mx = m2;
            }
            if (lane == 0) u[MCL_] = log_mu_bin - (alpha + mx + __logf(s));
        }
        __syncthreads();

        // ---- v update: columns of Z (+u) logsumexp over m+1 ----
        {
            const int j = tid;
            float mx = alpha + u[MCL_];   // dustbin term first
            float s  = 1.f;
            #pragma unroll 4
            for (int i = 0; i < MCL_; i++) {
                float zv = Z[(size_t)i * HW_ + j] + u[i];
                if (zv > mx) { s = s * __expf(mx - zv) + 1.f; mx = zv; }
                else           s += __expf(zv - mx);
            }
            v[j] = log_nu - (mx + __logf(s));
        }
        __syncthreads();
    }

    // ---- final: P = exp(Z + u + v - norm), dustbin row dropped ----
    {
        const int j = tid;
        const float vj = v[j] - norm_c;
        #pragma unroll 4
        for (int i = 0; i < MCL_; i++) {
            size_t idx = (size_t)i * HW_ + j;
            Z[idx] = __expf(Z[idx] + u[i] + vj);
        }
    }
}

// -------------------------------------------------------------------------
// VLAD aggregation: agg[l,m] = sum_n f[l,n] * p[m,n], per-cluster L2 over l,
// written to out[b, 256 + l*64 + m]. One CTA per batch.
// -------------------------------------------------------------------------
__global__ void __launch_bounds__(256)
agg_kernel(const float* __restrict__ Fg, const float* __restrict__ Pg,
           float* __restrict__ out)
{
    const int b = blockIdx.x;
    const float* f = Fg + (size_t)b * LDIM_ * HW_;
    const float* p = Pg + (size_t)b * MCL_  * HW_;

    __shared__ __align__(16) float sbuf[8384];   // max(phase1, phase2) floats
    float (*Fs)[129] = (float(*)[129])sbuf;               // [32][129]
    float (*Ps)[65]  = (float(*)[65])(sbuf + 32 * 129);   // [32][65]

    const int tid = threadIdx.x;
    const int tr = tid >> 4, tc = tid & 15;   // l base tr*8, m base tc*4

    float acc[8][4];
    #pragma unroll
    for (int i = 0; i < 8; i++)
        #pragma unroll
        for (int j = 0; j < 4; j++) acc[i][j] = 0.f;

    for (int n0 = 0; n0 < HW_; n0 += 32) {
        #pragma unroll
        for (int q = 0; q < 16; q++) {
            int idx = tid + q * 256;
            int l = idx >> 5, n = idx & 31;
            Fs[n][l] = f[(size_t)l * HW_ + n0 + n];
        }
        #pragma unroll
        for (int q = 0; q < 8; q++) {
            int idx = tid + q * 256;
            int m = idx >> 5, n = idx & 31;
            Ps[n][m] = p[(size_t)m * HW_ + n0 + n];
        }
        __syncthreads();

        #pragma unroll
        for (int n = 0; n < 32; n++) {
            float rf[8], rp[4];
            #pragma unroll
            for (int i = 0; i < 8; i++) rf[i] = Fs[n][tr*8 + i];
            #pragma unroll
            for (int j = 0; j < 4; j++) rp[j] = Ps[n][tc*4 + j];
            #pragma unroll
            for (int i = 0; i < 8; i++)
                #pragma unroll
                for (int j = 0; j < 4; j++)
                    acc[i][j] = fmaf(rf[i], rp[j], acc[i][j]);
        }
        __syncthreads();
    }

    // phase 2: per-cluster (over l) L2 norm, then write
    float (*Cs)[65] = (float(*)[65])sbuf;        // [128][65]
    float* nrm = sbuf + 128 * 65;                // [64]
    #pragma unroll
    for (int i = 0; i < 8; i++)
        #pragma unroll
        for (int j = 0; j < 4; j++) Cs[tr*8 + i][tc*4 + j] = acc[i][j];
    __syncthreads();
    if (tid < MCL_) {
        float s = 0.f;
        for (int l = 0; l < LDIM_; l++) { float c = Cs[l][tid]; s += c * c; }
        nrm[tid] = 1.f / fmaxf(sqrtf(s), EPSV);
    }
    __syncthreads();
    float* orow = out + (size_t)b * OUTD_ + GDIM_;
    #pragma unroll
    for (int q = 0; q < 32; q++) {
        int idx = tid + q * 256;
        int l = idx >> 6, m = idx & 63;
        orow[idx] = Cs[l][m] * nrm[m];
    }
}

// -------------------------------------------------------------------------
// Final row L2 normalization over 8448 elements per batch.
// -------------------------------------------------------------------------
__global__ void __launch_bounds__(256)
rownorm_kernel(float* __restrict__ out)
{
    const int b = blockIdx.x;
    float* row = out + (size_t)b * OUTD_;
    const int tid = threadIdx.x, warp = tid >> 5, lane = tid & 31;
    __shared__ float red[8];

    float s = 0.f;
    for (int i = tid; i < OUTD_; i += 256) { float x = row[i]; s += x * x; }
    #pragma unroll
    for (int o = 16; o; o >>= 1) s += __shfl_xor_sync(0xffffffffu, s, o);
    if (lane == 0) red[warp] = s;
    __syncthreads();
    if (warp == 0) {
        float r = (lane < 8) ? red[lane] : 0.f;
        #pragma unroll
        for (int o = 4; o; o >>= 1) r += __shfl_xor_sync(0xffffffffu, r, o);
        if (lane == 0) red[0] = r;
    }
    __syncthreads();
    const float inv = 1.f / fmaxf(sqrtf(red[0]), EPSV);
    for (int i = tid; i < OUTD_; i += 256) row[i] *= inv;
}

// -------------------------------------------------------------------------
// Launch
// -------------------------------------------------------------------------
extern "C" void kernel_launch(void* const* d_in, const int* in_sizes, int n_in,
                              void* d_out, int out_size)
{
    const float* x     = (const float*)d_in[0];
    const float* t     = (const float*)d_in[1];
    const float* cf_w1 = (const float*)d_in[2];
    const float* cf_b1 = (const float*)d_in[3];
    const float* cf_w2 = (const float*)d_in[4];
    const float* cf_b2 = (const float*)d_in[5];
    const float* sc_w1 = (const float*)d_in[6];
    const float* sc_b1 = (const float*)d_in[7];
    const float* sc_w2 = (const float*)d_in[8];
    const float* sc_b2 = (const float*)d_in[9];
    const float* tk_w1 = (const float*)d_in[10];
    const float* tk_b1 = (const float*)d_in[11];
    const float* tk_w2 = (const float*)d_in[12];
    const float* tk_b2 = (const float*)d_in[13];
    const float* dust  = (const float*)d_in[14];
    float* out = (float*)d_out;

    float *H, *F, *P;
    cudaGetSymbolAddress((void**)&H, g_H);
    cudaGetSymbolAddress((void**)&F, g_F);
    cudaGetSymbolAddress((void**)&P, g_P);

    const size_t strideX = (size_t)C_ * HW_;        // x batch stride
    const size_t strideH = (size_t)2 * HID_ * HW_;  // H batch stride

    // Layer 1: H[:, 0:512, :] = relu(cf_w1 @ x + b),  H[:, 512:1024, :] = relu(sc_w1 @ x + b)
    sgemm_bias<128,128,16,8,8,true ><<<dim3(HW_/128, HID_/128, B_), 256>>>(
        cf_w1, x, cf_b1, H,                 C_,  HW_, strideX, strideH);
    sgemm_bias<128,128,16,8,8,true ><<<dim3(HW_/128, HID_/128, B_), 256>>>(
        sc_w1, x, sc_b1, H + HID_*HW_,      C_,  HW_, strideX, strideH);

    // Layer 2: F = cf_w2 @ H_cf + b ;  P = sc_w2 @ H_sc + b
    sgemm_bias<128,128,16,8,8,false><<<dim3(HW_/128, 1, B_), 256>>>(
        cf_w2, H,              cf_b2, F,    HID_, HW_, strideH, (size_t)LDIM_*HW_);
    sgemm_bias< 64,128,16,4,8,false><<<dim3(HW_/128, 1, B_), 256>>>(
        sc_w2, H + HID_*HW_,   sc_b2, P,    HID_, HW_, strideH, (size_t)MCL_*HW_);

    // Token MLP -> out[:, 0:256] (pre-normalized per token vector)
    token_kernel<<<B_, 256>>>(t, tk_w1, tk_b1, tk_w2, tk_b2, out);

    // Sinkhorn OT on P (in place), then VLAD aggregation -> out[:, 256:]
    sinkhorn_kernel<<<B_, 1024>>>(P, dust);
    agg_kernel<<<B_, 256>>>(F, P, out);

    // Final full-row L2 normalization
    rownorm_kernel<<<B_, 256>>>(out);
}

// round 6
// speedup vs baseline: 2.3933x; 2.3933x over previous
#include <cuda_runtime.h>
#include <cuda_bf16.h>
#include <math.h>
#include <stdint.h>

// Problem constants
#define B_    32
#define C_    1536
#define HW_   1024      // 32*32
#define HID_  512
#define LDIM_ 128
#define MCL_  64
#define GDIM_ 256
#define OUTD_ (GDIM_ + LDIM_*MCL_)   // 8448
#define EPSV  1e-12f

// -------------------------------------------------------------------------
// Scratch (__device__ globals: allocation-free, graph-capture safe)
// -------------------------------------------------------------------------
__device__ __align__(256) __nv_bfloat16 g_xT_hi[(size_t)B_ * HW_ * C_];
__device__ __align__(256) __nv_bfloat16 g_xT_lo[(size_t)B_ * HW_ * C_];
__device__ __align__(256) __nv_bfloat16 g_W1hi[1024 * C_];
__device__ __align__(256) __nv_bfloat16 g_W1lo[1024 * C_];
__device__ __align__(256) __nv_bfloat16 g_W2hi[256 * HID_];
__device__ __align__(256) __nv_bfloat16 g_W2lo[256 * HID_];
__device__ __align__(256) float g_b1s[1024];
__device__ __align__(256) float g_b2s[256];
__device__ __align__(256) __nv_bfloat16 g_Ht_hi[(size_t)B_ * HW_ * 1024]; // pixel-major
__device__ __align__(256) __nv_bfloat16 g_Ht_lo[(size_t)B_ * HW_ * 1024];
__device__ __align__(256) float g_F[(size_t)B_ * LDIM_ * HW_];
__device__ __align__(256) float g_P[(size_t)B_ * MCL_  * HW_];

// -------------------------------------------------------------------------
// PTX helpers (family-agnostic: mma.sync / ldmatrix / cp.async)
// -------------------------------------------------------------------------
__device__ __forceinline__ uint32_t smem_u32(const void* p) {
    uint32_t a;
    asm("{ .reg .u64 t; cvta.to.shared.u64 t, %1; cvt.u32.u64 %0, t; }" : "=r"(a) : "l"(p));
    return a;
}
__device__ __forceinline__ void cp16(uint32_t dst, const void* src) {
    asm volatile("cp.async.cg.shared.global [%0], [%1], 16;" :: "r"(dst), "l"(src));
}
#define CP_COMMIT() asm volatile("cp.async.commit_group;" ::: "memory")
#define CP_WAIT(n)  asm volatile("cp.async.wait_group %0;" :: "n"(n) : "memory")

__device__ __forceinline__ void ldsm4(uint32_t* r, uint32_t addr) {
    asm volatile("ldmatrix.sync.aligned.m8n8.x4.shared.b16 {%0,%1,%2,%3}, [%4];"
        : "=r"(r[0]), "=r"(r[1]), "=r"(r[2]), "=r"(r[3]) : "r"(addr));
}
__device__ __forceinline__ void mma16816(float* c, const uint32_t* a, const uint32_t* b) {
    asm volatile(
        "mma.sync.aligned.m16n8k16.row.col.f32.bf16.bf16.f32 "
        "{%0,%1,%2,%3}, {%4,%5,%6,%7}, {%8,%9}, {%0,%1,%2,%3};"
        : "+f"(c[0]), "+f"(c[1]), "+f"(c[2]), "+f"(c[3])
        : "r"(a[0]), "r"(a[1]), "r"(a[2]), "r"(a[3]), "r"(b[0]), "r"(b[1]));
}
__device__ __forceinline__ uint32_t swz(uint32_t off) {      // SW128-style 16B-chunk XOR
    return off ^ ((off >> 3) & 0x70);
}

// -------------------------------------------------------------------------
// Weight prep: stack + hi/lo split
// -------------------------------------------------------------------------
__global__ void prep_w1(const float* __restrict__ cf_w1, const float* __restrict__ cf_b1,
                        const float* __restrict__ sc_w1, const float* __restrict__ sc_b1)
{
    const int r = blockIdx.x;               // 0..1023
    const float* src = (r < HID_) ? cf_w1 + (size_t)r * C_ : sc_w1 + (size_t)(r - HID_) * C_;
    for (int i = threadIdx.x; i < C_; i += blockDim.x) {
        float v = src[i];
        __nv_bfloat16 h = __float2bfloat16(v);
        g_W1hi[(size_t)r * C_ + i] = h;
        g_W1lo[(size_t)r * C_ + i] = __float2bfloat16(v - __bfloat162float(h));
    }
    if (threadIdx.x == 0)
        g_b1s[r] = (r < HID_) ? cf_b1[r] : sc_b1[r - HID_];
}

__global__ void prep_w2(const float* __restrict__ cf_w2, const float* __restrict__ cf_b2,
                        const float* __restrict__ sc_w2, const float* __restrict__ sc_b2)
{
    const int r = blockIdx.x;               // 0..255
    const float* src = (r < LDIM_) ? cf_w2 + (size_t)r * HID_
                     : (r < LDIM_ + MCL_) ? sc_w2 + (size_t)(r - LDIM_) * HID_ : nullptr;
    for (int i = threadIdx.x; i < HID_; i += blockDim.x) {
        float v = src ? src[i] : 0.f;
        __nv_bfloat16 h = __float2bfloat16(v);
        g_W2hi[(size_t)r * HID_ + i] = h;
        g_W2lo[(size_t)r * HID_ + i] = __float2bfloat16(v - __bfloat162float(h));
    }
    if (threadIdx.x == 0)
        g_b2s[r] = (r < LDIM_) ? cf_b2[r] : (r < LDIM_ + MCL_) ? sc_b2[r - LDIM_] : 0.f;
}

// -------------------------------------------------------------------------
// x [B, C, HW] fp32  ->  xT [B, HW, C] bf16 hi/lo  (32x32 smem transpose)
// -------------------------------------------------------------------------
__global__ void __launch_bounds__(256)
transpose_split_x(const float* __restrict__ x)
{
    __shared__ float s[32][33];
    const int n0 = blockIdx.x * 32;
    const int c0 = blockIdx.y * 32;
    const int b  = blockIdx.z;
    const int tx = threadIdx.x & 31, ty = threadIdx.x >> 5;

    #pragma unroll
    for (int q = 0; q < 4; q++) {
        int c = ty + q * 8;
        s[c][tx] = x[((size_t)b * C_ + c0 + c) * HW_ + n0 + tx];
    }
    __syncthreads();
    #pragma unroll
    for (int q = 0; q < 4; q++) {
        int n = ty + q * 8;
        float v = s[tx][n];
        __nv_bfloat16 h = __float2bfloat16(v);
        size_t idx = ((size_t)b * HW_ + n0 + n) * C_ + c0 + tx;
        g_xT_hi[idx] = h;
        g_xT_lo[idx] = __float2bfloat16(v - __bfloat162float(h));
    }
}

// -------------------------------------------------------------------------
// Tensor-core GEMM via mma.sync:  D[m,n] = sum_k A[m,k]*B[n,k]
// 3-pass bf16 hi/lo, fp32 accum. CTA 128x128, 8 warps @ 64x32, BK=64.
// k-loop deliberately NOT unrolled (#pragma unroll 1): keeps SASS small and
// ptxas fast (prior full-unroll build suspected of hitting container timeout).
// EPI=1: bias+relu -> bf16 hi/lo split -> pixel-major Ht (via smem transpose).
// EPI=2: bias -> fp32 F (rows<128) / P (rows 128..191), channel-major.
// -------------------------------------------------------------------------
#define STAGE_BYTES 65536                        // Ahi,Alo,Bhi,Blo @16KB each
#define GEMM_SMEM   (1024 + 2 * STAGE_BYTES)     // 132096

template<int KDIM, int BSTR, int EPI>
__global__ void __launch_bounds__(256)
gemm_mma(const __nv_bfloat16* __restrict__ Ahi, const __nv_bfloat16* __restrict__ Alo,
         const __nv_bfloat16* __restrict__ Bhi, const __nv_bfloat16* __restrict__ Blo,
         const float* __restrict__ bias,
         __nv_bfloat16* __restrict__ OutHi, __nv_bfloat16* __restrict__ OutLo,
         float* __restrict__ OutF, float* __restrict__ OutP)
{
    constexpr int NCHUNK = KDIM / 64;
    extern __shared__ __align__(1024) char smem[];
    const uint32_t sbase = smem_u32(smem);
    float* bias_s = (float*)smem;                 // 128 floats

    const int tid  = threadIdx.x;
    const int wid  = tid >> 5, lane = tid & 31;
    const int n0   = blockIdx.x * 128;
    const int m0   = blockIdx.y * 128;
    const int bz   = blockIdx.z;
    const int koff = (EPI == 2) ? blockIdx.y * 512 : 0;

    const int warp_m = (wid >> 2) * 64;           // 0 or 64
    const int warp_n = (wid & 3) * 32;            // 0,32,64,96

    if (tid < 128) bias_s[tid] = bias[m0 + tid];

    const size_t bRow = (size_t)bz * HW_ + n0;

    // ---- stage loader: 16 cp.async per thread ----
    auto load_stage = [&](int c, int stage) {
        const uint32_t base = sbase + 1024 + stage * STAGE_BYTES;
        #pragma unroll
        for (int h = 0; h < 2; h++) {
            const __nv_bfloat16* Ag = h ? Alo : Ahi;
            const uint32_t abuf = base + h * 16384;
            #pragma unroll
            for (int q = 0; q < 4; q++) {
                int idx = tid + q * 256;            // 1024 chunks of 16B
                int row = idx >> 3, seg = idx & 7;
                cp16(abuf + swz(row * 128 + seg * 16),
                     Ag + (size_t)(m0 + row) * KDIM + c * 64 + seg * 8);
            }
        }
        #pragma unroll
        for (int h = 0; h < 2; h++) {
            const __nv_bfloat16* Bg = h ? Blo : Bhi;
            const uint32_t bbuf = base + 32768 + h * 16384;
            #pragma unroll
            for (int q = 0; q < 4; q++) {
                int idx = tid + q * 256;
                int row = idx >> 3, seg = idx & 7;
                cp16(bbuf + swz(row * 128 + seg * 16),
                     Bg + (bRow + row) * BSTR + koff + c * 64 + seg * 8);
            }
        }
        CP_COMMIT();
    };

    float acc[4][4][4];
    #pragma unroll
    for (int i = 0; i < 4; i++)
        #pragma unroll
        for (int j = 0; j < 4; j++)
            #pragma unroll
            for (int r = 0; r < 4; r++) acc[i][j][r] = 0.f;

    load_stage(0, 0);

    #pragma unroll 1
    for (int c = 0; c < NCHUNK; c++) {
        const int cur = c & 1;
        if (c + 1 < NCHUNK) { load_stage(c + 1, 1 - cur); CP_WAIT(1); }
        else                { CP_WAIT(0); }
        __syncthreads();

        const uint32_t aBase = sbase + 1024 + cur * STAGE_BYTES;
        const uint32_t bBase = aBase + 32768;

        #pragma unroll
        for (int s = 0; s < 4; s++) {
            uint32_t ah[4][4], al[4][4], bh[4][2], bl[4][2];
            // A fragments (hi+lo): 16x16 blocks, rows m-local
            #pragma unroll
            for (int mb = 0; mb < 4; mb++) {
                int row = warp_m + mb * 16 + (lane & 15);
                uint32_t off = swz(row * 128 + s * 32 + ((lane >> 4) << 4));
                ldsm4(ah[mb], aBase + off);
                ldsm4(al[mb], aBase + 16384 + off);
            }
            // B fragments (hi+lo): two 8-col blocks per x4
            #pragma unroll
            for (int nbp = 0; nbp < 2; nbp++) {
                int grp = lane >> 3;
                int row = warp_n + nbp * 16 + ((grp >> 1) << 3) + (lane & 7);
                uint32_t off = swz(row * 128 + s * 32 + ((grp & 1) << 4));
                uint32_t t[4];
                ldsm4(t, bBase + off);
                bh[nbp*2][0] = t[0]; bh[nbp*2][1] = t[1];
                bh[nbp*2+1][0] = t[2]; bh[nbp*2+1][1] = t[3];
                ldsm4(t, bBase + 16384 + off);
                bl[nbp*2][0] = t[0]; bl[nbp*2][1] = t[1];
                bl[nbp*2+1][0] = t[2]; bl[nbp*2+1][1] = t[3];
            }
            // 3 passes: Ah*Bh + Ah*Bl + Al*Bh
            #pragma unroll
            for (int mb = 0; mb < 4; mb++)
                #pragma unroll
                for (int nb = 0; nb < 4; nb++) mma16816(acc[mb][nb], ah[mb], bh[nb]);
            #pragma unroll
            for (int mb = 0; mb < 4; mb++)
                #pragma unroll
                for (int nb = 0; nb < 4; nb++) mma16816(acc[mb][nb], ah[mb], bl[nb]);
            #pragma unroll
            for (int mb = 0; mb < 4; mb++)
                #pragma unroll
                for (int nb = 0; nb < 4; nb++) mma16816(acc[mb][nb], al[mb], bh[nb]);
        }
        __syncthreads();
    }

    // ---------------- epilogue ----------------
    const int qr = lane >> 2, qc = (lane & 3) * 2;

    if (EPI == 1) {
        // stage to smem transposed: sC[n][m], pitch 132
        float* sC = (float*)(smem + 1024);
        #pragma unroll
        for (int mb = 0; mb < 4; mb++)
            #pragma unroll
            for (int nb = 0; nb < 4; nb++)
                #pragma unroll
                for (int r = 0; r < 4; r++) {
                    int m = warp_m + mb * 16 + qr + ((r >> 1) << 3);
                    int n = warp_n + nb * 8 + qc + (r & 1);
                    sC[n * 132 + m] = fmaxf(acc[mb][nb][r] + bias_s[m], 0.f);
                }
        __syncthreads();
        #pragma unroll
        for (int q = 0; q < 8; q++) {
            int idx = tid + q * 256;                // 2048 = 128px * 16 segs
            int px = idx >> 4, sg = idx & 15;
            const float* src = sC + px * 132 + sg * 8;
            __nv_bfloat16 hi[8], lo[8];
            #pragma unroll
            for (int j = 0; j < 8; j++) {
                float v = src[j];
                hi[j] = __float2bfloat16(v);
                lo[j] = __float2bfloat16(v - __bfloat162float(hi[j]));
            }
            size_t g = ((size_t)bz * HW_ + n0 + px) * 1024 + m0 + sg * 8;
            *(uint4*)(OutHi + g) = *(const uint4*)hi;
            *(uint4*)(OutLo + g) = *(const uint4*)lo;
        }
    } else {
        // direct fp32 store, channel-major
        #pragma unroll
        for (int mb = 0; mb < 4; mb++)
            #pragma unroll
            for (int nb = 0; nb < 4; nb++)
                #pragma unroll
                for (int r = 0; r < 4; r++) {
                    int ml = warp_m + mb * 16 + qr + ((r >> 1) << 3);
                    int n  = warp_n + nb * 8 + qc + (r & 1);
                    int row = m0 + ml;
                    float v = acc[mb][nb][r] + bias_s[ml];
                    if (row < LDIM_)
                        OutF[((size_t)bz * LDIM_ + row) * HW_ + n0 + n] = v;
                    else if (row < LDIM_ + MCL_)
                        OutP[((size_t)bz * MCL_ + row - LDIM_) * HW_ + n0 + n] = v;
                }
    }
}

// -------------------------------------------------------------------------
// Token MLP (unchanged, passing since R1)
// -------------------------------------------------------------------------
__global__ void __launch_bounds__(256)
token_kernel(const float* __restrict__ t,
             const float* __restrict__ w1, const float* __restrict__ b1,
             const float* __restrict__ w2, const float* __restrict__ b2,
             float* __restrict__ out)
{
    const int b = blockIdx.x;
    const int tid = threadIdx.x, warp = tid >> 5, lane = tid & 31;

    __shared__ float ts[C_];
    __shared__ float h[HID_];
    __shared__ float tk[GDIM_];
    __shared__ float red[8];

    for (int i = tid; i < C_; i += 256) ts[i] = t[(size_t)b * C_ + i];
    __syncthreads();

    for (int j = warp; j < HID_; j += 8) {
        const float* wr = w1 + (size_t)j * C_;
        float s = 0.f;
        for (int k = lane * 4; k < C_; k += 128) {
            float4 w4 = *(const float4*)(wr + k);
            float4 t4 = *(const float4*)(ts + k);
            s += w4.x*t4.x + w4.y*t4.y + w4.z*t4.z + w4.w*t4.w;
        }
        #pragma unroll
        for (int o = 16; o; o >>= 1) s += __shfl_xor_sync(0xffffffffu, s, o);
        if (lane == 0) h[j] = fmaxf(s + b1[j], 0.f);
    }
    __syncthreads();

    for (int j = warp; j < GDIM_; j += 8) {
        const float* wr = w2 + (size_t)j * HID_;
        float s = 0.f;
        for (int k = lane * 4; k < HID_; k += 128) {
            float4 w4 = *(const float4*)(wr + k);
            float4 h4 = *(const float4*)(h + k);
            s += w4.x*h4.x + w4.y*h4.y + w4.z*h4.z + w4.w*h4.w;
        }
        #pragma unroll
        for (int o = 16; o; o >>= 1) s += __shfl_xor_sync(0xffffffffu, s, o);
        if (lane == 0) tk[j] = s + b2[j];
    }
    __syncthreads();

    float v = tk[tid];
    float sq = v * v;
    #pragma unroll
    for (int o = 16; o; o >>= 1) sq += __shfl_xor_sync(0xffffffffu, sq, o);
    if (lane == 0) red[warp] = sq;
    __syncthreads();
    if (warp == 0) {
        float r = (lane < 8) ? red[lane] : 0.f;
        #pragma unroll
        for (int o = 4; o; o >>= 1) r += __shfl_xor_sync(0xffffffffu, r, o);
        if (lane == 0) red[0] = r;
    }
    __syncthreads();
    const float inv = 1.f / fmaxf(sqrtf(red[0]), EPSV);
    out[(size_t)b * OUTD_ + tid] = v * inv;
}

// -------------------------------------------------------------------------
// Log-space Sinkhorn (unchanged, passing since R1)
// -------------------------------------------------------------------------
__global__ void __launch_bounds__(1024)
sinkhorn_kernel(float* __restrict__ Pg, const float* __restrict__ dust)
{
    const int b = blockIdx.x;
    float* Z = Pg + (size_t)b * MCL_ * HW_;
    const int tid = threadIdx.x, warp = tid >> 5, lane = tid & 31;

    __shared__ float u[MCL_ + 1];
    __shared__ float v[HW_];

    const float alpha = dust[0];
    const float norm_c     = -logf((float)(MCL_ + HW_));
    const float log_mu     = norm_c;
    const float log_mu_bin = logf((float)(HW_ - MCL_)) + norm_c;
    const float log_nu     = norm_c;

    v[tid] = 0.f;
    __syncthreads();

    for (int it = 0; it < 3; it++) {
        for (int i = warp; i < MCL_; i += 32) {
            const float* zr = Z + (size_t)i * HW_;
            float mx = -3.0e38f, s = 0.f;
            for (int j = lane; j < HW_; j += 32) {
                float zv = zr[j] + v[j];
                if (zv > mx) { s = s * __expf(mx - zv) + 1.f; mx = zv; }
                else           s += __expf(zv - mx);
            }
            #pragma unroll
            for (int o = 16; o; o >>= 1) {
                float mo = __shfl_xor_sync(0xffffffffu, mx, o);
                float so = __shfl_xor_sync(0xffffffffu, s,  o);
                float m2 = fmaxf(mx, mo);
                s  = s * __expf(mx - m2) + so * __expf(mo - m2);
                mx = m2;
            }
            if (lane == 0) u[i] = log_mu - (mx + __logf(s));
        }
        if (warp == 0) {
            float mx = -3.0e38f, s = 0.f;
            for (int j = lane; j < HW_; j += 32) {
                float zv = v[j];
                if (zv > mx) { s = s * __expf(mx - zv) + 1.f; mx = zv; }
                else           s += __expf(zv - mx);
            }
            #pragma unroll
            for (int o = 16; o; o >>= 1) {
                float mo = __shfl_xor_sync(0xffffffffu, mx, o);
                float so = __shfl_xor_sync(0xffffffffu, s,  o);
                float m2 = fmaxf(mx, mo);
                s  = s * __expf(mx - m2) + so * __expf(mo - m2);
                mx = m2;
            }
            if (lane == 0) u[MCL_] = log_mu_bin - (alpha + mx + __logf(s));
        }
        __syncthreads();

        {
            const int j = tid;
            float mx = alpha + u[MCL_];
            float s  = 1.f;
            #pragma unroll 4
            for (int i = 0; i < MCL_; i++) {
                float zv = Z[(size_t)i * HW_ + j] + u[i];
                if (zv > mx) { s = s * __expf(mx - zv) + 1.f; mx = zv; }
                else           s += __expf(zv - mx);
            }
            v[j] = log_nu - (mx + __logf(s));
        }
        __syncthreads();
    }

    {
        const int j = tid;
        const float vj = v[j] - norm_c;
        #pragma unroll 4
        for (int i = 0; i < MCL_; i++) {
            size_t idx = (size_t)i * HW_ + j;
            Z[idx] = __expf(Z[idx] + u[i] + vj);
        }
    }
}

// -------------------------------------------------------------------------
// VLAD aggregation + per-cluster L2 (unchanged, passing since R1)
// -------------------------------------------------------------------------
__global__ void __launch_bounds__(256)
agg_kernel(const float* __restrict__ Fg, const float* __restrict__ Pg,
           float* __restrict__ out)
{
    const int b = blockIdx.x;
    const float* f = Fg + (size_t)b * LDIM_ * HW_;
    const float* p = Pg + (size_t)b * MCL_  * HW_;

    __shared__ __align__(16) float sbuf[8384];
    float (*Fs)[129] = (float(*)[129])sbuf;
    float (*Ps)[65]  = (float(*)[65])(sbuf + 32 * 129);

    const int tid = threadIdx.x;
    const int tr = tid >> 4, tc = tid & 15;

    float acc[8][4];
    #pragma unroll
    for (int i = 0; i < 8; i++)
        #pragma unroll
        for (int j = 0; j < 4; j++) acc[i][j] = 0.f;

    for (int n0 = 0; n0 < HW_; n0 += 32) {
        #pragma unroll
        for (int q = 0; q < 16; q++) {
            int idx = tid + q * 256;
            int l = idx >> 5, n = idx & 31;
            Fs[n][l] = f[(size_t)l * HW_ + n0 + n];
        }
        #pragma unroll
        for (int q = 0; q < 8; q++) {
            int idx = tid + q * 256;
            int m = idx >> 5, n = idx & 31;
            Ps[n][m] = p[(size_t)m * HW_ + n0 + n];
        }
        __syncthreads();

        #pragma unroll
        for (int n = 0; n < 32; n++) {
            float rf[8], rp[4];
            #pragma unroll
            for (int i = 0; i < 8; i++) rf[i] = Fs[n][tr*8 + i];
            #pragma unroll
            for (int j = 0; j < 4; j++) rp[j] = Ps[n][tc*4 + j];
            #pragma unroll
            for (int i = 0; i < 8; i++)
                #pragma unroll
                for (int j = 0; j < 4; j++)
                    acc[i][j] = fmaf(rf[i], rp[j], acc[i][j]);
        }
        __syncthreads();
    }

    float (*Cs)[65] = (float(*)[65])sbuf;
    float* nrm = sbuf + 128 * 65;
    #pragma unroll
    for (int i = 0; i < 8; i++)
        #pragma unroll
        for (int j = 0; j < 4; j++) Cs[tr*8 + i][tc*4 + j] = acc[i][j];
    __syncthreads();
    if (tid < MCL_) {
        float s = 0.f;
        for (int l = 0; l < LDIM_; l++) { float c = Cs[l][tid]; s += c * c; }
        nrm[tid] = 1.f / fmaxf(sqrtf(s), EPSV);
    }
    __syncthreads();
    float* orow = out + (size_t)b * OUTD_ + GDIM_;
    #pragma unroll
    for (int q = 0; q < 32; q++) {
        int idx = tid + q * 256;
        int l = idx >> 6, m = idx & 63;
        orow[idx] = Cs[l][m] * nrm[m];
    }
}

// -------------------------------------------------------------------------
// Final row L2 normalization (unchanged, passing since R1)
// -------------------------------------------------------------------------
__global__ void __launch_bounds__(256)
rownorm_kernel(float* __restrict__ out)
{
    const int b = blockIdx.x;
    float* row = out + (size_t)b * OUTD_;
    const int tid = threadIdx.x, warp = tid >> 5, lane = tid & 31;
    __shared__ float red[8];

    float s = 0.f;
    for (int i = tid; i < OUTD_; i += 256) { float x = row[i]; s += x * x; }
    #pragma unroll
    for (int o = 16; o; o >>= 1) s += __shfl_xor_sync(0xffffffffu, s, o);
    if (lane == 0) red[warp] = s;
    __syncthreads();
    if (warp == 0) {
        float r = (lane < 8) ? red[lane] : 0.f;
        #pragma unroll
        for (int o = 4; o; o >>= 1) r += __shfl_xor_sync(0xffffffffu, r, o);
        if (lane == 0) red[0] = r;
    }
    __syncthreads();
    const float inv = 1.f / fmaxf(sqrtf(red[0]), EPSV);
    for (int i = tid; i < OUTD_; i += 256) row[i] *= inv;
}

// -------------------------------------------------------------------------
// Launch
// -------------------------------------------------------------------------
extern "C" void kernel_launch(void* const* d_in, const int* in_sizes, int n_in,
                              void* d_out, int out_size)
{
    const float* x     = (const float*)d_in[0];
    const float* t     = (const float*)d_in[1];
    const float* cf_w1 = (const float*)d_in[2];
    const float* cf_b1 = (const float*)d_in[3];
    const float* cf_w2 = (const float*)d_in[4];
    const float* cf_b2 = (const float*)d_in[5];
    const float* sc_w1 = (const float*)d_in[6];
    const float* sc_b1 = (const float*)d_in[7];
    const float* sc_w2 = (const float*)d_in[8];
    const float* sc_b2 = (const float*)d_in[9];
    const float* tk_w1 = (const float*)d_in[10];
    const float* tk_b1 = (const float*)d_in[11];
    const float* tk_w2 = (const float*)d_in[12];
    const float* tk_b2 = (const float*)d_in[13];
    const float* dust  = (const float*)d_in[14];
    float* out = (float*)d_out;

    __nv_bfloat16 *xTh, *xTl, *W1h, *W1l, *W2h, *W2l, *Hth, *Htl;
    float *b1s, *b2s, *F, *P;
    cudaGetSymbolAddress((void**)&xTh, g_xT_hi);
    cudaGetSymbolAddress((void**)&xTl, g_xT_lo);
    cudaGetSymbolAddress((void**)&W1h, g_W1hi);
    cudaGetSymbolAddress((void**)&W1l, g_W1lo);
    cudaGetSymbolAddress((void**)&W2h, g_W2hi);
    cudaGetSymbolAddress((void**)&W2l, g_W2lo);
    cudaGetSymbolAddress((void**)&Hth, g_Ht_hi);
    cudaGetSymbolAddress((void**)&Htl, g_Ht_lo);
    cudaGetSymbolAddress((void**)&b1s, g_b1s);
    cudaGetSymbolAddress((void**)&b2s, g_b2s);
    cudaGetSymbolAddress((void**)&F,   g_F);
    cudaGetSymbolAddress((void**)&P,   g_P);

    cudaFuncSetAttribute(gemm_mma<1536, 1536, 1>,
                         cudaFuncAttributeMaxDynamicSharedMemorySize, GEMM_SMEM);
    cudaFuncSetAttribute(gemm_mma<512, 1024, 2>,
                         cudaFuncAttributeMaxDynamicSharedMemorySize, GEMM_SMEM);

    // Prep: weight stacking/splitting + x transpose/split
    prep_w1<<<1024, 256>>>(cf_w1, cf_b1, sc_w1, sc_b1);
    prep_w2<<<256, 128>>>(cf_w2, cf_b2, sc_w2, sc_b2);
    transpose_split_x<<<dim3(HW_/32, C_/32, B_), 256>>>(x);

    // Layer 1 (fused cf+sc): Ht[b, px, 1024ch] = relu(W1 @ x + b1), bf16 hi/lo
    gemm_mma<1536, 1536, 1><<<dim3(HW_/128, 1024/128, B_), 256, GEMM_SMEM>>>(
        W1h, W1l, xTh, xTl, b1s, Hth, Htl, nullptr, nullptr);

    // Layer 2 (fused cf+sc): F fp32 [B,128,HW], P fp32 [B,64,HW]
    gemm_mma<512, 1024, 2><<<dim3(HW_/128, 2, B_), 256, GEMM_SMEM>>>(
        W2h, W2l, Hth, Htl, b2s, nullptr, nullptr, F, P);

    // Token MLP -> out[:, 0:256]
    token_kernel<<<B_, 256>>>(t, tk_w1, tk_b1, tk_w2, tk_b2, out);

    // Sinkhorn + VLAD aggregation + final norm
    sinkhorn_kernel<<<B_, 1024>>>(P, dust);
    agg_kernel<<<B_, 256>>>(F, P, out);
    rownorm_kernel<<<B_, 256>>>(out);
}

// round 7
// speedup vs baseline: 2.5316x; 1.0578x over previous
#include <cuda_runtime.h>
#include <cuda_bf16.h>
#include <math.h>
#include <stdint.h>

// Problem constants
#define B_    32
#define C_    1536
#define HW_   1024      // 32*32
#define HID_  512
#define LDIM_ 128
#define MCL_  64
#define GDIM_ 256
#define OUTD_ (GDIM_ + LDIM_*MCL_)   // 8448
#define EPSV  1e-12f

// -------------------------------------------------------------------------
// Scratch (__device__ globals: allocation-free, graph-capture safe)
// -------------------------------------------------------------------------
__device__ __align__(256) __nv_bfloat16 g_xT_hi[(size_t)B_ * HW_ * C_];
__device__ __align__(256) __nv_bfloat16 g_xT_lo[(size_t)B_ * HW_ * C_];
__device__ __align__(256) __nv_bfloat16 g_W1hi[1024 * C_];
__device__ __align__(256) __nv_bfloat16 g_W1lo[1024 * C_];
__device__ __align__(256) __nv_bfloat16 g_W2hi[256 * HID_];
__device__ __align__(256) __nv_bfloat16 g_W2lo[256 * HID_];
__device__ __align__(256) float g_b1s[1024];
__device__ __align__(256) float g_b2s[256];
__device__ __align__(256) __nv_bfloat16 g_Ht_hi[(size_t)B_ * HW_ * 1024]; // pixel-major
__device__ __align__(256) __nv_bfloat16 g_Ht_lo[(size_t)B_ * HW_ * 1024];
__device__ __align__(256) float g_F[(size_t)B_ * LDIM_ * HW_];
__device__ __align__(256) float g_P[(size_t)B_ * MCL_  * HW_];
__device__ __align__(256) float g_aggp[4 * B_ * LDIM_ * MCL_];            // 4 HW-slices

// -------------------------------------------------------------------------
// PTX helpers (family-agnostic: mma.sync / ldmatrix / cp.async)
// -------------------------------------------------------------------------
__device__ __forceinline__ uint32_t smem_u32(const void* p) {
    uint32_t a;
    asm("{ .reg .u64 t; cvta.to.shared.u64 t, %1; cvt.u32.u64 %0, t; }" : "=r"(a) : "l"(p));
    return a;
}
__device__ __forceinline__ void cp16(uint32_t dst, const void* src) {
    asm volatile("cp.async.cg.shared.global [%0], [%1], 16;" :: "r"(dst), "l"(src));
}
#define CP_COMMIT() asm volatile("cp.async.commit_group;" ::: "memory")
#define CP_WAIT(n)  asm volatile("cp.async.wait_group %0;" :: "n"(n) : "memory")

__device__ __forceinline__ void ldsm4(uint32_t* r, uint32_t addr) {
    asm volatile("ldmatrix.sync.aligned.m8n8.x4.shared.b16 {%0,%1,%2,%3}, [%4];"
        : "=r"(r[0]), "=r"(r[1]), "=r"(r[2]), "=r"(r[3]) : "r"(addr));
}
__device__ __forceinline__ void mma16816(float* c, const uint32_t* a, const uint32_t* b) {
    asm volatile(
        "mma.sync.aligned.m16n8k16.row.col.f32.bf16.bf16.f32 "
        "{%0,%1,%2,%3}, {%4,%5,%6,%7}, {%8,%9}, {%0,%1,%2,%3};"
        : "+f"(c[0]), "+f"(c[1]), "+f"(c[2]), "+f"(c[3])
        : "r"(a[0]), "r"(a[1]), "r"(a[2]), "r"(a[3]), "r"(b[0]), "r"(b[1]));
}
__device__ __forceinline__ uint32_t swz(uint32_t off) {      // SW128-style 16B-chunk XOR
    return off ^ ((off >> 3) & 0x70);
}

// -------------------------------------------------------------------------
// Weight prep: stack + hi/lo split
// -------------------------------------------------------------------------
__global__ void prep_w1(const float* __restrict__ cf_w1, const float* __restrict__ cf_b1,
                        const float* __restrict__ sc_w1, const float* __restrict__ sc_b1)
{
    const int r = blockIdx.x;               // 0..1023
    const float* src = (r < HID_) ? cf_w1 + (size_t)r * C_ : sc_w1 + (size_t)(r - HID_) * C_;
    for (int i = threadIdx.x; i < C_; i += blockDim.x) {
        float v = src[i];
        __nv_bfloat16 h = __float2bfloat16(v);
        g_W1hi[(size_t)r * C_ + i] = h;
        g_W1lo[(size_t)r * C_ + i] = __float2bfloat16(v - __bfloat162float(h));
    }
    if (threadIdx.x == 0)
        g_b1s[r] = (r < HID_) ? cf_b1[r] : sc_b1[r - HID_];
}

__global__ void prep_w2(const float* __restrict__ cf_w2, const float* __restrict__ cf_b2,
                        const float* __restrict__ sc_w2, const float* __restrict__ sc_b2)
{
    const int r = blockIdx.x;               // 0..255
    const float* src = (r < LDIM_) ? cf_w2 + (size_t)r * HID_
                     : (r < LDIM_ + MCL_) ? sc_w2 + (size_t)(r - LDIM_) * HID_ : nullptr;
    for (int i = threadIdx.x; i < HID_; i += blockDim.x) {
        float v = src ? src[i] : 0.f;
        __nv_bfloat16 h = __float2bfloat16(v);
        g_W2hi[(size_t)r * HID_ + i] = h;
        g_W2lo[(size_t)r * HID_ + i] = __float2bfloat16(v - __bfloat162float(h));
    }
    if (threadIdx.x == 0)
        g_b2s[r] = (r < LDIM_) ? cf_b2[r] : (r < LDIM_ + MCL_) ? sc_b2[r - LDIM_] : 0.f;
}

// -------------------------------------------------------------------------
// x [B, C, HW] fp32  ->  xT [B, HW, C] bf16 hi/lo  (32x32 smem transpose)
// -------------------------------------------------------------------------
__global__ void __launch_bounds__(256)
transpose_split_x(const float* __restrict__ x)
{
    __shared__ float s[32][33];
    const int n0 = blockIdx.x * 32;
    const int c0 = blockIdx.y * 32;
    const int b  = blockIdx.z;
    const int tx = threadIdx.x & 31, ty = threadIdx.x >> 5;

    #pragma unroll
    for (int q = 0; q < 4; q++) {
        int c = ty + q * 8;
        s[c][tx] = x[((size_t)b * C_ + c0 + c) * HW_ + n0 + tx];
    }
    __syncthreads();
    #pragma unroll
    for (int q = 0; q < 4; q++) {
        int n = ty + q * 8;
        float v = s[tx][n];
        __nv_bfloat16 h = __float2bfloat16(v);
        size_t idx = ((size_t)b * HW_ + n0 + n) * C_ + c0 + tx;
        g_xT_hi[idx] = h;
        g_xT_lo[idx] = __float2bfloat16(v - __bfloat162float(h));
    }
}

// -------------------------------------------------------------------------
// Tensor-core GEMM via mma.sync:  D[m,n] = sum_k A[m,k]*B[n,k]
// 3-pass bf16 hi/lo, fp32 accum. CTA 128x128, 16 warps @ 32x32 tiles, BK=64.
// 3-stage cp.async pipeline, ONE __syncthreads per chunk.
// k-loop NOT unrolled (#pragma unroll 1): keeps SASS small / ptxas fast.
// EPI=1: bias+relu -> bf16 hi/lo split -> pixel-major Ht (via smem transpose).
// EPI=2: bias -> fp32 F (rows<128) / P (rows 128..191), channel-major.
// -------------------------------------------------------------------------
#define STAGE_BYTES 65536                        // Ahi,Alo,Bhi,Blo @16KB each
#define GEMM_SMEM   (1024 + 3 * STAGE_BYTES)     // 197632

template<int KDIM, int BSTR, int EPI>
__global__ void __launch_bounds__(512)
gemm_mma(const __nv_bfloat16* __restrict__ Ahi, const __nv_bfloat16* __restrict__ Alo,
         const __nv_bfloat16* __restrict__ Bhi, const __nv_bfloat16* __restrict__ Blo,
         const float* __restrict__ bias,
         __nv_bfloat16* __restrict__ OutHi, __nv_bfloat16* __restrict__ OutLo,
         float* __restrict__ OutF, float* __restrict__ OutP)
{
    constexpr int NCHUNK = KDIM / 64;
    extern __shared__ __align__(1024) char smem[];
    const uint32_t sbase = smem_u32(smem);
    float* bias_s = (float*)smem;                 // 128 floats

    const int tid  = threadIdx.x;
    const int wid  = tid >> 5, lane = tid & 31;
    const int n0   = blockIdx.x * 128;
    const int m0   = blockIdx.y * 128;
    const int bz   = blockIdx.z;
    const int koff = (EPI == 2) ? blockIdx.y * 512 : 0;

    const int warp_m = (wid >> 2) * 32;           // 0,32,64,96
    const int warp_n = (wid & 3) * 32;            // 0,32,64,96

    if (tid < 128) bias_s[tid] = bias[m0 + tid];

    const size_t bRow = (size_t)bz * HW_ + n0;

    // ---- stage loader: 8 cp.async per thread (512 threads) ----
    auto load_stage = [&](int c, int stage) {
        const uint32_t base = sbase + 1024 + stage * STAGE_BYTES;
        #pragma unroll
        for (int h = 0; h < 2; h++) {
            const __nv_bfloat16* Ag = h ? Alo : Ahi;
            const uint32_t abuf = base + h * 16384;
            #pragma unroll
            for (int q = 0; q < 2; q++) {
                int idx = tid + q * 512;            // 1024 chunks of 16B
                int row = idx >> 3, seg = idx & 7;
                cp16(abuf + swz(row * 128 + seg * 16),
                     Ag + (size_t)(m0 + row) * KDIM + c * 64 + seg * 8);
            }
        }
        #pragma unroll
        for (int h = 0; h < 2; h++) {
            const __nv_bfloat16* Bg = h ? Blo : Bhi;
            const uint32_t bbuf = base + 32768 + h * 16384;
            #pragma unroll
            for (int q = 0; q < 2; q++) {
                int idx = tid + q * 512;
                int row = idx >> 3, seg = idx & 7;
                cp16(bbuf + swz(row * 128 + seg * 16),
                     Bg + (bRow + row) * BSTR + koff + c * 64 + seg * 8);
            }
        }
        CP_COMMIT();
    };

    float acc[2][4][4];
    #pragma unroll
    for (int i = 0; i < 2; i++)
        #pragma unroll
        for (int j = 0; j < 4; j++)
            #pragma unroll
            for (int r = 0; r < 4; r++) acc[i][j][r] = 0.f;

    load_stage(0, 0);
    if (NCHUNK > 1) load_stage(1, 1);

    #pragma unroll 1
    for (int c = 0; c < NCHUNK; c++) {
        if (c + 1 < NCHUNK) { CP_WAIT(1); }       // chunk c complete, c+1 may fly
        else                { CP_WAIT(0); }
        __syncthreads();                          // data visible; stage (c+2)%3 free

        if (c + 2 < NCHUNK) load_stage(c + 2, (c + 2) % 3);

        const uint32_t aBase = sbase + 1024 + (c % 3) * STAGE_BYTES;
        const uint32_t bBase = aBase + 32768;

        #pragma unroll
        for (int s = 0; s < 4; s++) {
            uint32_t ah[2][4], al[2][4], bh[4][2], bl[4][2];
            // A fragments (hi+lo): two 16x16 blocks
            #pragma unroll
            for (int mb = 0; mb < 2; mb++) {
                int row = warp_m + mb * 16 + (lane & 15);
                uint32_t off = swz(row * 128 + s * 32 + ((lane >> 4) << 4));
                ldsm4(ah[mb], aBase + off);
                ldsm4(al[mb], aBase + 16384 + off);
            }
            // B fragments (hi+lo): two 16-col groups -> four 8-col blocks
            #pragma unroll
            for (int nbp = 0; nbp < 2; nbp++) {
                int grp = lane >> 3;
                int row = warp_n + nbp * 16 + ((grp >> 1) << 3) + (lane & 7);
                uint32_t off = swz(row * 128 + s * 32 + ((grp & 1) << 4));
                uint32_t t[4];
                ldsm4(t, bBase + off);
                bh[nbp*2][0] = t[0]; bh[nbp*2][1] = t[1];
                bh[nbp*2+1][0] = t[2]; bh[nbp*2+1][1] = t[3];
                ldsm4(t, bBase + 16384 + off);
                bl[nbp*2][0] = t[0]; bl[nbp*2][1] = t[1];
                bl[nbp*2+1][0] = t[2]; bl[nbp*2+1][1] = t[3];
            }
            // 3 passes: Ah*Bh + Ah*Bl + Al*Bh
            #pragma unroll
            for (int mb = 0; mb < 2; mb++)
                #pragma unroll
                for (int nb = 0; nb < 4; nb++) mma16816(acc[mb][nb], ah[mb], bh[nb]);
            #pragma unroll
            for (int mb = 0; mb < 2; mb++)
                #pragma unroll
                for (int nb = 0; nb < 4; nb++) mma16816(acc[mb][nb], ah[mb], bl[nb]);
            #pragma unroll
            for (int mb = 0; mb < 2; mb++)
                #pragma unroll
                for (int nb = 0; nb < 4; nb++) mma16816(acc[mb][nb], al[mb], bh[nb]);
        }
    }
    __syncthreads();   // all MMAs done before smem reuse in epilogue

    // ---------------- epilogue ----------------
    const int qr = lane >> 2, qc = (lane & 3) * 2;

    if (EPI == 1) {
        // stage to smem transposed: sC[n][m], pitch 132
        float* sC = (float*)(smem + 1024);
        #pragma unroll
        for (int mb = 0; mb < 2; mb++)
            #pragma unroll
            for (int nb = 0; nb < 4; nb++)
                #pragma unroll
                for (int r = 0; r < 4; r++) {
                    int m = warp_m + mb * 16 + qr + ((r >> 1) << 3);
                    int n = warp_n + nb * 8 + qc + (r & 1);
                    sC[n * 132 + m] = fmaxf(acc[mb][nb][r] + bias_s[m], 0.f);
                }
        __syncthreads();
        #pragma unroll
        for (int q = 0; q < 4; q++) {
            int idx = tid + q * 512;                // 2048 = 128px * 16 segs
            int px = idx >> 4, sg = idx & 15;
            const float* src = sC + px * 132 + sg * 8;
            __nv_bfloat16 hi[8], lo[8];
            #pragma unroll
            for (int j = 0; j < 8; j++) {
                float v = src[j];
                hi[j] = __float2bfloat16(v);
                lo[j] = __float2bfloat16(v - __bfloat162float(hi[j]));
            }
            size_t g = ((size_t)bz * HW_ + n0 + px) * 1024 + m0 + sg * 8;
            *(uint4*)(OutHi + g) = *(const uint4*)hi;
            *(uint4*)(OutLo + g) = *(const uint4*)lo;
        }
    } else {
        // direct fp32 store, channel-major
        #pragma unroll
        for (int mb = 0; mb < 2; mb++)
            #pragma unroll
            for (int nb = 0; nb < 4; nb++)
                #pragma unroll
                for (int r = 0; r < 4; r++) {
                    int ml = warp_m + mb * 16 + qr + ((r >> 1) << 3);
                    int n  = warp_n + nb * 8 + qc + (r & 1);
                    int row = m0 + ml;
                    float v = acc[mb][nb][r] + bias_s[ml];
                    if (row < LDIM_)
                        OutF[((size_t)bz * LDIM_ + row) * HW_ + n0 + n] = v;
                    else if (row < LDIM_ + MCL_)
                        OutP[((size_t)bz * MCL_ + row - LDIM_) * HW_ + n0 + n] = v;
                }
    }
}

// -------------------------------------------------------------------------
// Token MLP (unchanged, passing since R1)
// -------------------------------------------------------------------------
__global__ void __launch_bounds__(256)
token_kernel(const float* __restrict__ t,
             const float* __restrict__ w1, const float* __restrict__ b1,
             const float* __restrict__ w2, const float* __restrict__ b2,
             float* __restrict__ out)
{
    const int b = blockIdx.x;
    const int tid = threadIdx.x, warp = tid >> 5, lane = tid & 31;

    __shared__ float ts[C_];
    __shared__ float h[HID_];
    __shared__ float tk[GDIM_];
    __shared__ float red[8];

    for (int i = tid; i < C_; i += 256) ts[i] = t[(size_t)b * C_ + i];
    __syncthreads();

    for (int j = warp; j < HID_; j += 8) {
        const float* wr = w1 + (size_t)j * C_;
        float s = 0.f;
        for (int k = lane * 4; k < C_; k += 128) {
            float4 w4 = *(const float4*)(wr + k);
            float4 t4 = *(const float4*)(ts + k);
            s += w4.x*t4.x + w4.y*t4.y + w4.z*t4.z + w4.w*t4.w;
        }
        #pragma unroll
        for (int o = 16; o; o >>= 1) s += __shfl_xor_sync(0xffffffffu, s, o);
        if (lane == 0) h[j] = fmaxf(s + b1[j], 0.f);
    }
    __syncthreads();

    for (int j = warp; j < GDIM_; j += 8) {
        const float* wr = w2 + (size_t)j * HID_;
        float s = 0.f;
        for (int k = lane * 4; k < HID_; k += 128) {
            float4 w4 = *(const float4*)(wr + k);
            float4 h4 = *(const float4*)(h + k);
            s += w4.x*h4.x + w4.y*h4.y + w4.z*h4.z + w4.w*h4.w;
        }
        #pragma unroll
        for (int o = 16; o; o >>= 1) s += __shfl_xor_sync(0xffffffffu, s, o);
        if (lane == 0) tk[j] = s + b2[j];
    }
    __syncthreads();

    float v = tk[tid];
    float sq = v * v;
    #pragma unroll
    for (int o = 16; o; o >>= 1) sq += __shfl_xor_sync(0xffffffffu, sq, o);
    if (lane == 0) red[warp] = sq;
    __syncthreads();
    if (warp == 0) {
        float r = (lane < 8) ? red[lane] : 0.f;
        #pragma unroll
        for (int o = 4; o; o >>= 1) r += __shfl_xor_sync(0xffffffffu, r, o);
        if (lane == 0) red[0] = r;
    }
    __syncthreads();
    const float inv = 1.f / fmaxf(sqrtf(red[0]), EPSV);
    out[(size_t)b * OUTD_ + tid] = v * inv;
}

// -------------------------------------------------------------------------
// Log-space Sinkhorn (unchanged, passing since R1)
// -------------------------------------------------------------------------
__global__ void __launch_bounds__(1024)
sinkhorn_kernel(float* __restrict__ Pg, const float* __restrict__ dust)
{
    const int b = blockIdx.x;
    float* Z = Pg + (size_t)b * MCL_ * HW_;
    const int tid = threadIdx.x, warp = tid >> 5, lane = tid & 31;

    __shared__ float u[MCL_ + 1];
    __shared__ float v[HW_];

    const float alpha = dust[0];
    const float norm_c     = -logf((float)(MCL_ + HW_));
    const float log_mu     = norm_c;
    const float log_mu_bin = logf((float)(HW_ - MCL_)) + norm_c;
    const float log_nu     = norm_c;

    v[tid] = 0.f;
    __syncthreads();

    for (int it = 0; it < 3; it++) {
        for (int i = warp; i < MCL_; i += 32) {
            const float* zr = Z + (size_t)i * HW_;
            float mx = -3.0e38f, s = 0.f;
            for (int j = lane; j < HW_; j += 32) {
                float zv = zr[j] + v[j];
                if (zv > mx) { s = s * __expf(mx - zv) + 1.f; mx = zv; }
                else           s += __expf(zv - mx);
            }
            #pragma unroll
            for (int o = 16; o; o >>= 1) {
                float mo = __shfl_xor_sync(0xffffffffu, mx, o);
                float so = __shfl_xor_sync(0xffffffffu, s,  o);
                float m2 = fmaxf(mx, mo);
                s  = s * __expf(mx - m2) + so * __expf(mo - m2);
                mx = m2;
            }
            if (lane == 0) u[i] = log_mu - (mx + __logf(s));
        }
        if (warp == 0) {
            float mx = -3.0e38f, s = 0.f;
            for (int j = lane; j < HW_; j += 32) {
                float zv = v[j];
                if (zv > mx) { s = s * __expf(mx - zv) + 1.f; mx = zv; }
                else           s += __expf(zv - mx);
            }
            #pragma unroll
            for (int o = 16; o; o >>= 1) {
                float mo = __shfl_xor_sync(0xffffffffu, mx, o);
                float so = __shfl_xor_sync(0xffffffffu, s,  o);
                float m2 = fmaxf(mx, mo);
                s  = s * __expf(mx - m2) + so * __expf(mo - m2);
                mx = m2;
            }
            if (lane == 0) u[MCL_] = log_mu_bin - (alpha + mx + __logf(s));
        }
        __syncthreads();

        {
            const int j = tid;
            float mx = alpha + u[MCL_];
            float s  = 1.f;
            #pragma unroll 4
            for (int i = 0; i < MCL_; i++) {
                float zv = Z[(size_t)i * HW_ + j] + u[i];
                if (zv > mx) { s = s * __expf(mx - zv) + 1.f; mx = zv; }
                else           s += __expf(zv - mx);
            }
            v[j] = log_nu - (mx + __logf(s));
        }
        __syncthreads();
    }

    {
        const int j = tid;
        const float vj = v[j] - norm_c;
        #pragma unroll 4
        for (int i = 0; i < MCL_; i++) {
            size_t idx = (size_t)i * HW_ + j;
            Z[idx] = __expf(Z[idx] + u[i] + vj);
        }
    }
}

// -------------------------------------------------------------------------
// VLAD aggregation, stage 1: partial agg over an HW quarter (no atomics).
// grid (4 slices, 32 batches), 256 threads. Writes g_aggp[slice][b][l][m].
// -------------------------------------------------------------------------
__global__ void __launch_bounds__(256)
agg_partial(const float* __restrict__ Fg, const float* __restrict__ Pg)
{
    const int sl = blockIdx.x;               // 0..3
    const int b  = blockIdx.y;
    const float* f = Fg + (size_t)b * LDIM_ * HW_;
    const float* p = Pg + (size_t)b * MCL_  * HW_;

    __shared__ __align__(16) float sbuf[32 * 129 + 32 * 65];
    float (*Fs)[129] = (float(*)[129])sbuf;
    float (*Ps)[65]  = (float(*)[65])(sbuf + 32 * 129);

    const int tid = threadIdx.x;
    const int tr = tid >> 4, tc = tid & 15;

    float acc[8][4];
    #pragma unroll
    for (int i = 0; i < 8; i++)
        #pragma unroll
        for (int j = 0; j < 4; j++) acc[i][j] = 0.f;

    const int nbeg = sl * 256, nend = nbeg + 256;
    for (int n0 = nbeg; n0 < nend; n0 += 32) {
        #pragma unroll
        for (int q = 0; q < 16; q++) {
            int idx = tid + q * 256;
            int l = idx >> 5, n = idx & 31;
            Fs[n][l] = f[(size_t)l * HW_ + n0 + n];
        }
        #pragma unroll
        for (int q = 0; q < 8; q++) {
            int idx = tid + q * 256;
            int m = idx >> 5, n = idx & 31;
            Ps[n][m] = p[(size_t)m * HW_ + n0 + n];
        }
        __syncthreads();

        #pragma unroll
        for (int n = 0; n < 32; n++) {
            float rf[8], rp[4];
            #pragma unroll
            for (int i = 0; i < 8; i++) rf[i] = Fs[n][tr*8 + i];
            #pragma unroll
            for (int j = 0; j < 4; j++) rp[j] = Ps[n][tc*4 + j];
            #pragma unroll
            for (int i = 0; i < 8; i++)
                #pragma unroll
                for (int j = 0; j < 4; j++)
                    acc[i][j] = fmaf(rf[i], rp[j], acc[i][j]);
        }
        __syncthreads();
    }

    float* dst = g_aggp + (((size_t)sl * B_ + b) * LDIM_) * MCL_;
    #pragma unroll
    for (int i = 0; i < 8; i++)
        #pragma unroll
        for (int j = 0; j < 4; j++)
            dst[(size_t)(tr*8 + i) * MCL_ + tc*4 + j] = acc[i][j];
}

// -------------------------------------------------------------------------
// VLAD aggregation, stage 2: sum 4 partials, per-cluster L2 over l, write out.
// -------------------------------------------------------------------------
__global__ void __launch_bounds__(256)
agg_norm(float* __restrict__ out)
{
    const int b = blockIdx.x;
    __shared__ __align__(16) float sbuf[128 * 65 + 64];
    float (*Cs)[65] = (float(*)[65])sbuf;
    float* nrm = sbuf + 128 * 65;
    const int tid = threadIdx.x;

    #pragma unroll
    for (int q = 0; q < 32; q++) {
        int idx = tid + q * 256;               // 8192 = 128*64
        int l = idx >> 6, m = idx & 63;
        float s = 0.f;
        #pragma unroll
        for (int sl = 0; sl < 4; sl++)
            s += g_aggp[(((size_t)sl * B_ + b) * LDIM_ + l) * MCL_ + m];
        Cs[l][m] = s;
    }
    __syncthreads();
    if (tid < MCL_) {
        float s = 0.f;
        for (int l = 0; l < LDIM_; l++) { float c = Cs[l][tid]; s += c * c; }
        nrm[tid] = 1.f / fmaxf(sqrtf(s), EPSV);
    }
    __syncthreads();
    float* orow = out + (size_t)b * OUTD_ + GDIM_;
    #pragma unroll
    for (int q = 0; q < 32; q++) {
        int idx = tid + q * 256;
        int l = idx >> 6, m = idx & 63;
        orow[idx] = Cs[l][m] * nrm[m];
    }
}

// -------------------------------------------------------------------------
// Final row L2 normalization (unchanged, passing since R1)
// -------------------------------------------------------------------------
__global__ void __launch_bounds__(256)
rownorm_kernel(float* __restrict__ out)
{
    const int b = blockIdx.x;
    float* row = out + (size_t)b * OUTD_;
    const int tid = threadIdx.x, warp = tid >> 5, lane = tid & 31;
    __shared__ float red[8];

    float s = 0.f;
    for (int i = tid; i < OUTD_; i += 256) { float x = row[i]; s += x * x; }
    #pragma unroll
    for (int o = 16; o; o >>= 1) s += __shfl_xor_sync(0xffffffffu, s, o);
    if (lane == 0) red[warp] = s;
    __syncthreads();
    if (warp == 0) {
        float r = (lane < 8) ? red[lane] : 0.f;
        #pragma unroll
        for (int o = 4; o; o >>= 1) r += __shfl_xor_sync(0xffffffffu, r, o);
        if (lane == 0) red[0] = r;
    }
    __syncthreads();
    const float inv = 1.f / fmaxf(sqrtf(red[0]), EPSV);
    for (int i = tid; i < OUTD_; i += 256) row[i] *= inv;
}

// -------------------------------------------------------------------------
// Launch
// -------------------------------------------------------------------------
extern "C" void kernel_launch(void* const* d_in, const int* in_sizes, int n_in,
                              void* d_out, int out_size)
{
    const float* x     = (const float*)d_in[0];
    const float* t     = (const float*)d_in[1];
    const float* cf_w1 = (const float*)d_in[2];
    const float* cf_b1 = (const float*)d_in[3];
    const float* cf_w2 = (const float*)d_in[4];
    const float* cf_b2 = (const float*)d_in[5];
    const float* sc_w1 = (const float*)d_in[6];
    const float* sc_b1 = (const float*)d_in[7];
    const float* sc_w2 = (const float*)d_in[8];
    const float* sc_b2 = (const float*)d_in[9];
    const float* tk_w1 = (const float*)d_in[10];
    const float* tk_b1 = (const float*)d_in[11];
    const float* tk_w2 = (const float*)d_in[12];
    const float* tk_b2 = (const float*)d_in[13];
    const float* dust  = (const float*)d_in[14];
    float* out = (float*)d_out;

    __nv_bfloat16 *xTh, *xTl, *W1h, *W1l, *W2h, *W2l, *Hth, *Htl;
    float *b1s, *b2s, *F, *P;
    cudaGetSymbolAddress((void**)&xTh, g_xT_hi);
    cudaGetSymbolAddress((void**)&xTl, g_xT_lo);
    cudaGetSymbolAddress((void**)&W1h, g_W1hi);
    cudaGetSymbolAddress((void**)&W1l, g_W1lo);
    cudaGetSymbolAddress((void**)&W2h, g_W2hi);
    cudaGetSymbolAddress((void**)&W2l, g_W2lo);
    cudaGetSymbolAddress((void**)&Hth, g_Ht_hi);
    cudaGetSymbolAddress((void**)&Htl, g_Ht_lo);
    cudaGetSymbolAddress((void**)&b1s, g_b1s);
    cudaGetSymbolAddress((void**)&b2s, g_b2s);
    cudaGetSymbolAddress((void**)&F,   g_F);
    cudaGetSymbolAddress((void**)&P,   g_P);

    cudaFuncSetAttribute(gemm_mma<1536, 1536, 1>,
                         cudaFuncAttributeMaxDynamicSharedMemorySize, GEMM_SMEM);
    cudaFuncSetAttribute(gemm_mma<512, 1024, 2>,
                         cudaFuncAttributeMaxDynamicSharedMemorySize, GEMM_SMEM);

    // Prep: weight stacking/splitting + x transpose/split
    prep_w1<<<1024, 256>>>(cf_w1, cf_b1, sc_w1, sc_b1);
    prep_w2<<<256, 128>>>(cf_w2, cf_b2, sc_w2, sc_b2);
    transpose_split_x<<<dim3(HW_/32, C_/32, B_), 256>>>(x);

    // Layer 1 (fused cf+sc): Ht[b, px, 1024ch] = relu(W1 @ x + b1), bf16 hi/lo
    gemm_mma<1536, 1536, 1><<<dim3(HW_/128, 1024/128, B_), 512, GEMM_SMEM>>>(
        W1h, W1l, xTh, xTl, b1s, Hth, Htl, nullptr, nullptr);

    // Layer 2 (fused cf+sc): F fp32 [B,128,HW], P fp32 [B,64,HW]
    gemm_mma<512, 1024, 2><<<dim3(HW_/128, 2, B_), 512, GEMM_SMEM>>>(
        W2h, W2l, Hth, Htl, b2s, nullptr, nullptr, F, P);

    // Token MLP -> out[:, 0:256]
    token_kernel<<<B_, 256>>>(t, tk_w1, tk_b1, tk_w2, tk_b2, out);

    // Sinkhorn + parallel VLAD aggregation + final norm
    sinkhorn_kernel<<<B_, 1024>>>(P, dust);
    agg_partial<<<dim3(4, B_), 256>>>(F, P);
    agg_norm<<<B_, 256>>>(out);
    rownorm_kernel<<<B_, 256>>>(out);
}

// round 8
// speedup vs baseline: 2.6341x; 1.0405x over previous
#include <cuda_runtime.h>
#include <cuda_bf16.h>
#include <math.h>
#include <stdint.h>

// Problem constants
#define B_    32
#define C_    1536
#define HW_   1024      // 32*32
#define HID_  512
#define LDIM_ 128
#define MCL_  64
#define GDIM_ 256
#define OUTD_ (GDIM_ + LDIM_*MCL_)   // 8448
#define EPSV  1e-12f

// -------------------------------------------------------------------------
// Scratch (__device__ globals: allocation-free, graph-capture safe)
// -------------------------------------------------------------------------
__device__ __align__(256) __nv_bfloat16 g_xT_hi[(size_t)B_ * HW_ * C_];
__device__ __align__(256) __nv_bfloat16 g_xT_lo[(size_t)B_ * HW_ * C_];
__device__ __align__(256) __nv_bfloat16 g_W1hi[1024 * C_];
__device__ __align__(256) __nv_bfloat16 g_W1lo[1024 * C_];
__device__ __align__(256) __nv_bfloat16 g_W2hi[256 * HID_];
__device__ __align__(256) __nv_bfloat16 g_W2lo[256 * HID_];
__device__ __align__(256) float g_b1s[1024];
__device__ __align__(256) float g_b2s[256];
__device__ __align__(256) __nv_bfloat16 g_Ht_hi[(size_t)B_ * HW_ * 1024]; // pixel-major
__device__ __align__(256) __nv_bfloat16 g_Ht_lo[(size_t)B_ * HW_ * 1024];
__device__ __align__(256) float g_F[(size_t)B_ * LDIM_ * HW_];
__device__ __align__(256) float g_P[(size_t)B_ * MCL_  * HW_];
__device__ __align__(256) float g_aggp[4 * B_ * LDIM_ * MCL_];            // 4 HW-slices

// -------------------------------------------------------------------------
// PTX helpers (family-agnostic: mma.sync / ldmatrix / cp.async)
// -------------------------------------------------------------------------
__device__ __forceinline__ uint32_t smem_u32(const void* p) {
    uint32_t a;
    asm("{ .reg .u64 t; cvta.to.shared.u64 t, %1; cvt.u32.u64 %0, t; }" : "=r"(a) : "l"(p));
    return a;
}
__device__ __forceinline__ void cp16(uint32_t dst, const void* src) {
    asm volatile("cp.async.cg.shared.global [%0], [%1], 16;" :: "r"(dst), "l"(src));
}
#define CP_COMMIT() asm volatile("cp.async.commit_group;" ::: "memory")
#define CP_WAIT(n)  asm volatile("cp.async.wait_group %0;" :: "n"(n) : "memory")

__device__ __forceinline__ void ldsm4(uint32_t* r, uint32_t addr) {
    asm volatile("ldmatrix.sync.aligned.m8n8.x4.shared.b16 {%0,%1,%2,%3}, [%4];"
        : "=r"(r[0]), "=r"(r[1]), "=r"(r[2]), "=r"(r[3]) : "r"(addr));
}
__device__ __forceinline__ void mma16816(float* c, const uint32_t* a, const uint32_t* b) {
    asm volatile(
        "mma.sync.aligned.m16n8k16.row.col.f32.bf16.bf16.f32 "
        "{%0,%1,%2,%3}, {%4,%5,%6,%7}, {%8,%9}, {%0,%1,%2,%3};"
        : "+f"(c[0]), "+f"(c[1]), "+f"(c[2]), "+f"(c[3])
        : "r"(a[0]), "r"(a[1]), "r"(a[2]), "r"(a[3]), "r"(b[0]), "r"(b[1]));
}
__device__ __forceinline__ uint32_t swz(uint32_t off) {      // SW128-style 16B-chunk XOR
    return off ^ ((off >> 3) & 0x70);
}

// -------------------------------------------------------------------------
// Weight prep: stack + hi/lo split
// -------------------------------------------------------------------------
__global__ void prep_w1(const float* __restrict__ cf_w1, const float* __restrict__ cf_b1,
                        const float* __restrict__ sc_w1, const float* __restrict__ sc_b1)
{
    const int r = blockIdx.x;               // 0..1023
    const float* src = (r < HID_) ? cf_w1 + (size_t)r * C_ : sc_w1 + (size_t)(r - HID_) * C_;
    for (int i = threadIdx.x; i < C_; i += blockDim.x) {
        float v = src[i];
        __nv_bfloat16 h = __float2bfloat16(v);
        g_W1hi[(size_t)r * C_ + i] = h;
        g_W1lo[(size_t)r * C_ + i] = __float2bfloat16(v - __bfloat162float(h));
    }
    if (threadIdx.x == 0)
        g_b1s[r] = (r < HID_) ? cf_b1[r] : sc_b1[r - HID_];
}

__global__ void prep_w2(const float* __restrict__ cf_w2, const float* __restrict__ cf_b2,
                        const float* __restrict__ sc_w2, const float* __restrict__ sc_b2)
{
    const int r = blockIdx.x;               // 0..255
    const float* src = (r < LDIM_) ? cf_w2 + (size_t)r * HID_
                     : (r < LDIM_ + MCL_) ? sc_w2 + (size_t)(r - LDIM_) * HID_ : nullptr;
    for (int i = threadIdx.x; i < HID_; i += blockDim.x) {
        float v = src ? src[i] : 0.f;
        __nv_bfloat16 h = __float2bfloat16(v);
        g_W2hi[(size_t)r * HID_ + i] = h;
        g_W2lo[(size_t)r * HID_ + i] = __float2bfloat16(v - __bfloat162float(h));
    }
    if (threadIdx.x == 0)
        g_b2s[r] = (r < LDIM_) ? cf_b2[r] : (r < LDIM_ + MCL_) ? sc_b2[r - LDIM_] : 0.f;
}

// -------------------------------------------------------------------------
// x [B, C, HW] fp32  ->  xT [B, HW, C] bf16 hi/lo  (32x32 smem transpose,
// vectorized uint2 stores, conflict-free reads)
// -------------------------------------------------------------------------
__global__ void __launch_bounds__(256)
transpose_split_x(const float* __restrict__ x)
{
    __shared__ float s[32][33];
    const int n0 = blockIdx.x * 32;
    const int c0 = blockIdx.y * 32;
    const int b  = blockIdx.z;
    const int tx = threadIdx.x & 31, ty = threadIdx.x >> 5;

    #pragma unroll
    for (int q = 0; q < 4; q++) {
        int c = ty + q * 8;
        s[c][tx] = x[((size_t)b * C_ + c0 + c) * HW_ + n0 + tx];
    }
    __syncthreads();

    const int n  = threadIdx.x >> 3;            // 0..31
    const int cs = (threadIdx.x & 7) * 4;       // 0..28
    __nv_bfloat16 hi[4], lo[4];
    #pragma unroll
    for (int j = 0; j < 4; j++) {
        float v = s[cs + j][n];
        hi[j] = __float2bfloat16(v);
        lo[j] = __float2bfloat16(v - __bfloat162float(hi[j]));
    }
    size_t idx = ((size_t)b * HW_ + n0 + n) * C_ + c0 + cs;
    *(uint2*)(g_xT_hi + idx) = *(const uint2*)hi;
    *(uint2*)(g_xT_lo + idx) = *(const uint2*)lo;
}

// -------------------------------------------------------------------------
// Tensor-core GEMM via mma.sync:  D[m,n] = sum_k A[m,k]*B[n,k]
// 3-pass bf16 hi/lo, fp32 accum. CTA = CTAM x 128, 8 warps (WGM x WGN grid),
// warp tile (CTAM/WGM) x (128/WGN). BK=64, 2-stage cp.async pipeline.
// EPI=1: bias+relu -> bf16 hi/lo split -> pixel-major Ht (smem transpose).
// EPI=2: bias -> fp32 F (rows<128) / P (rows 128..191), channel-major.
// -------------------------------------------------------------------------
template<int KDIM, int BSTR, int EPI, int CTAM, int WGM, int WGN>
__global__ void __launch_bounds__(256)
gemm_mma(const __nv_bfloat16* __restrict__ Ahi, const __nv_bfloat16* __restrict__ Alo,
         const __nv_bfloat16* __restrict__ Bhi, const __nv_bfloat16* __restrict__ Blo,
         const float* __restrict__ bias,
         __nv_bfloat16* __restrict__ OutHi, __nv_bfloat16* __restrict__ OutLo,
         float* __restrict__ OutF, float* __restrict__ OutP)
{
    constexpr int NCHUNK  = KDIM / 64;
    constexpr int A_BYTES = CTAM * 128;          // one hi (or lo) A chunk
    constexpr int STAGE   = 2 * A_BYTES + 32768; // Ahi,Alo,Bhi,Blo
    constexpr int WTM = CTAM / WGM, WTN = 128 / WGN;
    constexpr int MB = WTM / 16, NB = WTN / 8, NBP = WTN / 16;
    constexpr int AIT = (CTAM * 8) / 256;        // 16B chunks of A per thread

    extern __shared__ __align__(1024) char smem[];
    const uint32_t sbase = smem_u32(smem);
    float* bias_s = (float*)smem;                // CTAM floats (<=1024B)

    const int tid  = threadIdx.x;
    const int wid  = tid >> 5, lane = tid & 31;
    const int n0   = blockIdx.x * 128;
    const int m0   = blockIdx.y * CTAM;
    const int bz   = blockIdx.z;
    const int koff = (EPI == 2) ? blockIdx.y * 512 : 0;

    const int warp_m = (wid / WGN) * WTM;
    const int warp_n = (wid % WGN) * WTN;

    if (tid < CTAM) bias_s[tid] = bias[m0 + tid];

    const size_t bRow = (size_t)bz * HW_ + n0;

    auto load_stage = [&](int c, int stage) {
        const uint32_t base = sbase + 1024 + stage * STAGE;
        #pragma unroll
        for (int h = 0; h < 2; h++) {
            const __nv_bfloat16* Ag = h ? Alo : Ahi;
            const uint32_t abuf = base + h * A_BYTES;
            #pragma unroll
            for (int q = 0; q < AIT; q++) {
                int idx = tid + q * 256;
                int row = idx >> 3, seg = idx & 7;
                cp16(abuf + swz(row * 128 + seg * 16),
                     Ag + (size_t)(m0 + row) * KDIM + c * 64 + seg * 8);
            }
        }
        #pragma unroll
        for (int h = 0; h < 2; h++) {
            const __nv_bfloat16* Bg = h ? Blo : Bhi;
            const uint32_t bbuf = base + 2 * A_BYTES + h * 16384;
            #pragma unroll
            for (int q = 0; q < 4; q++) {
                int idx = tid + q * 256;
                int row = idx >> 3, seg = idx & 7;
                cp16(bbuf + swz(row * 128 + seg * 16),
                     Bg + (bRow + row) * BSTR + koff + c * 64 + seg * 8);
            }
        }
        CP_COMMIT();
    };

    float acc[MB][NB][4];
    #pragma unroll
    for (int i = 0; i < MB; i++)
        #pragma unroll
        for (int j = 0; j < NB; j++)
            #pragma unroll
            for (int r = 0; r < 4; r++) acc[i][j][r] = 0.f;

    load_stage(0, 0);

    #pragma unroll 1
    for (int c = 0; c < NCHUNK; c++) {
        if (c + 1 < NCHUNK) { load_stage(c + 1, (c + 1) & 1); CP_WAIT(1); }
        else                { CP_WAIT(0); }
        __syncthreads();                          // chunk c visible

        const uint32_t aBase = sbase + 1024 + (c & 1) * STAGE;
        const uint32_t bBase = aBase + 2 * A_BYTES;

        #pragma unroll
        for (int s = 0; s < 4; s++) {
            uint32_t ah[MB][4], al[MB][4], bh[NB][2], bl[NB][2];
            #pragma unroll
            for (int mb = 0; mb < MB; mb++) {
                int row = warp_m + mb * 16 + (lane & 15);
                uint32_t off = swz(row * 128 + s * 32 + ((lane >> 4) << 4));
                ldsm4(ah[mb], aBase + off);
                ldsm4(al[mb], aBase + A_BYTES + off);
            }
            #pragma unroll
            for (int nbp = 0; nbp < NBP; nbp++) {
                int grp = lane >> 3;
                int row = warp_n + nbp * 16 + ((grp >> 1) << 3) + (lane & 7);
                uint32_t off = swz(row * 128 + s * 32 + ((grp & 1) << 4));
                uint32_t t[4];
                ldsm4(t, bBase + off);
                bh[nbp*2][0] = t[0]; bh[nbp*2][1] = t[1];
                bh[nbp*2+1][0] = t[2]; bh[nbp*2+1][1] = t[3];
                ldsm4(t, bBase + 16384 + off);
                bl[nbp*2][0] = t[0]; bl[nbp*2][1] = t[1];
                bl[nbp*2+1][0] = t[2]; bl[nbp*2+1][1] = t[3];
            }
            #pragma unroll
            for (int mb = 0; mb < MB; mb++)
                #pragma unroll
                for (int nb = 0; nb < NB; nb++) mma16816(acc[mb][nb], ah[mb], bh[nb]);
            #pragma unroll
            for (int mb = 0; mb < MB; mb++)
                #pragma unroll
                for (int nb = 0; nb < NB; nb++) mma16816(acc[mb][nb], ah[mb], bl[nb]);
            #pragma unroll
            for (int mb = 0; mb < MB; mb++)
                #pragma unroll
                for (int nb = 0; nb < NB; nb++) mma16816(acc[mb][nb], al[mb], bh[nb]);
        }
        __syncthreads();                          // stage (c&1) free for c+2
    }

    // ---------------- epilogue ----------------
    const int qr = lane >> 2, qc = (lane & 3) * 2;

    if (EPI == 1) {
        // stage to smem transposed: sC[n][m], pitch CTAM+4
        constexpr int PITCH = CTAM + 4;
        float* sC = (float*)(smem + 1024);
        #pragma unroll
        for (int mb = 0; mb < MB; mb++)
            #pragma unroll
            for (int nb = 0; nb < NB; nb++)
                #pragma unroll
                for (int r = 0; r < 4; r++) {
                    int m = warp_m + mb * 16 + qr + ((r >> 1) << 3);
                    int n = warp_n + nb * 8 + qc + (r & 1);
                    sC[n * PITCH + m] = fmaxf(acc[mb][nb][r] + bias_s[m], 0.f);
                }
        __syncthreads();
        constexpr int SEGS = CTAM / 8;            // 8-ch segments per pixel
        #pragma unroll
        for (int q = 0; q < (128 * SEGS) / 256; q++) {
            int idx = tid + q * 256;
            int px = idx / SEGS, sg = idx % SEGS;
            const float* src = sC + px * PITCH + sg * 8;
            __nv_bfloat16 hi[8], lo[8];
            #pragma unroll
            for (int j = 0; j < 8; j++) {
                float v = src[j];
                hi[j] = __float2bfloat16(v);
                lo[j] = __float2bfloat16(v - __bfloat162float(hi[j]));
            }
            size_t g = ((size_t)bz * HW_ + n0 + px) * 1024 + m0 + sg * 8;
            *(uint4*)(OutHi + g) = *(const uint4*)hi;
            *(uint4*)(OutLo + g) = *(const uint4*)lo;
        }
    } else {
        #pragma unroll
        for (int mb = 0; mb < MB; mb++)
            #pragma unroll
            for (int nb = 0; nb < NB; nb++)
                #pragma unroll
                for (int r = 0; r < 4; r++) {
                    int ml = warp_m + mb * 16 + qr + ((r >> 1) << 3);
                    int n  = warp_n + nb * 8 + qc + (r & 1);
                    int row = m0 + ml;
                    float v = acc[mb][nb][r] + bias_s[ml];
                    if (row < LDIM_)
                        OutF[((size_t)bz * LDIM_ + row) * HW_ + n0 + n] = v;
                    else if (row < LDIM_ + MCL_)
                        OutP[((size_t)bz * MCL_ + row - LDIM_) * HW_ + n0 + n] = v;
                }
    }
}

// layer-1: CTA 256x128, 8 warps @ 64x64 tiles
#define SMEM_L1 (1024 + 2 * (2 * 256 * 128 + 32768))   // 197632
// layer-2: CTA 128x128, 8 warps @ 64x32 tiles
#define SMEM_L2 (1024 + 2 * (2 * 128 * 128 + 32768))   // 132096

// -------------------------------------------------------------------------
// Token MLP (unchanged, passing since R1)
// -------------------------------------------------------------------------
__global__ void __launch_bounds__(256)
token_kernel(const float* __restrict__ t,
             const float* __restrict__ w1, const float* __restrict__ b1,
             const float* __restrict__ w2, const float* __restrict__ b2,
             float* __restrict__ out)
{
    const int b = blockIdx.x;
    const int tid = threadIdx.x, warp = tid >> 5, lane = tid & 31;

    __shared__ float ts[C_];
    __shared__ float h[HID_];
    __shared__ float tk[GDIM_];
    __shared__ float red[8];

    for (int i = tid; i < C_; i += 256) ts[i] = t[(size_t)b * C_ + i];
    __syncthreads();

    for (int j = warp; j < HID_; j += 8) {
        const float* wr = w1 + (size_t)j * C_;
        float s = 0.f;
        for (int k = lane * 4; k < C_; k += 128) {
            float4 w4 = *(const float4*)(wr + k);
            float4 t4 = *(const float4*)(ts + k);
            s += w4.x*t4.x + w4.y*t4.y + w4.z*t4.z + w4.w*t4.w;
        }
        #pragma unroll
        for (int o = 16; o; o >>= 1) s += __shfl_xor_sync(0xffffffffu, s, o);
        if (lane == 0) h[j] = fmaxf(s + b1[j], 0.f);
    }
    __syncthreads();

    for (int j = warp; j < GDIM_; j += 8) {
        const float* wr = w2 + (size_t)j * HID_;
        float s = 0.f;
        for (int k = lane * 4; k < HID_; k += 128) {
            float4 w4 = *(const float4*)(wr + k);
            float4 h4 = *(const float4*)(h + k);
            s += w4.x*h4.x + w4.y*h4.y + w4.z*h4.z + w4.w*h4.w;
        }
        #pragma unroll
        for (int o = 16; o; o >>= 1) s += __shfl_xor_sync(0xffffffffu, s, o);
        if (lane == 0) tk[j] = s + b2[j];
    }
    __syncthreads();

    float v = tk[tid];
    float sq = v * v;
    #pragma unroll
    for (int o = 16; o; o >>= 1) sq += __shfl_xor_sync(0xffffffffu, sq, o);
    if (lane == 0) red[warp] = sq;
    __syncthreads();
    if (warp == 0) {
        float r = (lane < 8) ? red[lane] : 0.f;
        #pragma unroll
        for (int o = 4; o; o >>= 1) r += __shfl_xor_sync(0xffffffffu, r, o);
        if (lane == 0) red[0] = r;
    }
    __syncthreads();
    const float inv = 1.f / fmaxf(sqrtf(red[0]), EPSV);
    out[(size_t)b * OUTD_ + tid] = v * inv;
}

// -------------------------------------------------------------------------
// Log-space Sinkhorn (unchanged, passing since R1)
// -------------------------------------------------------------------------
__global__ void __launch_bounds__(1024)
sinkhorn_kernel(float* __restrict__ Pg, const float* __restrict__ dust)
{
    const int b = blockIdx.x;
    float* Z = Pg + (size_t)b * MCL_ * HW_;
    const int tid = threadIdx.x, warp = tid >> 5, lane = tid & 31;

    __shared__ float u[MCL_ + 1];
    __shared__ float v[HW_];

    const float alpha = dust[0];
    const float norm_c     = -logf((float)(MCL_ + HW_));
    const float log_mu     = norm_c;
    const float log_mu_bin = logf((float)(HW_ - MCL_)) + norm_c;
    const float log_nu     = norm_c;

    v[tid] = 0.f;
    __syncthreads();

    for (int it = 0; it < 3; it++) {
        for (int i = warp; i < MCL_; i += 32) {
            const float* zr = Z + (size_t)i * HW_;
            float mx = -3.0e38f, s = 0.f;
            for (int j = lane; j < HW_; j += 32) {
                float zv = zr[j] + v[j];
                if (zv > mx) { s = s * __expf(mx - zv) + 1.f; mx = zv; }
                else           s += __expf(zv - mx);
            }
            #pragma unroll
            for (int o = 16; o; o >>= 1) {
                float mo = __shfl_xor_sync(0xffffffffu, mx, o);
                float so = __shfl_xor_sync(0xffffffffu, s,  o);
                float m2 = fmaxf(mx, mo);
                s  = s * __expf(mx - m2) + so * __expf(mo - m2);
                mx = m2;
            }
            if (lane == 0) u[i] = log_mu - (mx + __logf(s));
        }
        if (warp == 0) {
            float mx = -3.0e38f, s = 0.f;
            for (int j = lane; j < HW_; j += 32) {
                float zv = v[j];
                if (zv > mx) { s = s * __expf(mx - zv) + 1.f; mx = zv; }
                else           s += __expf(zv - mx);
            }
            #pragma unroll
            for (int o = 16; o; o >>= 1) {
                float mo = __shfl_xor_sync(0xffffffffu, mx, o);
                float so = __shfl_xor_sync(0xffffffffu, s,  o);
                float m2 = fmaxf(mx, mo);
                s  = s * __expf(mx - m2) + so * __expf(mo - m2);
                mx = m2;
            }
            if (lane == 0) u[MCL_] = log_mu_bin - (alpha + mx + __logf(s));
        }
        __syncthreads();

        {
            const int j = tid;
            float mx = alpha + u[MCL_];
            float s  = 1.f;
            #pragma unroll 4
            for (int i = 0; i < MCL_; i++) {
                float zv = Z[(size_t)i * HW_ + j] + u[i];
                if (zv > mx) { s = s * __expf(mx - zv) + 1.f; mx = zv; }
                else           s += __expf(zv - mx);
            }
            v[j] = log_nu - (mx + __logf(s));
        }
        __syncthreads();
    }

    {
        const int j = tid;
        const float vj = v[j] - norm_c;
        #pragma unroll 4
        for (int i = 0; i < MCL_; i++) {
            size_t idx = (size_t)i * HW_ + j;
            Z[idx] = __expf(Z[idx] + u[i] + vj);
        }
    }
}

// -------------------------------------------------------------------------
// VLAD aggregation, stage 1: partial agg over an HW quarter (no atomics).
// -------------------------------------------------------------------------
__global__ void __launch_bounds__(256)
agg_partial(const float* __restrict__ Fg, const float* __restrict__ Pg)
{
    const int sl = blockIdx.x;               // 0..3
    const int b  = blockIdx.y;
    const float* f = Fg + (size_t)b * LDIM_ * HW_;
    const float* p = Pg + (size_t)b * MCL_  * HW_;

    __shared__ __align__(16) float sbuf[32 * 129 + 32 * 65];
    float (*Fs)[129] = (float(*)[129])sbuf;
    float (*Ps)[65]  = (float(*)[65])(sbuf + 32 * 129);

    const int tid = threadIdx.x;
    const int tr = tid >> 4, tc = tid & 15;

    float acc[8][4];
    #pragma unroll
    for (int i = 0; i < 8; i++)
        #pragma unroll
        for (int j = 0; j < 4; j++) acc[i][j] = 0.f;

    const int nbeg = sl * 256, nend = nbeg + 256;
    for (int n0 = nbeg; n0 < nend; n0 += 32) {
        #pragma unroll
        for (int q = 0; q < 16; q++) {
            int idx = tid + q * 256;
            int l = idx >> 5, n = idx & 31;
            Fs[n][l] = f[(size_t)l * HW_ + n0 + n];
        }
        #pragma unroll
        for (int q = 0; q < 8; q++) {
            int idx = tid + q * 256;
            int m = idx >> 5, n = idx & 31;
            Ps[n][m] = p[(size_t)m * HW_ + n0 + n];
        }
        __syncthreads();

        #pragma unroll
        for (int n = 0; n < 32; n++) {
            float rf[8], rp[4];
            #pragma unroll
            for (int i = 0; i < 8; i++) rf[i] = Fs[n][tr*8 + i];
            #pragma unroll
            for (int j = 0; j < 4; j++) rp[j] = Ps[n][tc*4 + j];
            #pragma unroll
            for (int i = 0; i < 8; i++)
                #pragma unroll
                for (int j = 0; j < 4; j++)
                    acc[i][j] = fmaf(rf[i], rp[j], acc[i][j]);
        }
        __syncthreads();
    }

    float* dst = g_aggp + (((size_t)sl * B_ + b) * LDIM_) * MCL_;
    #pragma unroll
    for (int i = 0; i < 8; i++)
        #pragma unroll
        for (int j = 0; j < 4; j++)
            dst[(size_t)(tr*8 + i) * MCL_ + tc*4 + j] = acc[i][j];
}

// -------------------------------------------------------------------------
// VLAD aggregation, stage 2: sum 4 partials, per-cluster L2 over l, write out.
// -------------------------------------------------------------------------
__global__ void __launch_bounds__(256)
agg_norm(float* __restrict__ out)
{
    const int b = blockIdx.x;
    __shared__ __align__(16) float sbuf[128 * 65 + 64];
    float (*Cs)[65] = (float(*)[65])sbuf;
    float* nrm = sbuf + 128 * 65;
    const int tid = threadIdx.x;

    #pragma unroll
    for (int q = 0; q < 32; q++) {
        int idx = tid + q * 256;               // 8192 = 128*64
        int l = idx >> 6, m = idx & 63;
        float s = 0.f;
        #pragma unroll
        for (int sl = 0; sl < 4; sl++)
            s += g_aggp[(((size_t)sl * B_ + b) * LDIM_ + l) * MCL_ + m];
        Cs[l][m] = s;
    }
    __syncthreads();
    if (tid < MCL_) {
        float s = 0.f;
        for (int l = 0; l < LDIM_; l++) { float c = Cs[l][tid]; s += c * c; }
        nrm[tid] = 1.f / fmaxf(sqrtf(s), EPSV);
    }
    __syncthreads();
    float* orow = out + (size_t)b * OUTD_ + GDIM_;
    #pragma unroll
    for (int q = 0; q < 32; q++) {
        int idx = tid + q * 256;
        int l = idx >> 6, m = idx & 63;
        orow[idx] = Cs[l][m] * nrm[m];
    }
}

// -------------------------------------------------------------------------
// Final row L2 normalization (unchanged, passing since R1)
// -------------------------------------------------------------------------
__global__ void __launch_bounds__(256)
rownorm_kernel(float* __restrict__ out)
{
    const int b = blockIdx.x;
    float* row = out + (size_t)b * OUTD_;
    const int tid = threadIdx.x, warp = tid >> 5, lane = tid & 31;
    __shared__ float red[8];

    float s = 0.f;
    for (int i = tid; i < OUTD_; i += 256) { float x = row[i]; s += x * x; }
    #pragma unroll
    for (int o = 16; o; o >>= 1) s += __shfl_xor_sync(0xffffffffu, s, o);
    if (lane == 0) red[warp] = s;
    __syncthreads();
    if (warp == 0) {
        float r = (lane < 8) ? red[lane] : 0.f;
        #pragma unroll
        for (int o = 4; o; o >>= 1) r += __shfl_xor_sync(0xffffffffu, r, o);
        if (lane == 0) red[0] = r;
    }
    __syncthreads();
    const float inv = 1.f / fmaxf(sqrtf(red[0]), EPSV);
    for (int i = tid; i < OUTD_; i += 256) row[i] *= inv;
}

// -------------------------------------------------------------------------
// Launch
// -------------------------------------------------------------------------
extern "C" void kernel_launch(void* const* d_in, const int* in_sizes, int n_in,
                              void* d_out, int out_size)
{
    const float* x     = (const float*)d_in[0];
    const float* t     = (const float*)d_in[1];
    const float* cf_w1 = (const float*)d_in[2];
    const float* cf_b1 = (const float*)d_in[3];
    const float* cf_w2 = (const float*)d_in[4];
    const float* cf_b2 = (const float*)d_in[5];
    const float* sc_w1 = (const float*)d_in[6];
    const float* sc_b1 = (const float*)d_in[7];
    const float* sc_w2 = (const float*)d_in[8];
    const float* sc_b2 = (const float*)d_in[9];
    const float* tk_w1 = (const float*)d_in[10];
    const float* tk_b1 = (const float*)d_in[11];
    const float* tk_w2 = (const float*)d_in[12];
    const float* tk_b2 = (const float*)d_in[13];
    const float* dust  = (const float*)d_in[14];
    float* out = (float*)d_out;

    __nv_bfloat16 *xTh, *xTl, *W1h, *W1l, *W2h, *W2l, *Hth, *Htl;
    float *b1s, *b2s, *F, *P;
    cudaGetSymbolAddress((void**)&xTh, g_xT_hi);
    cudaGetSymbolAddress((void**)&xTl, g_xT_lo);
    cudaGetSymbolAddress((void**)&W1h, g_W1hi);
    cudaGetSymbolAddress((void**)&W1l, g_W1lo);
    cudaGetSymbolAddress((void**)&W2h, g_W2hi);
    cudaGetSymbolAddress((void**)&W2l, g_W2lo);
    cudaGetSymbolAddress((void**)&Hth, g_Ht_hi);
    cudaGetSymbolAddress((void**)&Htl, g_Ht_lo);
    cudaGetSymbolAddress((void**)&b1s, g_b1s);
    cudaGetSymbolAddress((void**)&b2s, g_b2s);
    cudaGetSymbolAddress((void**)&F,   g_F);
    cudaGetSymbolAddress((void**)&P,   g_P);

    cudaFuncSetAttribute((gemm_mma<1536, 1536, 1, 256, 4, 2>),
                         cudaFuncAttributeMaxDynamicSharedMemorySize, SMEM_L1);
    cudaFuncSetAttribute((gemm_mma<512, 1024, 2, 128, 2, 4>),
                         cudaFuncAttributeMaxDynamicSharedMemorySize, SMEM_L2);

    // Prep: weight stacking/splitting + x transpose/split
    prep_w1<<<1024, 256>>>(cf_w1, cf_b1, sc_w1, sc_b1);
    prep_w2<<<256, 128>>>(cf_w2, cf_b2, sc_w2, sc_b2);
    transpose_split_x<<<dim3(HW_/32, C_/32, B_), 256>>>(x);

    // Layer 1 (fused cf+sc): Ht[b, px, 1024ch] = relu(W1 @ x + b1), bf16 hi/lo
    gemm_mma<1536, 1536, 1, 256, 4, 2><<<dim3(HW_/128, 1024/256, B_), 256, SMEM_L1>>>(
        W1h, W1l, xTh, xTl, b1s, Hth, Htl, nullptr, nullptr);

    // Layer 2 (fused cf+sc): F fp32 [B,128,HW], P fp32 [B,64,HW]
    gemm_mma<512, 1024, 2, 128, 2, 4><<<dim3(HW_/128, 2, B_), 256, SMEM_L2>>>(
        W2h, W2l, Hth, Htl, b2s, nullptr, nullptr, F, P);

    // Token MLP -> out[:, 0:256]
    token_kernel<<<B_, 256>>>(t, tk_w1, tk_b1, tk_w2, tk_b2, out);

    // Sinkhorn + parallel VLAD aggregation + final norm
    sinkhorn_kernel<<<B_, 1024>>>(P, dust);
    agg_partial<<<dim3(4, B_), 256>>>(F, P);
    agg_norm<<<B_, 256>>>(out);
    rownorm_kernel<<<B_, 256>>>(out);
}

// round 9
// speedup vs baseline: 4.4419x; 1.6863x over previous
#include <cuda_runtime.h>
#include <cuda_fp16.h>
#include <math.h>
#include <stdint.h>

// Problem constants
#define B_    32
#define C_    1536
#define HW_   1024      // 32*32
#define HID_  512
#define LDIM_ 128
#define MCL_  64
#define GDIM_ 256
#define OUTD_ (GDIM_ + LDIM_*MCL_)   // 8448
#define EPSV  1e-12f

// -------------------------------------------------------------------------
// Scratch (__device__ globals: allocation-free, graph-capture safe)
// -------------------------------------------------------------------------
__device__ __align__(256) __half g_xT[(size_t)B_ * HW_ * C_];     // pixel-major fp16
__device__ __align__(256) __half g_W1[1024 * C_];
__device__ __align__(256) __half g_W2[256 * HID_];
__device__ __align__(256) float  g_b1s[1024];
__device__ __align__(256) float  g_b2s[256];
__device__ __align__(256) __half g_Ht[(size_t)B_ * HW_ * 1024];   // pixel-major fp16
__device__ __align__(256) float  g_F[(size_t)B_ * LDIM_ * HW_];
__device__ __align__(256) float  g_P[(size_t)B_ * MCL_  * HW_];
__device__ __align__(256) float  g_aggp[4 * B_ * LDIM_ * MCL_];   // 4 HW-slices

// -------------------------------------------------------------------------
// PTX helpers (family-agnostic: mma.sync / ldmatrix / cp.async)
// -------------------------------------------------------------------------
__device__ __forceinline__ uint32_t smem_u32(const void* p) {
    uint32_t a;
    asm("{ .reg .u64 t; cvta.to.shared.u64 t, %1; cvt.u32.u64 %0, t; }" : "=r"(a) : "l"(p));
    return a;
}
__device__ __forceinline__ void cp16(uint32_t dst, const void* src) {
    asm volatile("cp.async.cg.shared.global [%0], [%1], 16;" :: "r"(dst), "l"(src));
}
#define CP_COMMIT() asm volatile("cp.async.commit_group;" ::: "memory")
#define CP_WAIT(n)  asm volatile("cp.async.wait_group %0;" :: "n"(n) : "memory")

__device__ __forceinline__ void ldsm4(uint32_t* r, uint32_t addr) {
    asm volatile("ldmatrix.sync.aligned.m8n8.x4.shared.b16 {%0,%1,%2,%3}, [%4];"
        : "=r"(r[0]), "=r"(r[1]), "=r"(r[2]), "=r"(r[3]) : "r"(addr));
}
__device__ __forceinline__ void mma16816(float* c, const uint32_t* a, const uint32_t* b) {
    asm volatile(
        "mma.sync.aligned.m16n8k16.row.col.f32.f16.f16.f32 "
        "{%0,%1,%2,%3}, {%4,%5,%6,%7}, {%8,%9}, {%0,%1,%2,%3};"
        : "+f"(c[0]), "+f"(c[1]), "+f"(c[2]), "+f"(c[3])
        : "r"(a[0]), "r"(a[1]), "r"(a[2]), "r"(a[3]), "r"(b[0]), "r"(b[1]));
}
__device__ __forceinline__ uint32_t swz(uint32_t off) {      // SW128-style 16B-chunk XOR
    return off ^ ((off >> 3) & 0x70);
}

// -------------------------------------------------------------------------
// Weight prep: stack + fp16 convert
// -------------------------------------------------------------------------
__global__ void prep_w1(const float* __restrict__ cf_w1, const float* __restrict__ cf_b1,
                        const float* __restrict__ sc_w1, const float* __restrict__ sc_b1)
{
    const int r = blockIdx.x;               // 0..1023
    const float* src = (r < HID_) ? cf_w1 + (size_t)r * C_ : sc_w1 + (size_t)(r - HID_) * C_;
    for (int i = threadIdx.x; i < C_; i += blockDim.x)
        g_W1[(size_t)r * C_ + i] = __float2half_rn(src[i]);
    if (threadIdx.x == 0)
        g_b1s[r] = (r < HID_) ? cf_b1[r] : sc_b1[r - HID_];
}

__global__ void prep_w2(const float* __restrict__ cf_w2, const float* __restrict__ cf_b2,
                        const float* __restrict__ sc_w2, const float* __restrict__ sc_b2)
{
    const int r = blockIdx.x;               // 0..255
    const float* src = (r < LDIM_) ? cf_w2 + (size_t)r * HID_
                     : (r < LDIM_ + MCL_) ? sc_w2 + (size_t)(r - LDIM_) * HID_ : nullptr;
    for (int i = threadIdx.x; i < HID_; i += blockDim.x)
        g_W2[(size_t)r * HID_ + i] = __float2half_rn(src ? src[i] : 0.f);
    if (threadIdx.x == 0)
        g_b2s[r] = (r < LDIM_) ? cf_b2[r] : (r < LDIM_ + MCL_) ? sc_b2[r - LDIM_] : 0.f;
}

// -------------------------------------------------------------------------
// x [B, C, HW] fp32  ->  xT [B, HW, C] fp16  (32x32 smem transpose)
// -------------------------------------------------------------------------
__global__ void __launch_bounds__(256)
transpose_x(const float* __restrict__ x)
{
    __shared__ float s[32][33];
    const int n0 = blockIdx.x * 32;
    const int c0 = blockIdx.y * 32;
    const int b  = blockIdx.z;
    const int tx = threadIdx.x & 31, ty = threadIdx.x >> 5;

    #pragma unroll
    for (int q = 0; q < 4; q++) {
        int c = ty + q * 8;
        s[c][tx] = x[((size_t)b * C_ + c0 + c) * HW_ + n0 + tx];
    }
    __syncthreads();

    const int n  = threadIdx.x >> 3;            // 0..31
    const int cs = (threadIdx.x & 7) * 4;       // 0..28
    __half h4[4];
    #pragma unroll
    for (int j = 0; j < 4; j++) h4[j] = __float2half_rn(s[cs + j][n]);
    size_t idx = ((size_t)b * HW_ + n0 + n) * C_ + c0 + cs;
    *(uint2*)(g_xT + idx) = *(const uint2*)h4;
}

// -------------------------------------------------------------------------
// Tensor-core GEMM via mma.sync (single-pass fp16, fp32 accum):
//   D[m,n] = sum_k A[m,k]*B[n,k]
// CTA = CTAM x 128, 8 warps (WGM x WGN), warp tile (CTAM/WGM) x (128/WGN).
// BK=64, 3-stage cp.async pipeline, one __syncthreads per chunk.
// EPI=1: bias+relu -> fp16 -> pixel-major Ht (via smem transpose).
// EPI=2: bias -> fp32 F (rows<128) / P (rows 128..191), channel-major.
// -------------------------------------------------------------------------
template<int KDIM, int BSTR, int EPI, int CTAM, int WGM, int WGN>
__global__ void __launch_bounds__(256)
gemm_mma(const __half* __restrict__ Ag, const __half* __restrict__ Bg,
         const float* __restrict__ bias,
         __half* __restrict__ OutH, float* __restrict__ OutF, float* __restrict__ OutP)
{
    constexpr int NCHUNK  = KDIM / 64;
    constexpr int A_BYTES = CTAM * 128;          // CTAM x 64 fp16
    constexpr int STAGE   = A_BYTES + 16384;     // + 128 x 64 fp16 B tile
    constexpr int WTM = CTAM / WGM, WTN = 128 / WGN;
    constexpr int MB = WTM / 16, NB = WTN / 8, NBP = WTN / 16;
    constexpr int AIT = (CTAM * 8) / 256;        // 16B chunks of A per thread

    extern __shared__ __align__(1024) char smem[];
    const uint32_t sbase = smem_u32(smem);
    float* bias_s = (float*)smem;                // CTAM floats (<=1024B)

    const int tid  = threadIdx.x;
    const int wid  = tid >> 5, lane = tid & 31;
    const int n0   = blockIdx.x * 128;
    const int m0   = blockIdx.y * CTAM;
    const int bz   = blockIdx.z;
    const int koff = (EPI == 2) ? blockIdx.y * 512 : 0;

    const int warp_m = (wid / WGN) * WTM;
    const int warp_n = (wid % WGN) * WTN;

    if (tid < CTAM) bias_s[tid] = bias[m0 + tid];

    const size_t bRow = (size_t)bz * HW_ + n0;

    auto load_stage = [&](int c, int stage) {
        const uint32_t base = sbase + 1024 + stage * STAGE;
        #pragma unroll
        for (int q = 0; q < AIT; q++) {
            int idx = tid + q * 256;
            int row = idx >> 3, seg = idx & 7;
            cp16(base + swz(row * 128 + seg * 16),
                 Ag + (size_t)(m0 + row) * KDIM + c * 64 + seg * 8);
        }
        const uint32_t bbuf = base + A_BYTES;
        #pragma unroll
        for (int q = 0; q < 4; q++) {
            int idx = tid + q * 256;
            int row = idx >> 3, seg = idx & 7;
            cp16(bbuf + swz(row * 128 + seg * 16),
                 Bg + (bRow + row) * BSTR + koff + c * 64 + seg * 8);
        }
        CP_COMMIT();
    };

    float acc[MB][NB][4];
    #pragma unroll
    for (int i = 0; i < MB; i++)
        #pragma unroll
        for (int j = 0; j < NB; j++)
            #pragma unroll
            for (int r = 0; r < 4; r++) acc[i][j][r] = 0.f;

    load_stage(0, 0);
    if (NCHUNK > 1) load_stage(1, 1);

    #pragma unroll 1
    for (int c = 0; c < NCHUNK; c++) {
        if (c + 1 < NCHUNK) { CP_WAIT(1); }       // chunk c complete
        else                { CP_WAIT(0); }
        __syncthreads();                          // data visible; stage (c+2)%3 free

        if (c + 2 < NCHUNK) load_stage(c + 2, (c + 2) % 3);

        const uint32_t aBase = sbase + 1024 + (c % 3) * STAGE;
        const uint32_t bBase = aBase + A_BYTES;

        #pragma unroll
        for (int s = 0; s < 4; s++) {
            uint32_t af[MB][4], bf[NB][2];
            #pragma unroll
            for (int mb = 0; mb < MB; mb++) {
                int row = warp_m + mb * 16 + (lane & 15);
                uint32_t off = swz(row * 128 + s * 32 + ((lane >> 4) << 4));
                ldsm4(af[mb], aBase + off);
            }
            #pragma unroll
            for (int nbp = 0; nbp < NBP; nbp++) {
                int grp = lane >> 3;
                int row = warp_n + nbp * 16 + ((grp >> 1) << 3) + (lane & 7);
                uint32_t off = swz(row * 128 + s * 32 + ((grp & 1) << 4));
                uint32_t t[4];
                ldsm4(t, bBase + off);
                bf[nbp*2][0] = t[0]; bf[nbp*2][1] = t[1];
                bf[nbp*2+1][0] = t[2]; bf[nbp*2+1][1] = t[3];
            }
            #pragma unroll
            for (int mb = 0; mb < MB; mb++)
                #pragma unroll
                for (int nb = 0; nb < NB; nb++) mma16816(acc[mb][nb], af[mb], bf[nb]);
        }
    }
    __syncthreads();   // all warps done with stage smem before epilogue reuse

    // ---------------- epilogue ----------------
    const int qr = lane >> 2, qc = (lane & 3) * 2;

    if (EPI == 1) {
        // stage to smem transposed: sC[n][m], pitch CTAM+4
        constexpr int PITCH = CTAM + 4;
        float* sC = (float*)(smem + 1024);
        #pragma unroll
        for (int mb = 0; mb < MB; mb++)
            #pragma unroll
            for (int nb = 0; nb < NB; nb++)
                #pragma unroll
                for (int r = 0; r < 4; r++) {
                    int m = warp_m + mb * 16 + qr + ((r >> 1) << 3);
                    int n = warp_n + nb * 8 + qc + (r & 1);
                    sC[n * PITCH + m] = fmaxf(acc[mb][nb][r] + bias_s[m], 0.f);
                }
        __syncthreads();
        constexpr int SEGS = CTAM / 8;            // 8-ch segments per pixel
        #pragma unroll
        for (int q = 0; q < (128 * SEGS) / 256; q++) {
            int idx = tid + q * 256;
            int px = idx / SEGS, sg = idx % SEGS;
            const float* src = sC + px * PITCH + sg * 8;
            __half h8[8];
            #pragma unroll
            for (int j = 0; j < 8; j++) h8[j] = __float2half_rn(src[j]);
            size_t g = ((size_t)bz * HW_ + n0 + px) * 1024 + m0 + sg * 8;
            *(uint4*)(OutH + g) = *(const uint4*)h8;
        }
    } else {
        #pragma unroll
        for (int mb = 0; mb < MB; mb++)
            #pragma unroll
            for (int nb = 0; nb < NB; nb++)
                #pragma unroll
                for (int r = 0; r < 4; r++) {
                    int ml = warp_m + mb * 16 + qr + ((r >> 1) << 3);
                    int n  = warp_n + nb * 8 + qc + (r & 1);
                    int row = m0 + ml;
                    float v = acc[mb][nb][r] + bias_s[ml];
                    if (row < LDIM_)
                        OutF[((size_t)bz * LDIM_ + row) * HW_ + n0 + n] = v;
                    else if (row < LDIM_ + MCL_)
                        OutP[((size_t)bz * MCL_ + row - LDIM_) * HW_ + n0 + n] = v;
                }
    }
}

// layer-1: CTA 256x128, 8 warps @ 64x64 tiles, 3 stages of 48KB
#define SMEM_L1 (1024 + 3 * (256 * 128 + 16384))   // 148480
// layer-2: CTA 128x128, 8 warps @ 64x32 tiles, 3 stages of 32KB
#define SMEM_L2 (1024 + 3 * (128 * 128 + 16384))   // 99328

// -------------------------------------------------------------------------
// Token MLP (unchanged, passing since R1)
// -------------------------------------------------------------------------
__global__ void __launch_bounds__(256)
token_kernel(const float* __restrict__ t,
             const float* __restrict__ w1, const float* __restrict__ b1,
             const float* __restrict__ w2, const float* __restrict__ b2,
             float* __restrict__ out)
{
    const int b = blockIdx.x;
    const int tid = threadIdx.x, warp = tid >> 5, lane = tid & 31;

    __shared__ float ts[C_];
    __shared__ float h[HID_];
    __shared__ float tk[GDIM_];
    __shared__ float red[8];

    for (int i = tid; i < C_; i += 256) ts[i] = t[(size_t)b * C_ + i];
    __syncthreads();

    for (int j = warp; j < HID_; j += 8) {
        const float* wr = w1 + (size_t)j * C_;
        float s = 0.f;
        for (int k = lane * 4; k < C_; k += 128) {
            float4 w4 = *(const float4*)(wr + k);
            float4 t4 = *(const float4*)(ts + k);
            s += w4.x*t4.x + w4.y*t4.y + w4.z*t4.z + w4.w*t4.w;
        }
        #pragma unroll
        for (int o = 16; o; o >>= 1) s += __shfl_xor_sync(0xffffffffu, s, o);
        if (lane == 0) h[j] = fmaxf(s + b1[j], 0.f);
    }
    __syncthreads();

    for (int j = warp; j < GDIM_; j += 8) {
        const float* wr = w2 + (size_t)j * HID_;
        float s = 0.f;
        for (int k = lane * 4; k < HID_; k += 128) {
            float4 w4 = *(const float4*)(wr + k);
            float4 h4 = *(const float4*)(h + k);
            s += w4.x*h4.x + w4.y*h4.y + w4.z*h4.z + w4.w*h4.w;
        }
        #pragma unroll
        for (int o = 16; o; o >>= 1) s += __shfl_xor_sync(0xffffffffu, s, o);
        if (lane == 0) tk[j] = s + b2[j];
    }
    __syncthreads();

    float v = tk[tid];
    float sq = v * v;
    #pragma unroll
    for (int o = 16; o; o >>= 1) sq += __shfl_xor_sync(0xffffffffu, sq, o);
    if (lane == 0) red[warp] = sq;
    __syncthreads();
    if (warp == 0) {
        float r = (lane < 8) ? red[lane] : 0.f;
        #pragma unroll
        for (int o = 4; o; o >>= 1) r += __shfl_xor_sync(0xffffffffu, r, o);
        if (lane == 0) red[0] = r;
    }
    __syncthreads();
    const float inv = 1.f / fmaxf(sqrtf(red[0]), EPSV);
    out[(size_t)b * OUTD_ + tid] = v * inv;
}

// -------------------------------------------------------------------------
// Log-space Sinkhorn (unchanged, passing since R1)
// -------------------------------------------------------------------------
__global__ void __launch_bounds__(1024)
sinkhorn_kernel(float* __restrict__ Pg, const float* __restrict__ dust)
{
    const int b = blockIdx.x;
    float* Z = Pg + (size_t)b * MCL_ * HW_;
    const int tid = threadIdx.x, warp = tid >> 5, lane = tid & 31;

    __shared__ float u[MCL_ + 1];
    __shared__ float v[HW_];

    const float alpha = dust[0];
    const float norm_c     = -logf((float)(MCL_ + HW_));
    const float log_mu     = norm_c;
    const float log_mu_bin = logf((float)(HW_ - MCL_)) + norm_c;
    const float log_nu     = norm_c;

    v[tid] = 0.f;
    __syncthreads();

    for (int it = 0; it < 3; it++) {
        for (int i = warp; i < MCL_; i += 32) {
            const float* zr = Z + (size_t)i * HW_;
            float mx = -3.0e38f, s = 0.f;
            for (int j = lane; j < HW_; j += 32) {
                float zv = zr[j] + v[j];
                if (zv > mx) { s = s * __expf(mx - zv) + 1.f; mx = zv; }
                else           s += __expf(zv - mx);
            }
            #pragma unroll
            for (int o = 16; o; o >>= 1) {
                float mo = __shfl_xor_sync(0xffffffffu, mx, o);
                float so = __shfl_xor_sync(0xffffffffu, s,  o);
                float m2 = fmaxf(mx, mo);
                s  = s * __expf(mx - m2) + so * __expf(mo - m2);
                mx = m2;
            }
            if (lane == 0) u[i] = log_mu - (mx + __logf(s));
        }
        if (warp == 0) {
            float mx = -3.0e38f, s = 0.f;
            for (int j = lane; j < HW_; j += 32) {
                float zv = v[j];
                if (zv > mx) { s = s * __expf(mx - zv) + 1.f; mx = zv; }
                else           s += __expf(zv - mx);
            }
            #pragma unroll
            for (int o = 16; o; o >>= 1) {
                float mo = __shfl_xor_sync(0xffffffffu, mx, o);
                float so = __shfl_xor_sync(0xffffffffu, s,  o);
                float m2 = fmaxf(mx, mo);
                s  = s * __expf(mx - m2) + so * __expf(mo - m2);
                mx = m2;
            }
            if (lane == 0) u[MCL_] = log_mu_bin - (alpha + mx + __logf(s));
        }
        __syncthreads();

        {
            const int j = tid;
            float mx = alpha + u[MCL_];
            float s  = 1.f;
            #pragma unroll 4
            for (int i = 0; i < MCL_; i++) {
                float zv = Z[(size_t)i * HW_ + j] + u[i];
                if (zv > mx) { s = s * __expf(mx - zv) + 1.f; mx = zv; }
                else           s += __expf(zv - mx);
            }
            v[j] = log_nu - (mx + __logf(s));
        }
        __syncthreads();
    }

    {
        const int j = tid;
        const float vj = v[j] - norm_c;
        #pragma unroll 4
        for (int i = 0; i < MCL_; i++) {
            size_t idx = (size_t)i * HW_ + j;
            Z[idx] = __expf(Z[idx] + u[i] + vj);
        }
    }
}

// -------------------------------------------------------------------------
// VLAD aggregation, stage 1: partial agg over an HW quarter (no atomics).
// -------------------------------------------------------------------------
__global__ void __launch_bounds__(256)
agg_partial(const float* __restrict__ Fg, const float* __restrict__ Pg)
{
    const int sl = blockIdx.x;               // 0..3
    const int b  = blockIdx.y;
    const float* f = Fg + (size_t)b * LDIM_ * HW_;
    const float* p = Pg + (size_t)b * MCL_  * HW_;

    __shared__ __align__(16) float sbuf[32 * 129 + 32 * 65];
    float (*Fs)[129] = (float(*)[129])sbuf;
    float (*Ps)[65]  = (float(*)[65])(sbuf + 32 * 129);

    const int tid = threadIdx.x;
    const int tr = tid >> 4, tc = tid & 15;

    float acc[8][4];
    #pragma unroll
    for (int i = 0; i < 8; i++)
        #pragma unroll
        for (int j = 0; j < 4; j++) acc[i][j] = 0.f;

    const int nbeg = sl * 256, nend = nbeg + 256;
    for (int n0 = nbeg; n0 < nend; n0 += 32) {
        #pragma unroll
        for (int q = 0; q < 16; q++) {
            int idx = tid + q * 256;
            int l = idx >> 5, n = idx & 31;
            Fs[n][l] = f[(size_t)l * HW_ + n0 + n];
        }
        #pragma unroll
        for (int q = 0; q < 8; q++) {
            int idx = tid + q * 256;
            int m = idx >> 5, n = idx & 31;
            Ps[n][m] = p[(size_t)m * HW_ + n0 + n];
        }
        __syncthreads();

        #pragma unroll
        for (int n = 0; n < 32; n++) {
            float rf[8], rp[4];
            #pragma unroll
            for (int i = 0; i < 8; i++) rf[i] = Fs[n][tr*8 + i];
            #pragma unroll
            for (int j = 0; j < 4; j++) rp[j] = Ps[n][tc*4 + j];
            #pragma unroll
            for (int i = 0; i < 8; i++)
                #pragma unroll
                for (int j = 0; j < 4; j++)
                    acc[i][j] = fmaf(rf[i], rp[j], acc[i][j]);
        }
        __syncthreads();
    }

    float* dst = g_aggp + (((size_t)sl * B_ + b) * LDIM_) * MCL_;
    #pragma unroll
    for (int i = 0; i < 8; i++)
        #pragma unroll
        for (int j = 0; j < 4; j++)
            dst[(size_t)(tr*8 + i) * MCL_ + tc*4 + j] = acc[i][j];
}

// -------------------------------------------------------------------------
// VLAD aggregation, stage 2: sum 4 partials, per-cluster L2 over l, write out.
// -------------------------------------------------------------------------
__global__ void __launch_bounds__(256)
agg_norm(float* __restrict__ out)
{
    const int b = blockIdx.x;
    __shared__ __align__(16) float sbuf[128 * 65 + 64];
    float (*Cs)[65] = (float(*)[65])sbuf;
    float* nrm = sbuf + 128 * 65;
    const int tid = threadIdx.x;

    #pragma unroll
    for (int q = 0; q < 32; q++) {
        int idx = tid + q * 256;               // 8192 = 128*64
        int l = idx >> 6, m = idx & 63;
        float s = 0.f;
        #pragma unroll
        for (int sl = 0; sl < 4; sl++)
            s += g_aggp[(((size_t)sl * B_ + b) * LDIM_ + l) * MCL_ + m];
        Cs[l][m] = s;
    }
    __syncthreads();
    if (tid < MCL_) {
        float s = 0.f;
        for (int l = 0; l < LDIM_; l++) { float c = Cs[l][tid]; s += c * c; }
        nrm[tid] = 1.f / fmaxf(sqrtf(s), EPSV);
    }
    __syncthreads();
    float* orow = out + (size_t)b * OUTD_ + GDIM_;
    #pragma unroll
    for (int q = 0; q < 32; q++) {
        int idx = tid + q * 256;
        int l = idx >> 6, m = idx & 63;
        orow[idx] = Cs[l][m] * nrm[m];
    }
}

// -------------------------------------------------------------------------
// Final row L2 normalization (unchanged, passing since R1)
// -------------------------------------------------------------------------
__global__ void __launch_bounds__(256)
rownorm_kernel(float* __restrict__ out)
{
    const int b = blockIdx.x;
    float* row = out + (size_t)b * OUTD_;
    const int tid = threadIdx.x, warp = tid >> 5, lane = tid & 31;
    __shared__ float red[8];

    float s = 0.f;
    for (int i = tid; i < OUTD_; i += 256) { float x = row[i]; s += x * x; }
    #pragma unroll
    for (int o = 16; o; o >>= 1) s += __shfl_xor_sync(0xffffffffu, s, o);
    if (lane == 0) red[warp] = s;
    __syncthreads();
    if (warp == 0) {
        float r = (lane < 8) ? red[lane] : 0.f;
        #pragma unroll
        for (int o = 4; o; o >>= 1) r += __shfl_xor_sync(0xffffffffu, r, o);
        if (lane == 0) red[0] = r;
    }
    __syncthreads();
    const float inv = 1.f / fmaxf(sqrtf(red[0]), EPSV);
    for (int i = tid; i < OUTD_; i += 256) row[i] *= inv;
}

// -------------------------------------------------------------------------
// Launch
// -------------------------------------------------------------------------
extern "C" void kernel_launch(void* const* d_in, const int* in_sizes, int n_in,
                              void* d_out, int out_size)
{
    const float* x     = (const float*)d_in[0];
    const float* t     = (const float*)d_in[1];
    const float* cf_w1 = (const float*)d_in[2];
    const float* cf_b1 = (const float*)d_in[3];
    const float* cf_w2 = (const float*)d_in[4];
    const float* cf_b2 = (const float*)d_in[5];
    const float* sc_w1 = (const float*)d_in[6];
    const float* sc_b1 = (const float*)d_in[7];
    const float* sc_w2 = (const float*)d_in[8];
    const float* sc_b2 = (const float*)d_in[9];
    const float* tk_w1 = (const float*)d_in[10];
    const float* tk_b1 = (const float*)d_in[11];
    const float* tk_w2 = (const float*)d_in[12];
    const float* tk_b2 = (const float*)d_in[13];
    const float* dust  = (const float*)d_in[14];
    float* out = (float*)d_out;

    __half *xT, *W1, *W2, *Ht;
    float *b1s, *b2s, *F, *P;
    cudaGetSymbolAddress((void**)&xT,  g_xT);
    cudaGetSymbolAddress((void**)&W1,  g_W1);
    cudaGetSymbolAddress((void**)&W2,  g_W2);
    cudaGetSymbolAddress((void**)&Ht,  g_Ht);
    cudaGetSymbolAddress((void**)&b1s, g_b1s);
    cudaGetSymbolAddress((void**)&b2s, g_b2s);
    cudaGetSymbolAddress((void**)&F,   g_F);
    cudaGetSymbolAddress((void**)&P,   g_P);

    cudaFuncSetAttribute((gemm_mma<1536, 1536, 1, 256, 4, 2>),
                         cudaFuncAttributeMaxDynamicSharedMemorySize, SMEM_L1);
    cudaFuncSetAttribute((gemm_mma<512, 1024, 2, 128, 2, 4>),
                         cudaFuncAttributeMaxDynamicSharedMemorySize, SMEM_L2);

    // Prep: weight stacking/fp16 + x transpose/fp16
    prep_w1<<<1024, 256>>>(cf_w1, cf_b1, sc_w1, sc_b1);
    prep_w2<<<256, 128>>>(cf_w2, cf_b2, sc_w2, sc_b2);
    transpose_x<<<dim3(HW_/32, C_/32, B_), 256>>>(x);

    // Layer 1 (fused cf+sc): Ht[b, px, 1024ch] = relu(W1 @ x + b1), fp16
    gemm_mma<1536, 1536, 1, 256, 4, 2><<<dim3(HW_/128, 1024/256, B_), 256, SMEM_L1>>>(
        W1, xT, b1s, Ht, nullptr, nullptr);

    // Layer 2 (fused cf+sc): F fp32 [B,128,HW], P fp32 [B,64,HW]
    gemm_mma<512, 1024, 2, 128, 2, 4><<<dim3(HW_/128, 2, B_), 256, SMEM_L2>>>(
        W2, Ht, b2s, nullptr, F, P);

    // Token MLP -> out[:, 0:256]
    token_kernel<<<B_, 256>>>(t, tk_w1, tk_b1, tk_w2, tk_b2, out);

    // Sinkhorn + parallel VLAD aggregation + final norm
    sinkhorn_kernel<<<B_, 1024>>>(P, dust);
    agg_partial<<<dim3(4, B_), 256>>>(F, P);
    agg_norm<<<B_, 256>>>(out);
    rownorm_kernel<<<B_, 256>>>(out);
}

// round 10
// speedup vs baseline: 4.7415x; 1.0675x over previous
#include <cuda_runtime.h>
#include <cuda_fp16.h>
#include <math.h>
#include <stdint.h>

// Problem constants
#define B_    32
#define C_    1536
#define HW_   1024      // 32*32
#define HID_  512
#define LDIM_ 128
#define MCL_  64
#define GDIM_ 256
#define OUTD_ (GDIM_ + LDIM_*MCL_)   // 8448
#define EPSV  1e-12f

// -------------------------------------------------------------------------
// Scratch (__device__ globals: allocation-free, graph-capture safe)
// -------------------------------------------------------------------------
__device__ __align__(256) __half g_xT[(size_t)B_ * HW_ * C_];     // pixel-major fp16
__device__ __align__(256) __half g_W1[1024 * C_];
__device__ __align__(256) __half g_W2[256 * HID_];
__device__ __align__(256) float  g_b1s[1024];
__device__ __align__(256) float  g_b2s[256];
__device__ __align__(256) __half g_Ht[(size_t)B_ * HW_ * 1024];   // pixel-major fp16
__device__ __align__(256) float  g_F[(size_t)B_ * LDIM_ * HW_];
__device__ __align__(256) float  g_P[(size_t)B_ * MCL_  * HW_];
__device__ __align__(256) float  g_aggp[4 * B_ * LDIM_ * MCL_];   // 4 HW-slices

// -------------------------------------------------------------------------
// PTX helpers (family-agnostic: mma.sync / ldmatrix / cp.async)
// -------------------------------------------------------------------------
__device__ __forceinline__ uint32_t smem_u32(const void* p) {
    uint32_t a;
    asm("{ .reg .u64 t; cvta.to.shared.u64 t, %1; cvt.u32.u64 %0, t; }" : "=r"(a) : "l"(p));
    return a;
}
__device__ __forceinline__ void cp16(uint32_t dst, const void* src) {
    asm volatile("cp.async.cg.shared.global [%0], [%1], 16;" :: "r"(dst), "l"(src));
}
#define CP_COMMIT() asm volatile("cp.async.commit_group;" ::: "memory")
#define CP_WAIT(n)  asm volatile("cp.async.wait_group %0;" :: "n"(n) : "memory")

__device__ __forceinline__ void ldsm4(uint32_t* r, uint32_t addr) {
    asm volatile("ldmatrix.sync.aligned.m8n8.x4.shared.b16 {%0,%1,%2,%3}, [%4];"
        : "=r"(r[0]), "=r"(r[1]), "=r"(r[2]), "=r"(r[3]) : "r"(addr));
}
__device__ __forceinline__ void mma16816(float* c, const uint32_t* a, const uint32_t* b) {
    asm volatile(
        "mma.sync.aligned.m16n8k16.row.col.f32.f16.f16.f32 "
        "{%0,%1,%2,%3}, {%4,%5,%6,%7}, {%8,%9}, {%0,%1,%2,%3};"
        : "+f"(c[0]), "+f"(c[1]), "+f"(c[2]), "+f"(c[3])
        : "r"(a[0]), "r"(a[1]), "r"(a[2]), "r"(a[3]), "r"(b[0]), "r"(b[1]));
}
__device__ __forceinline__ uint32_t swz(uint32_t off) {      // SW128-style 16B-chunk XOR
    return off ^ ((off >> 3) & 0x70);
}

// -------------------------------------------------------------------------
// Weight prep: stack + fp16 convert
// -------------------------------------------------------------------------
__global__ void prep_w1(const float* __restrict__ cf_w1, const float* __restrict__ cf_b1,
                        const float* __restrict__ sc_w1, const float* __restrict__ sc_b1)
{
    const int r = blockIdx.x;               // 0..1023
    const float* src = (r < HID_) ? cf_w1 + (size_t)r * C_ : sc_w1 + (size_t)(r - HID_) * C_;
    for (int i = threadIdx.x; i < C_; i += blockDim.x)
        g_W1[(size_t)r * C_ + i] = __float2half_rn(src[i]);
    if (threadIdx.x == 0)
        g_b1s[r] = (r < HID_) ? cf_b1[r] : sc_b1[r - HID_];
}

__global__ void prep_w2(const float* __restrict__ cf_w2, const float* __restrict__ cf_b2,
                        const float* __restrict__ sc_w2, const float* __restrict__ sc_b2)
{
    const int r = blockIdx.x;               // 0..255
    const float* src = (r < LDIM_) ? cf_w2 + (size_t)r * HID_
                     : (r < LDIM_ + MCL_) ? sc_w2 + (size_t)(r - LDIM_) * HID_ : nullptr;
    for (int i = threadIdx.x; i < HID_; i += blockDim.x)
        g_W2[(size_t)r * HID_ + i] = __float2half_rn(src ? src[i] : 0.f);
    if (threadIdx.x == 0)
        g_b2s[r] = (r < LDIM_) ? cf_b2[r] : (r < LDIM_ + MCL_) ? sc_b2[r - LDIM_] : 0.f;
}

// -------------------------------------------------------------------------
// x [B, C, HW] fp32  ->  xT [B, HW, C] fp16  (32x32 smem transpose)
// -------------------------------------------------------------------------
__global__ void __launch_bounds__(256)
transpose_x(const float* __restrict__ x)
{
    __shared__ float s[32][33];
    const int n0 = blockIdx.x * 32;
    const int c0 = blockIdx.y * 32;
    const int b  = blockIdx.z;
    const int tx = threadIdx.x & 31, ty = threadIdx.x >> 5;

    #pragma unroll
    for (int q = 0; q < 4; q++) {
        int c = ty + q * 8;
        s[c][tx] = x[((size_t)b * C_ + c0 + c) * HW_ + n0 + tx];
    }
    __syncthreads();

    const int n  = threadIdx.x >> 3;            // 0..31
    const int cs = (threadIdx.x & 7) * 4;       // 0..28
    __half h4[4];
    #pragma unroll
    for (int j = 0; j < 4; j++) h4[j] = __float2half_rn(s[cs + j][n]);
    size_t idx = ((size_t)b * HW_ + n0 + n) * C_ + c0 + cs;
    *(uint2*)(g_xT + idx) = *(const uint2*)h4;
}

// -------------------------------------------------------------------------
// Tensor-core GEMM via mma.sync (single-pass fp16, fp32 accum):
//   D[m,n] = sum_k A[m,k]*B[n,k]
// CTA = 128 x 128, 8 warps @ 64x32, BK=64, 3-stage cp.async pipeline.
// __launch_bounds__(256, 2): cap regs at 128 so TWO CTAs co-reside per SM
// (2 x 97KB smem = 194KB <= 228KB) -> 16 warps/SM to hide LDSM/MMA latency.
// EPI=1: bias+relu -> fp16 -> pixel-major Ht (via smem transpose).
// EPI=2: bias -> fp32 F (rows<128) / P (rows 128..191), channel-major.
// -------------------------------------------------------------------------
#define CTAM_ 128
#define GEMM_SMEM (1024 + 3 * (CTAM_ * 128 + 16384))   // 99328

template<int KDIM, int BSTR, int EPI>
__global__ void __launch_bounds__(256, 2)
gemm_mma(const __half* __restrict__ Ag, const __half* __restrict__ Bg,
         const float* __restrict__ bias,
         __half* __restrict__ OutH, float* __restrict__ OutF, float* __restrict__ OutP)
{
    constexpr int NCHUNK  = KDIM / 64;
    constexpr int A_BYTES = CTAM_ * 128;         // 128 x 64 fp16
    constexpr int STAGE   = A_BYTES + 16384;     // + 128 x 64 fp16 B tile
    constexpr int MB = 4, NB = 4, NBP = 2;       // warp tile 64 x 32

    extern __shared__ __align__(1024) char smem[];
    const uint32_t sbase = smem_u32(smem);
    float* bias_s = (float*)smem;                // 128 floats

    const int tid  = threadIdx.x;
    const int wid  = tid >> 5, lane = tid & 31;
    const int n0   = blockIdx.x * 128;
    const int m0   = blockIdx.y * CTAM_;
    const int bz   = blockIdx.z;
    const int koff = (EPI == 2) ? blockIdx.y * 512 : 0;

    const int warp_m = (wid >> 2) * 64;          // 0 or 64
    const int warp_n = (wid & 3) * 32;           // 0,32,64,96

    if (tid < CTAM_) bias_s[tid] = bias[m0 + tid];

    const size_t bRow = (size_t)bz * HW_ + n0;

    auto load_stage = [&](int c, int stage) {
        const uint32_t base = sbase + 1024 + stage * STAGE;
        #pragma unroll
        for (int q = 0; q < 4; q++) {
            int idx = tid + q * 256;
            int row = idx >> 3, seg = idx & 7;
            cp16(base + swz(row * 128 + seg * 16),
                 Ag + (size_t)(m0 + row) * KDIM + c * 64 + seg * 8);
        }
        const uint32_t bbuf = base + A_BYTES;
        #pragma unroll
        for (int q = 0; q < 4; q++) {
            int idx = tid + q * 256;
            int row = idx >> 3, seg = idx & 7;
            cp16(bbuf + swz(row * 128 + seg * 16),
                 Bg + (bRow + row) * BSTR + koff + c * 64 + seg * 8);
        }
        CP_COMMIT();
    };

    float acc[MB][NB][4];
    #pragma unroll
    for (int i = 0; i < MB; i++)
        #pragma unroll
        for (int j = 0; j < NB; j++)
            #pragma unroll
            for (int r = 0; r < 4; r++) acc[i][j][r] = 0.f;

    load_stage(0, 0);
    if (NCHUNK > 1) load_stage(1, 1);

    #pragma unroll 1
    for (int c = 0; c < NCHUNK; c++) {
        if (c + 1 < NCHUNK) { CP_WAIT(1); }       // chunk c complete
        else                { CP_WAIT(0); }
        __syncthreads();                          // data visible; stage (c+2)%3 free

        if (c + 2 < NCHUNK) load_stage(c + 2, (c + 2) % 3);

        const uint32_t aBase = sbase + 1024 + (c % 3) * STAGE;
        const uint32_t bBase = aBase + A_BYTES;

        #pragma unroll
        for (int s = 0; s < 4; s++) {
            uint32_t af[MB][4], bf[NB][2];
            #pragma unroll
            for (int mb = 0; mb < MB; mb++) {
                int row = warp_m + mb * 16 + (lane & 15);
                uint32_t off = swz(row * 128 + s * 32 + ((lane >> 4) << 4));
                ldsm4(af[mb], aBase + off);
            }
            #pragma unroll
            for (int nbp = 0; nbp < NBP; nbp++) {
                int grp = lane >> 3;
                int row = warp_n + nbp * 16 + ((grp >> 1) << 3) + (lane & 7);
                uint32_t off = swz(row * 128 + s * 32 + ((grp & 1) << 4));
                uint32_t t[4];
                ldsm4(t, bBase + off);
                bf[nbp*2][0] = t[0]; bf[nbp*2][1] = t[1];
                bf[nbp*2+1][0] = t[2]; bf[nbp*2+1][1] = t[3];
            }
            #pragma unroll
            for (int mb = 0; mb < MB; mb++)
                #pragma unroll
                for (int nb = 0; nb < NB; nb++) mma16816(acc[mb][nb], af[mb], bf[nb]);
        }
    }
    __syncthreads();   // all warps done with stage smem before epilogue reuse

    // ---------------- epilogue ----------------
    const int qr = lane >> 2, qc = (lane & 3) * 2;

    if (EPI == 1) {
        // stage to smem transposed: sC[n][m], pitch CTAM_+4
        constexpr int PITCH = CTAM_ + 4;
        float* sC = (float*)(smem + 1024);
        #pragma unroll
        for (int mb = 0; mb < MB; mb++)
            #pragma unroll
            for (int nb = 0; nb < NB; nb++)
                #pragma unroll
                for (int r = 0; r < 4; r++) {
                    int m = warp_m + mb * 16 + qr + ((r >> 1) << 3);
                    int n = warp_n + nb * 8 + qc + (r & 1);
                    sC[n * PITCH + m] = fmaxf(acc[mb][nb][r] + bias_s[m], 0.f);
                }
        __syncthreads();
        constexpr int SEGS = CTAM_ / 8;           // 16 segments of 8ch
        #pragma unroll
        for (int q = 0; q < (128 * SEGS) / 256; q++) {
            int idx = tid + q * 256;
            int px = idx / SEGS, sg = idx % SEGS;
            const float* src = sC + px * PITCH + sg * 8;
            __half h8[8];
            #pragma unroll
            for (int j = 0; j < 8; j++) h8[j] = __float2half_rn(src[j]);
            size_t g = ((size_t)bz * HW_ + n0 + px) * 1024 + m0 + sg * 8;
            *(uint4*)(OutH + g) = *(const uint4*)h8;
        }
    } else {
        #pragma unroll
        for (int mb = 0; mb < MB; mb++)
            #pragma unroll
            for (int nb = 0; nb < NB; nb++)
                #pragma unroll
                for (int r = 0; r < 4; r++) {
                    int ml = warp_m + mb * 16 + qr + ((r >> 1) << 3);
                    int n  = warp_n + nb * 8 + qc + (r & 1);
                    int row = m0 + ml;
                    float v = acc[mb][nb][r] + bias_s[ml];
                    if (row < LDIM_)
                        OutF[((size_t)bz * LDIM_ + row) * HW_ + n0 + n] = v;
                    else if (row < LDIM_ + MCL_)
                        OutP[((size_t)bz * MCL_ + row - LDIM_) * HW_ + n0 + n] = v;
                }
    }
}

// -------------------------------------------------------------------------
// Token MLP (unchanged, passing since R1)
// -------------------------------------------------------------------------
__global__ void __launch_bounds__(256)
token_kernel(const float* __restrict__ t,
             const float* __restrict__ w1, const float* __restrict__ b1,
             const float* __restrict__ w2, const float* __restrict__ b2,
             float* __restrict__ out)
{
    const int b = blockIdx.x;
    const int tid = threadIdx.x, warp = tid >> 5, lane = tid & 31;

    __shared__ float ts[C_];
    __shared__ float h[HID_];
    __shared__ float tk[GDIM_];
    __shared__ float red[8];

    for (int i = tid; i < C_; i += 256) ts[i] = t[(size_t)b * C_ + i];
    __syncthreads();

    for (int j = warp; j < HID_; j += 8) {
        const float* wr = w1 + (size_t)j * C_;
        float s = 0.f;
        for (int k = lane * 4; k < C_; k += 128) {
            float4 w4 = *(const float4*)(wr + k);
            float4 t4 = *(const float4*)(ts + k);
            s += w4.x*t4.x + w4.y*t4.y + w4.z*t4.z + w4.w*t4.w;
        }
        #pragma unroll
        for (int o = 16; o; o >>= 1) s += __shfl_xor_sync(0xffffffffu, s, o);
        if (lane == 0) h[j] = fmaxf(s + b1[j], 0.f);
    }
    __syncthreads();

    for (int j = warp; j < GDIM_; j += 8) {
        const float* wr = w2 + (size_t)j * HID_;
        float s = 0.f;
        for (int k = lane * 4; k < HID_; k += 128) {
            float4 w4 = *(const float4*)(wr + k);
            float4 h4 = *(const float4*)(h + k);
            s += w4.x*h4.x + w4.y*h4.y + w4.z*h4.z + w4.w*h4.w;
        }
        #pragma unroll
        for (int o = 16; o; o >>= 1) s += __shfl_xor_sync(0xffffffffu, s, o);
        if (lane == 0) tk[j] = s + b2[j];
    }
    __syncthreads();

    float v = tk[tid];
    float sq = v * v;
    #pragma unroll
    for (int o = 16; o; o >>= 1) sq += __shfl_xor_sync(0xffffffffu, sq, o);
    if (lane == 0) red[warp] = sq;
    __syncthreads();
    if (warp == 0) {
        float r = (lane < 8) ? red[lane] : 0.f;
        #pragma unroll
        for (int o = 4; o; o >>= 1) r += __shfl_xor_sync(0xffffffffu, r, o);
        if (lane == 0) red[0] = r;
    }
    __syncthreads();
    const float inv = 1.f / fmaxf(sqrtf(red[0]), EPSV);
    out[(size_t)b * OUTD_ + tid] = v * inv;
}

// -------------------------------------------------------------------------
// Log-space Sinkhorn (unchanged, passing since R1)
// -------------------------------------------------------------------------
__global__ void __launch_bounds__(1024)
sinkhorn_kernel(float* __restrict__ Pg, const float* __restrict__ dust)
{
    const int b = blockIdx.x;
    float* Z = Pg + (size_t)b * MCL_ * HW_;
    const int tid = threadIdx.x, warp = tid >> 5, lane = tid & 31;

    __shared__ float u[MCL_ + 1];
    __shared__ float v[HW_];

    const float alpha = dust[0];
    const float norm_c     = -logf((float)(MCL_ + HW_));
    const float log_mu     = norm_c;
    const float log_mu_bin = logf((float)(HW_ - MCL_)) + norm_c;
    const float log_nu     = norm_c;

    v[tid] = 0.f;
    __syncthreads();

    for (int it = 0; it < 3; it++) {
        for (int i = warp; i < MCL_; i += 32) {
            const float* zr = Z + (size_t)i * HW_;
            float mx = -3.0e38f, s = 0.f;
            for (int j = lane; j < HW_; j += 32) {
                float zv = zr[j] + v[j];
                if (zv > mx) { s = s * __expf(mx - zv) + 1.f; mx = zv; }
                else           s += __expf(zv - mx);
            }
            #pragma unroll
            for (int o = 16; o; o >>= 1) {
                float mo = __shfl_xor_sync(0xffffffffu, mx, o);
                float so = __shfl_xor_sync(0xffffffffu, s,  o);
                float m2 = fmaxf(mx, mo);
                s  = s * __expf(mx - m2) + so * __expf(mo - m2);
                mx = m2;
            }
            if (lane == 0) u[i] = log_mu - (mx + __logf(s));
        }
        if (warp == 0) {
            float mx = -3.0e38f, s = 0.f;
            for (int j = lane; j < HW_; j += 32) {
                float zv = v[j];
                if (zv > mx) { s = s * __expf(mx - zv) + 1.f; mx = zv; }
                else           s += __expf(zv - mx);
            }
            #pragma unroll
            for (int o = 16; o; o >>= 1) {
                float mo = __shfl_xor_sync(0xffffffffu, mx, o);
                float so = __shfl_xor_sync(0xffffffffu, s,  o);
                float m2 = fmaxf(mx, mo);
                s  = s * __expf(mx - m2) + so * __expf(mo - m2);
                mx = m2;
            }
            if (lane == 0) u[MCL_] = log_mu_bin - (alpha + mx + __logf(s));
        }
        __syncthreads();

        {
            const int j = tid;
            float mx = alpha + u[MCL_];
            float s  = 1.f;
            #pragma unroll 4
            for (int i = 0; i < MCL_; i++) {
                float zv = Z[(size_t)i * HW_ + j] + u[i];
                if (zv > mx) { s = s * __expf(mx - zv) + 1.f; mx = zv; }
                else           s += __expf(zv - mx);
            }
            v[j] = log_nu - (mx + __logf(s));
        }
        __syncthreads();
    }

    {
        const int j = tid;
        const float vj = v[j] - norm_c;
        #pragma unroll 4
        for (int i = 0; i < MCL_; i++) {
            size_t idx = (size_t)i * HW_ + j;
            Z[idx] = __expf(Z[idx] + u[i] + vj);
        }
    }
}

// -------------------------------------------------------------------------
// VLAD aggregation, stage 1: partial agg over an HW quarter (no atomics).
// -------------------------------------------------------------------------
__global__ void __launch_bounds__(256)
agg_partial(const float* __restrict__ Fg, const float* __restrict__ Pg)
{
    const int sl = blockIdx.x;               // 0..3
    const int b  = blockIdx.y;
    const float* f = Fg + (size_t)b * LDIM_ * HW_;
    const float* p = Pg + (size_t)b * MCL_  * HW_;

    __shared__ __align__(16) float sbuf[32 * 129 + 32 * 65];
    float (*Fs)[129] = (float(*)[129])sbuf;
    float (*Ps)[65]  = (float(*)[65])(sbuf + 32 * 129);

    const int tid = threadIdx.x;
    const int tr = tid >> 4, tc = tid & 15;

    float acc[8][4];
    #pragma unroll
    for (int i = 0; i < 8; i++)
        #pragma unroll
        for (int j = 0; j < 4; j++) acc[i][j] = 0.f;

    const int nbeg = sl * 256, nend = nbeg + 256;
    for (int n0 = nbeg; n0 < nend; n0 += 32) {
        #pragma unroll
        for (int q = 0; q < 16; q++) {
            int idx = tid + q * 256;
            int l = idx >> 5, n = idx & 31;
            Fs[n][l] = f[(size_t)l * HW_ + n0 + n];
        }
        #pragma unroll
        for (int q = 0; q < 8; q++) {
            int idx = tid + q * 256;
            int m = idx >> 5, n = idx & 31;
            Ps[n][m] = p[(size_t)m * HW_ + n0 + n];
        }
        __syncthreads();

        #pragma unroll
        for (int n = 0; n < 32; n++) {
            float rf[8], rp[4];
            #pragma unroll
            for (int i = 0; i < 8; i++) rf[i] = Fs[n][tr*8 + i];
            #pragma unroll
            for (int j = 0; j < 4; j++) rp[j] = Ps[n][tc*4 + j];
            #pragma unroll
            for (int i = 0; i < 8; i++)
                #pragma unroll
                for (int j = 0; j < 4; j++)
                    acc[i][j] = fmaf(rf[i], rp[j], acc[i][j]);
        }
        __syncthreads();
    }

    float* dst = g_aggp + (((size_t)sl * B_ + b) * LDIM_) * MCL_;
    #pragma unroll
    for (int i = 0; i < 8; i++)
        #pragma unroll
        for (int j = 0; j < 4; j++)
            dst[(size_t)(tr*8 + i) * MCL_ + tc*4 + j] = acc[i][j];
}

// -------------------------------------------------------------------------
// VLAD aggregation, stage 2: sum 4 partials, per-cluster L2 over l, write out.
// -------------------------------------------------------------------------
__global__ void __launch_bounds__(256)
agg_norm(float* __restrict__ out)
{
    const int b = blockIdx.x;
    __shared__ __align__(16) float sbuf[128 * 65 + 64];
    float (*Cs)[65] = (float(*)[65])sbuf;
    float* nrm = sbuf + 128 * 65;
    const int tid = threadIdx.x;

    #pragma unroll
    for (int q = 0; q < 32; q++) {
        int idx = tid + q * 256;               // 8192 = 128*64
        int l = idx >> 6, m = idx & 63;
        float s = 0.f;
        #pragma unroll
        for (int sl = 0; sl < 4; sl++)
            s += g_aggp[(((size_t)sl * B_ + b) * LDIM_ + l) * MCL_ + m];
        Cs[l][m] = s;
    }
    __syncthreads();
    if (tid < MCL_) {
        float s = 0.f;
        for (int l = 0; l < LDIM_; l++) { float c = Cs[l][tid]; s += c * c; }
        nrm[tid] = 1.f / fmaxf(sqrtf(s), EPSV);
    }
    __syncthreads();
    float* orow = out + (size_t)b * OUTD_ + GDIM_;
    #pragma unroll
    for (int q = 0; q < 32; q++) {
        int idx = tid + q * 256;
        int l = idx >> 6, m = idx & 63;
        orow[idx] = Cs[l][m] * nrm[m];
    }
}

// -------------------------------------------------------------------------
// Final row L2 normalization (unchanged, passing since R1)
// -------------------------------------------------------------------------
__global__ void __launch_bounds__(256)
rownorm_kernel(float* __restrict__ out)
{
    const int b = blockIdx.x;
    float* row = out + (size_t)b * OUTD_;
    const int tid = threadIdx.x, warp = tid >> 5, lane = tid & 31;
    __shared__ float red[8];

    float s = 0.f;
    for (int i = tid; i < OUTD_; i += 256) { float x = row[i]; s += x * x; }
    #pragma unroll
    for (int o = 16; o; o >>= 1) s += __shfl_xor_sync(0xffffffffu, s, o);
    if (lane == 0) red[warp] = s;
    __syncthreads();
    if (warp == 0) {
        float r = (lane < 8) ? red[lane] : 0.f;
        #pragma unroll
        for (int o = 4; o; o >>= 1) r += __shfl_xor_sync(0xffffffffu, r, o);
        if (lane == 0) red[0] = r;
    }
    __syncthreads();
    const float inv = 1.f / fmaxf(sqrtf(red[0]), EPSV);
    for (int i = tid; i < OUTD_; i += 256) row[i] *= inv;
}

// -------------------------------------------------------------------------
// Launch
// -------------------------------------------------------------------------
extern "C" void kernel_launch(void* const* d_in, const int* in_sizes, int n_in,
                              void* d_out, int out_size)
{
    const float* x     = (const float*)d_in[0];
    const float* t     = (const float*)d_in[1];
    const float* cf_w1 = (const float*)d_in[2];
    const float* cf_b1 = (const float*)d_in[3];
    const float* cf_w2 = (const float*)d_in[4];
    const float* cf_b2 = (const float*)d_in[5];
    const float* sc_w1 = (const float*)d_in[6];
    const float* sc_b1 = (const float*)d_in[7];
    const float* sc_w2 = (const float*)d_in[8];
    const float* sc_b2 = (const float*)d_in[9];
    const float* tk_w1 = (const float*)d_in[10];
    const float* tk_b1 = (const float*)d_in[11];
    const float* tk_w2 = (const float*)d_in[12];
    const float* tk_b2 = (const float*)d_in[13];
    const float* dust  = (const float*)d_in[14];
    float* out = (float*)d_out;

    __half *xT, *W1, *W2, *Ht;
    float *b1s, *b2s, *F, *P;
    cudaGetSymbolAddress((void**)&xT,  g_xT);
    cudaGetSymbolAddress((void**)&W1,  g_W1);
    cudaGetSymbolAddress((void**)&W2,  g_W2);
    cudaGetSymbolAddress((void**)&Ht,  g_Ht);
    cudaGetSymbolAddress((void**)&b1s, g_b1s);
    cudaGetSymbolAddress((void**)&b2s, g_b2s);
    cudaGetSymbolAddress((void**)&F,   g_F);
    cudaGetSymbolAddress((void**)&P,   g_P);

    cudaFuncSetAttribute((gemm_mma<1536, 1536, 1>),
                         cudaFuncAttributeMaxDynamicSharedMemorySize, GEMM_SMEM);
    cudaFuncSetAttribute((gemm_mma<512, 1024, 2>),
                         cudaFuncAttributeMaxDynamicSharedMemorySize, GEMM_SMEM);

    // Prep: weight stacking/fp16 + x transpose/fp16
    prep_w1<<<1024, 256>>>(cf_w1, cf_b1, sc_w1, sc_b1);
    prep_w2<<<256, 128>>>(cf_w2, cf_b2, sc_w2, sc_b2);
    transpose_x<<<dim3(HW_/32, C_/32, B_), 256>>>(x);

    // Layer 1 (fused cf+sc): Ht[b, px, 1024ch] = relu(W1 @ x + b1), fp16
    gemm_mma<1536, 1536, 1><<<dim3(HW_/128, 1024/128, B_), 256, GEMM_SMEM>>>(
        W1, xT, b1s, Ht, nullptr, nullptr);

    // Layer 2 (fused cf+sc): F fp32 [B,128,HW], P fp32 [B,64,HW]
    gemm_mma<512, 1024, 2><<<dim3(HW_/128, 2, B_), 256, GEMM_SMEM>>>(
        W2, Ht, b2s, nullptr, F, P);

    // Token MLP -> out[:, 0:256]
    token_kernel<<<B_, 256>>>(t, tk_w1, tk_b1, tk_w2, tk_b2, out);

    // Sinkhorn + parallel VLAD aggregation + final norm
    sinkhorn_kernel<<<B_, 1024>>>(P, dust);
    agg_partial<<<dim3(4, B_), 256>>>(F, P);
    agg_norm<<<B_, 256>>>(out);
    rownorm_kernel<<<B_, 256>>>(out);
}

// round 11
// speedup vs baseline: 4.9132x; 1.0362x over previous
#include <cuda_runtime.h>
#include <cuda_fp16.h>
#include <cooperative_groups.h>
#include <math.h>
#include <stdint.h>

namespace cg = cooperative_groups;

// Problem constants
#define B_    32
#define C_    1536
#define HW_   1024      // 32*32
#define HID_  512
#define LDIM_ 128
#define MCL_  64
#define GDIM_ 256
#define OUTD_ (GDIM_ + LDIM_*MCL_)   // 8448
#define EPSV  1e-12f

// -------------------------------------------------------------------------
// Scratch (__device__ globals: allocation-free, graph-capture safe)
// -------------------------------------------------------------------------
__device__ __align__(256) __half g_xT[(size_t)B_ * HW_ * C_];     // pixel-major fp16
__device__ __align__(256) __half g_W1[1024 * C_];
__device__ __align__(256) __half g_W2[256 * HID_];
__device__ __align__(256) float  g_b1s[1024];
__device__ __align__(256) float  g_b2s[256];
__device__ __align__(256) __half g_Ht[(size_t)B_ * HW_ * 1024];   // pixel-major fp16
__device__ __align__(256) float  g_F[(size_t)B_ * LDIM_ * HW_];
__device__ __align__(256) float  g_P[(size_t)B_ * MCL_  * HW_];
__device__ __align__(256) float  g_aggp[4 * B_ * LDIM_ * MCL_];   // 4 HW-slices

// -------------------------------------------------------------------------
// PTX helpers (family-agnostic: mma.sync / ldmatrix / cp.async)
// -------------------------------------------------------------------------
__device__ __forceinline__ uint32_t smem_u32(const void* p) {
    uint32_t a;
    asm("{ .reg .u64 t; cvta.to.shared.u64 t, %1; cvt.u32.u64 %0, t; }" : "=r"(a) : "l"(p));
    return a;
}
__device__ __forceinline__ void cp16(uint32_t dst, const void* src) {
    asm volatile("cp.async.cg.shared.global [%0], [%1], 16;" :: "r"(dst), "l"(src));
}
#define CP_COMMIT() asm volatile("cp.async.commit_group;" ::: "memory")
#define CP_WAIT(n)  asm volatile("cp.async.wait_group %0;" :: "n"(n) : "memory")

__device__ __forceinline__ void ldsm4(uint32_t* r, uint32_t addr) {
    asm volatile("ldmatrix.sync.aligned.m8n8.x4.shared.b16 {%0,%1,%2,%3}, [%4];"
        : "=r"(r[0]), "=r"(r[1]), "=r"(r[2]), "=r"(r[3]) : "r"(addr));
}
__device__ __forceinline__ void mma16816(float* c, const uint32_t* a, const uint32_t* b) {
    asm volatile(
        "mma.sync.aligned.m16n8k16.row.col.f32.f16.f16.f32 "
        "{%0,%1,%2,%3}, {%4,%5,%6,%7}, {%8,%9}, {%0,%1,%2,%3};"
        : "+f"(c[0]), "+f"(c[1]), "+f"(c[2]), "+f"(c[3])
        : "r"(a[0]), "r"(a[1]), "r"(a[2]), "r"(a[3]), "r"(b[0]), "r"(b[1]));
}
__device__ __forceinline__ uint32_t swz(uint32_t off) {      // SW128-style 16B-chunk XOR
    return off ^ ((off >> 3) & 0x70);
}

// -------------------------------------------------------------------------
// Weight prep: stack + fp16 convert
// -------------------------------------------------------------------------
__global__ void prep_w1(const float* __restrict__ cf_w1, const float* __restrict__ cf_b1,
                        const float* __restrict__ sc_w1, const float* __restrict__ sc_b1)
{
    const int r = blockIdx.x;               // 0..1023
    const float* src = (r < HID_) ? cf_w1 + (size_t)r * C_ : sc_w1 + (size_t)(r - HID_) * C_;
    for (int i = threadIdx.x; i < C_; i += blockDim.x)
        g_W1[(size_t)r * C_ + i] = __float2half_rn(src[i]);
    if (threadIdx.x == 0)
        g_b1s[r] = (r < HID_) ? cf_b1[r] : sc_b1[r - HID_];
}

__global__ void prep_w2(const float* __restrict__ cf_w2, const float* __restrict__ cf_b2,
                        const float* __restrict__ sc_w2, const float* __restrict__ sc_b2)
{
    const int r = blockIdx.x;               // 0..255
    const float* src = (r < LDIM_) ? cf_w2 + (size_t)r * HID_
                     : (r < LDIM_ + MCL_) ? sc_w2 + (size_t)(r - LDIM_) * HID_ : nullptr;
    for (int i = threadIdx.x; i < HID_; i += blockDim.x)
        g_W2[(size_t)r * HID_ + i] = __float2half_rn(src ? src[i] : 0.f);
    if (threadIdx.x == 0)
        g_b2s[r] = (r < LDIM_) ? cf_b2[r] : (r < LDIM_ + MCL_) ? sc_b2[r - LDIM_] : 0.f;
}

// -------------------------------------------------------------------------
// x [B, C, HW] fp32 -> xT [B, HW, C] fp16. Tile 64ch x 32px; float4 reads,
// 128B-contiguous per-pixel uint4 write groups.
// -------------------------------------------------------------------------
__global__ void __launch_bounds__(256)
transpose_x(const float* __restrict__ x)
{
    __shared__ float s[64][33];
    const int n0 = blockIdx.x * 32;
    const int c0 = blockIdx.y * 64;
    const int b  = blockIdx.z;
    const int tid = threadIdx.x;

    #pragma unroll
    for (int q = 0; q < 2; q++) {
        int idx = tid + q * 256;             // 512 float4s = 64 rows x 8
        int row = idx >> 3, p4 = (idx & 7) * 4;
        float4 v = *(const float4*)(x + ((size_t)b * C_ + c0 + row) * HW_ + n0 + p4);
        s[row][p4 + 0] = v.x; s[row][p4 + 1] = v.y;
        s[row][p4 + 2] = v.z; s[row][p4 + 3] = v.w;
    }
    __syncthreads();

    const int px = tid >> 3;                 // 0..31
    const int cgr = (tid & 7) * 8;           // 0..56
    __half h8[8];
    #pragma unroll
    for (int j = 0; j < 8; j++) h8[j] = __float2half_rn(s[cgr + j][px]);
    size_t idx = ((size_t)b * HW_ + n0 + px) * C_ + c0 + cgr;
    *(uint4*)(g_xT + idx) = *(const uint4*)h8;
}

// -------------------------------------------------------------------------
// Tensor-core GEMM via mma.sync (single-pass fp16, fp32 accum).
// CTA = 128x128, 8 warps @ 64x32, BK=64, 3-stage cp.async pipeline,
// __launch_bounds__(256,2) -> 2 CTAs/SM. (R10 winner, unchanged.)
// -------------------------------------------------------------------------
#define CTAM_ 128
#define GEMM_SMEM (1024 + 3 * (CTAM_ * 128 + 16384))   // 99328

template<int KDIM, int BSTR, int EPI>
__global__ void __launch_bounds__(256, 2)
gemm_mma(const __half* __restrict__ Ag, const __half* __restrict__ Bg,
         const float* __restrict__ bias,
         __half* __restrict__ OutH, float* __restrict__ OutF, float* __restrict__ OutP)
{
    constexpr int NCHUNK  = KDIM / 64;
    constexpr int A_BYTES = CTAM_ * 128;
    constexpr int STAGE   = A_BYTES + 16384;
    constexpr int MB = 4, NB = 4, NBP = 2;

    extern __shared__ __align__(1024) char smem[];
    const uint32_t sbase = smem_u32(smem);
    float* bias_s = (float*)smem;

    const int tid  = threadIdx.x;
    const int wid  = tid >> 5, lane = tid & 31;
    const int n0   = blockIdx.x * 128;
    const int m0   = blockIdx.y * CTAM_;
    const int bz   = blockIdx.z;
    const int koff = (EPI == 2) ? blockIdx.y * 512 : 0;

    const int warp_m = (wid >> 2) * 64;
    const int warp_n = (wid & 3) * 32;

    if (tid < CTAM_) bias_s[tid] = bias[m0 + tid];

    const size_t bRow = (size_t)bz * HW_ + n0;

    auto load_stage = [&](int c, int stage) {
        const uint32_t base = sbase + 1024 + stage * STAGE;
        #pragma unroll
        for (int q = 0; q < 4; q++) {
            int idx = tid + q * 256;
            int row = idx >> 3, seg = idx & 7;
            cp16(base + swz(row * 128 + seg * 16),
                 Ag + (size_t)(m0 + row) * KDIM + c * 64 + seg * 8);
        }
        const uint32_t bbuf = base + A_BYTES;
        #pragma unroll
        for (int q = 0; q < 4; q++) {
            int idx = tid + q * 256;
            int row = idx >> 3, seg = idx & 7;
            cp16(bbuf + swz(row * 128 + seg * 16),
                 Bg + (bRow + row) * BSTR + koff + c * 64 + seg * 8);
        }
        CP_COMMIT();
    };

    float acc[MB][NB][4];
    #pragma unroll
    for (int i = 0; i < MB; i++)
        #pragma unroll
        for (int j = 0; j < NB; j++)
            #pragma unroll
            for (int r = 0; r < 4; r++) acc[i][j][r] = 0.f;

    load_stage(0, 0);
    if (NCHUNK > 1) load_stage(1, 1);

    #pragma unroll 1
    for (int c = 0; c < NCHUNK; c++) {
        if (c + 1 < NCHUNK) { CP_WAIT(1); }
        else                { CP_WAIT(0); }
        __syncthreads();

        if (c + 2 < NCHUNK) load_stage(c + 2, (c + 2) % 3);

        const uint32_t aBase = sbase + 1024 + (c % 3) * STAGE;
        const uint32_t bBase = aBase + A_BYTES;

        #pragma unroll
        for (int s = 0; s < 4; s++) {
            uint32_t af[MB][4], bf[NB][2];
            #pragma unroll
            for (int mb = 0; mb < MB; mb++) {
                int row = warp_m + mb * 16 + (lane & 15);
                uint32_t off = swz(row * 128 + s * 32 + ((lane >> 4) << 4));
                ldsm4(af[mb], aBase + off);
            }
            #pragma unroll
            for (int nbp = 0; nbp < NBP; nbp++) {
                int grp = lane >> 3;
                int row = warp_n + nbp * 16 + ((grp >> 1) << 3) + (lane & 7);
                uint32_t off = swz(row * 128 + s * 32 + ((grp & 1) << 4));
                uint32_t t[4];
                ldsm4(t, bBase + off);
                bf[nbp*2][0] = t[0]; bf[nbp*2][1] = t[1];
                bf[nbp*2+1][0] = t[2]; bf[nbp*2+1][1] = t[3];
            }
            #pragma unroll
            for (int mb = 0; mb < MB; mb++)
                #pragma unroll
                for (int nb = 0; nb < NB; nb++) mma16816(acc[mb][nb], af[mb], bf[nb]);
        }
    }
    __syncthreads();

    const int qr = lane >> 2, qc = (lane & 3) * 2;

    if (EPI == 1) {
        constexpr int PITCH = CTAM_ + 4;
        float* sC = (float*)(smem + 1024);
        #pragma unroll
        for (int mb = 0; mb < MB; mb++)
            #pragma unroll
            for (int nb = 0; nb < NB; nb++)
                #pragma unroll
                for (int r = 0; r < 4; r++) {
                    int m = warp_m + mb * 16 + qr + ((r >> 1) << 3);
                    int n = warp_n + nb * 8 + qc + (r & 1);
                    sC[n * PITCH + m] = fmaxf(acc[mb][nb][r] + bias_s[m], 0.f);
                }
        __syncthreads();
        constexpr int SEGS = CTAM_ / 8;
        #pragma unroll
        for (int q = 0; q < (128 * SEGS) / 256; q++) {
            int idx = tid + q * 256;
            int px = idx / SEGS, sg = idx % SEGS;
            const float* src = sC + px * PITCH + sg * 8;
            __half h8[8];
            #pragma unroll
            for (int j = 0; j < 8; j++) h8[j] = __float2half_rn(src[j]);
            size_t g = ((size_t)bz * HW_ + n0 + px) * 1024 + m0 + sg * 8;
            *(uint4*)(OutH + g) = *(const uint4*)h8;
        }
    } else {
        #pragma unroll
        for (int mb = 0; mb < MB; mb++)
            #pragma unroll
            for (int nb = 0; nb < NB; nb++)
                #pragma unroll
                for (int r = 0; r < 4; r++) {
                    int ml = warp_m + mb * 16 + qr + ((r >> 1) << 3);
                    int n  = warp_n + nb * 8 + qc + (r & 1);
                    int row = m0 + ml;
                    float v = acc[mb][nb][r] + bias_s[ml];
                    if (row < LDIM_)
                        OutF[((size_t)bz * LDIM_ + row) * HW_ + n0 + n] = v;
                    else if (row < LDIM_ + MCL_)
                        OutP[((size_t)bz * MCL_ + row - LDIM_) * HW_ + n0 + n] = v;
                }
    }
}

// -------------------------------------------------------------------------
// Token MLP (unchanged, passing since R1)
// -------------------------------------------------------------------------
__global__ void __launch_bounds__(256)
token_kernel(const float* __restrict__ t,
             const float* __restrict__ w1, const float* __restrict__ b1,
             const float* __restrict__ w2, const float* __restrict__ b2,
             float* __restrict__ out)
{
    const int b = blockIdx.x;
    const int tid = threadIdx.x, warp = tid >> 5, lane = tid & 31;

    __shared__ float ts[C_];
    __shared__ float h[HID_];
    __shared__ float tk[GDIM_];
    __shared__ float red[8];

    for (int i = tid; i < C_; i += 256) ts[i] = t[(size_t)b * C_ + i];
    __syncthreads();

    for (int j = warp; j < HID_; j += 8) {
        const float* wr = w1 + (size_t)j * C_;
        float s = 0.f;
        for (int k = lane * 4; k < C_; k += 128) {
            float4 w4 = *(const float4*)(wr + k);
            float4 t4 = *(const float4*)(ts + k);
            s += w4.x*t4.x + w4.y*t4.y + w4.z*t4.z + w4.w*t4.w;
        }
        #pragma unroll
        for (int o = 16; o; o >>= 1) s += __shfl_xor_sync(0xffffffffu, s, o);
        if (lane == 0) h[j] = fmaxf(s + b1[j], 0.f);
    }
    __syncthreads();

    for (int j = warp; j < GDIM_; j += 8) {
        const float* wr = w2 + (size_t)j * HID_;
        float s = 0.f;
        for (int k = lane * 4; k < HID_; k += 128) {
            float4 w4 = *(const float4*)(wr + k);
            float4 h4 = *(const float4*)(h + k);
            s += w4.x*h4.x + w4.y*h4.y + w4.z*h4.z + w4.w*h4.w;
        }
        #pragma unroll
        for (int o = 16; o; o >>= 1) s += __shfl_xor_sync(0xffffffffu, s, o);
        if (lane == 0) tk[j] = s + b2[j];
    }
    __syncthreads();

    float v = tk[tid];
    float sq = v * v;
    #pragma unroll
    for (int o = 16; o; o >>= 1) sq += __shfl_xor_sync(0xffffffffu, sq, o);
    if (lane == 0) red[warp] = sq;
    __syncthreads();
    if (warp == 0) {
        float r = (lane < 8) ? red[lane] : 0.f;
        #pragma unroll
        for (int o = 4; o; o >>= 1) r += __shfl_xor_sync(0xffffffffu, r, o);
        if (lane == 0) red[0] = r;
    }
    __syncthreads();
    const float inv = 1.f / fmaxf(sqrtf(red[0]), EPSV);
    out[(size_t)b * OUTD_ + tid] = v * inv;
}

// -------------------------------------------------------------------------
// Cluster Sinkhorn: 2 CTAs per batch (column split), Z half resident in smem.
// Row-LSE partials exchanged via DSMEM once per iteration (double-buffered).
// Global traffic: read P once + write once (vs 7 sweeps).
// -------------------------------------------------------------------------
#define SK_COLS 512
#define SK_SMEM ((64 * SK_COLS + 72 + SK_COLS + 2 * 66 + 2 * 66) * 4)   // 134464 B

__global__ void __launch_bounds__(1024) __cluster_dims__(2, 1, 1)
sinkhorn_cluster(float* __restrict__ Pg, const float* __restrict__ dust)
{
    extern __shared__ float sk[];
    float* Zs = sk;                            // [64][512]
    float* u  = sk + 64 * SK_COLS;             // 65 (+pad to 72)
    float* v  = u + 72;                        // 512
    float* pm = v + SK_COLS;                   // 2 x 66 (iter parity)
    float* ps = pm + 2 * 66;                   // 2 x 66

    cg::cluster_group cluster = cg::this_cluster();
    const int rank = blockIdx.x & 1;
    const int b    = blockIdx.x >> 1;
    float* Z = Pg + (size_t)b * MCL_ * HW_ + rank * SK_COLS;
    const int tid = threadIdx.x, warp = tid >> 5, lane = tid & 31;

    const float alpha = dust[0];
    const float norm_c     = -logf((float)(MCL_ + HW_));
    const float log_mu     = norm_c;
    const float log_mu_bin = logf((float)(HW_ - MCL_)) + norm_c;
    const float log_nu     = norm_c;

    // load my column half of Z (coalesced 2KB rows)
    for (int idx = tid; idx < 64 * SK_COLS; idx += 1024)
        Zs[idx] = Z[(size_t)(idx >> 9) * HW_ + (idx & 511)];
    if (tid < SK_COLS) v[tid] = 0.f;
    __syncthreads();

    float* peer_pm = cluster.map_shared_rank(pm, rank ^ 1);
    float* peer_ps = cluster.map_shared_rank(ps, rank ^ 1);

    for (int it = 0; it < 3; it++) {
        float* pmx = pm + (it & 1) * 66;
        float* psm = ps + (it & 1) * 66;
        float* qmx = peer_pm + (it & 1) * 66;
        float* qsm = peer_ps + (it & 1) * 66;

        // ---- row partials over local 512 cols (warp per row) ----
        for (int i = warp; i < MCL_; i += 32) {
            const float* zr = Zs + i * SK_COLS;
            float mx = -3.0e38f, s = 0.f;
            for (int j = lane; j < SK_COLS; j += 32) {
                float zv = zr[j] + v[j];
                if (zv > mx) { s = s * __expf(mx - zv) + 1.f; mx = zv; }
                else           s += __expf(zv - mx);
            }
            #pragma unroll
            for (int o = 16; o; o >>= 1) {
                float mo = __shfl_xor_sync(0xffffffffu, mx, o);
                float so = __shfl_xor_sync(0xffffffffu, s,  o);
                float m2 = fmaxf(mx, mo);
                s  = s * __expf(mx - m2) + so * __expf(mo - m2);
                mx = m2;
            }
            if (lane == 0) { pmx[i] = mx; psm[i] = s; }
        }
        if (warp == 0) {   // dustbin partial: LSE over local v (alpha added at combine)
            float mx = -3.0e38f, s = 0.f;
            for (int j = lane; j < SK_COLS; j += 32) {
                float zv = v[j];
                if (zv > mx) { s = s * __expf(mx - zv) + 1.f; mx = zv; }
                else           s += __expf(zv - mx);
            }
            #pragma unroll
            for (int o = 16; o; o >>= 1) {
                float mo = __shfl_xor_sync(0xffffffffu, mx, o);
                float so = __shfl_xor_sync(0xffffffffu, s,  o);
                float m2 = fmaxf(mx, mo);
                s  = s * __expf(mx - m2) + so * __expf(mo - m2);
                mx = m2;
            }
            if (lane == 0) { pmx[MCL_] = mx; psm[MCL_] = s; }
        }
        cluster.sync();    // partials visible cluster-wide

        // ---- combine with peer partials -> u ----
        if (tid <= MCL_) {
            float mA = pmx[tid], sA = psm[tid];
            float mB = qmx[tid], sB = qsm[tid];
            float M = fmaxf(mA, mB);
            float lse = M + __logf(sA * __expf(mA - M) + sB * __expf(mB - M));
            u[tid] = (tid < MCL_) ? (log_mu - lse) : (log_mu_bin - (alpha + lse));
        }
        __syncthreads();

        // ---- col pass: fully local ----
        if (tid < SK_COLS) {
            const int j = tid;
            float mx = alpha + u[MCL_];
            float s  = 1.f;
            #pragma unroll 4
            for (int i = 0; i < MCL_; i++) {
                float zv = Zs[i * SK_COLS + j] + u[i];
                if (zv > mx) { s = s * __expf(mx - zv) + 1.f; mx = zv; }
                else           s += __expf(zv - mx);
            }
            v[j] = log_nu - (mx + __logf(s));
        }
        __syncthreads();
    }

    // ---- final: P = exp(Z + u + v - norm) ----
    for (int idx = tid; idx < 64 * SK_COLS; idx += 1024) {
        int i = idx >> 9, j = idx & 511;
        Z[(size_t)i * HW_ + j] = __expf(Zs[idx] + u[i] + v[j] - norm_c);
    }
    cluster.sync();    // peers done reading my smem before exit
}

// -------------------------------------------------------------------------
// VLAD aggregation, stage 1: partial agg over an HW quarter (no atomics).
// -------------------------------------------------------------------------
__global__ void __launch_bounds__(256)
agg_partial(const float* __restrict__ Fg, const float* __restrict__ Pg)
{
    const int sl = blockIdx.x;               // 0..3
    const int b  = blockIdx.y;
    const float* f = Fg + (size_t)b * LDIM_ * HW_;
    const float* p = Pg + (size_t)b * MCL_  * HW_;

    __shared__ __align__(16) float sbuf[32 * 129 + 32 * 65];
    float (*Fs)[129] = (float(*)[129])sbuf;
    float (*Ps)[65]  = (float(*)[65])(sbuf + 32 * 129);

    const int tid = threadIdx.x;
    const int tr = tid >> 4, tc = tid & 15;

    float acc[8][4];
    #pragma unroll
    for (int i = 0; i < 8; i++)
        #pragma unroll
        for (int j = 0; j < 4; j++) acc[i][j] = 0.f;

    const int nbeg = sl * 256, nend = nbeg + 256;
    for (int n0 = nbeg; n0 < nend; n0 += 32) {
        #pragma unroll
        for (int q = 0; q < 16; q++) {
            int idx = tid + q * 256;
            int l = idx >> 5, n = idx & 31;
            Fs[n][l] = f[(size_t)l * HW_ + n0 + n];
        }
        #pragma unroll
        for (int q = 0; q < 8; q++) {
            int idx = tid + q * 256;
            int m = idx >> 5, n = idx & 31;
            Ps[n][m] = p[(size_t)m * HW_ + n0 + n];
        }
        __syncthreads();

        #pragma unroll
        for (int n = 0; n < 32; n++) {
            float rf[8], rp[4];
            #pragma unroll
            for (int i = 0; i < 8; i++) rf[i] = Fs[n][tr*8 + i];
            #pragma unroll
            for (int j = 0; j < 4; j++) rp[j] = Ps[n][tc*4 + j];
            #pragma unroll
            for (int i = 0; i < 8; i++)
                #pragma unroll
                for (int j = 0; j < 4; j++)
                    acc[i][j] = fmaf(rf[i], rp[j], acc[i][j]);
        }
        __syncthreads();
    }

    float* dst = g_aggp + (((size_t)sl * B_ + b) * LDIM_) * MCL_;
    #pragma unroll
    for (int i = 0; i < 8; i++)
        #pragma unroll
        for (int j = 0; j < 4; j++)
            dst[(size_t)(tr*8 + i) * MCL_ + tc*4 + j] = acc[i][j];
}

// -------------------------------------------------------------------------
// VLAD aggregation, stage 2: sum 4 partials, per-cluster L2 over l, write out.
// -------------------------------------------------------------------------
__global__ void __launch_bounds__(256)
agg_norm(float* __restrict__ out)
{
    const int b = blockIdx.x;
    __shared__ __align__(16) float sbuf[128 * 65 + 64];
    float (*Cs)[65] = (float(*)[65])sbuf;
    float* nrm = sbuf + 128 * 65;
    const int tid = threadIdx.x;

    #pragma unroll
    for (int q = 0; q < 32; q++) {
        int idx = tid + q * 256;               // 8192 = 128*64
        int l = idx >> 6, m = idx & 63;
        float s = 0.f;
        #pragma unroll
        for (int sl = 0; sl < 4; sl++)
            s += g_aggp[(((size_t)sl * B_ + b) * LDIM_ + l) * MCL_ + m];
        Cs[l][m] = s;
    }
    __syncthreads();
    if (tid < MCL_) {
        float s = 0.f;
        for (int l = 0; l < LDIM_; l++) { float c = Cs[l][tid]; s += c * c; }
        nrm[tid] = 1.f / fmaxf(sqrtf(s), EPSV);
    }
    __syncthreads();
    float* orow = out + (size_t)b * OUTD_ + GDIM_;
    #pragma unroll
    for (int q = 0; q < 32; q++) {
        int idx = tid + q * 256;
        int l = idx >> 6, m = idx & 63;
        orow[idx] = Cs[l][m] * nrm[m];
    }
}

// -------------------------------------------------------------------------
// Final row L2 normalization (unchanged, passing since R1)
// -------------------------------------------------------------------------
__global__ void __launch_bounds__(256)
rownorm_kernel(float* __restrict__ out)
{
    const int b = blockIdx.x;
    float* row = out + (size_t)b * OUTD_;
    const int tid = threadIdx.x, warp = tid >> 5, lane = tid & 31;
    __shared__ float red[8];

    float s = 0.f;
    for (int i = tid; i < OUTD_; i += 256) { float x = row[i]; s += x * x; }
    #pragma unroll
    for (int o = 16; o; o >>= 1) s += __shfl_xor_sync(0xffffffffu, s, o);
    if (lane == 0) red[warp] = s;
    __syncthreads();
    if (warp == 0) {
        float r = (lane < 8) ? red[lane] : 0.f;
        #pragma unroll
        for (int o = 4; o; o >>= 1) r += __shfl_xor_sync(0xffffffffu, r, o);
        if (lane == 0) red[0] = r;
    }
    __syncthreads();
    const float inv = 1.f / fmaxf(sqrtf(red[0]), EPSV);
    for (int i = tid; i < OUTD_; i += 256) row[i] *= inv;
}

// -------------------------------------------------------------------------
// Launch
// -------------------------------------------------------------------------
extern "C" void kernel_launch(void* const* d_in, const int* in_sizes, int n_in,
                              void* d_out, int out_size)
{
    const float* x     = (const float*)d_in[0];
    const float* t     = (const float*)d_in[1];
    const float* cf_w1 = (const float*)d_in[2];
    const float* cf_b1 = (const float*)d_in[3];
    const float* cf_w2 = (const float*)d_in[4];
    const float* cf_b2 = (const float*)d_in[5];
    const float* sc_w1 = (const float*)d_in[6];
    const float* sc_b1 = (const float*)d_in[7];
    const float* sc_w2 = (const float*)d_in[8];
    const float* sc_b2 = (const float*)d_in[9];
    const float* tk_w1 = (const float*)d_in[10];
    const float* tk_b1 = (const float*)d_in[11];
    const float* tk_w2 = (const float*)d_in[12];
    const float* tk_b2 = (const float*)d_in[13];
    const float* dust  = (const float*)d_in[14];
    float* out = (float*)d_out;

    __half *xT, *W1, *W2, *Ht;
    float *b1s, *b2s, *F, *P;
    cudaGetSymbolAddress((void**)&xT,  g_xT);
    cudaGetSymbolAddress((void**)&W1,  g_W1);
    cudaGetSymbolAddress((void**)&W2,  g_W2);
    cudaGetSymbolAddress((void**)&Ht,  g_Ht);
    cudaGetSymbolAddress((void**)&b1s, g_b1s);
    cudaGetSymbolAddress((void**)&b2s, g_b2s);
    cudaGetSymbolAddress((void**)&F,   g_F);
    cudaGetSymbolAddress((void**)&P,   g_P);

    cudaFuncSetAttribute((gemm_mma<1536, 1536, 1>),
                         cudaFuncAttributeMaxDynamicSharedMemorySize, GEMM_SMEM);
    cudaFuncSetAttribute((gemm_mma<512, 1024, 2>),
                         cudaFuncAttributeMaxDynamicSharedMemorySize, GEMM_SMEM);
    cudaFuncSetAttribute(sinkhorn_cluster,
                         cudaFuncAttributeMaxDynamicSharedMemorySize, SK_SMEM);

    // Prep: weight stacking/fp16 + x transpose/fp16
    prep_w1<<<1024, 256>>>(cf_w1, cf_b1, sc_w1, sc_b1);
    prep_w2<<<256, 128>>>(cf_w2, cf_b2, sc_w2, sc_b2);
    transpose_x<<<dim3(HW_/32, C_/64, B_), 256>>>(x);

    // Layer 1 (fused cf+sc): Ht[b, px, 1024ch] = relu(W1 @ x + b1), fp16
    gemm_mma<1536, 1536, 1><<<dim3(HW_/128, 1024/128, B_), 256, GEMM_SMEM>>>(
        W1, xT, b1s, Ht, nullptr, nullptr);

    // Layer 2 (fused cf+sc): F fp32 [B,128,HW], P fp32 [B,64,HW]
    gemm_mma<512, 1024, 2><<<dim3(HW_/128, 2, B_), 256, GEMM_SMEM>>>(
        W2, Ht, b2s, nullptr, F, P);

    // Token MLP -> out[:, 0:256]
    token_kernel<<<B_, 256>>>(t, tk_w1, tk_b1, tk_w2, tk_b2, out);

    // Cluster Sinkhorn (2 CTAs/batch, smem-resident) + VLAD agg + norms
    sinkhorn_cluster<<<2 * B_, 1024, SK_SMEM>>>(P, dust);
    agg_partial<<<dim3(4, B_), 256>>>(F, P);
    agg_norm<<<B_, 256>>>(out);
    rownorm_kernel<<<B_, 256>>>(out);
}

// round 12
// speedup vs baseline: 4.9810x; 1.0138x over previous
#include <cuda_runtime.h>
#include <cuda_fp16.h>
#include <cooperative_groups.h>
#include <math.h>
#include <stdint.h>

namespace cg = cooperative_groups;

// Problem constants
#define B_    32
#define C_    1536
#define HW_   1024      // 32*32
#define HID_  512
#define LDIM_ 128
#define MCL_  64
#define GDIM_ 256
#define OUTD_ (GDIM_ + LDIM_*MCL_)   // 8448
#define EPSV  1e-12f

// -------------------------------------------------------------------------
// Scratch (__device__ globals: allocation-free, graph-capture safe)
// -------------------------------------------------------------------------
__device__ __align__(256) __half g_xT[(size_t)B_ * HW_ * C_];     // pixel-major fp16
__device__ __align__(256) __half g_W1[1024 * C_];
__device__ __align__(256) __half g_W2[256 * HID_];                // 0..127 cf, 128..191 sc
__device__ __align__(256) float  g_b1s[1024];
__device__ __align__(256) float  g_b2s[256];
__device__ __align__(256) __half g_Ht[(size_t)B_ * HW_ * 1024];   // pixel-major fp16
__device__ __align__(256) float  g_F[(size_t)B_ * LDIM_ * HW_];
__device__ __align__(256) float  g_P[(size_t)B_ * MCL_  * HW_];
__device__ __align__(256) float  g_aggp[4 * B_ * LDIM_ * MCL_];   // 4 HW-slices

// -------------------------------------------------------------------------
// PTX helpers
// -------------------------------------------------------------------------
__device__ __forceinline__ uint32_t smem_u32(const void* p) {
    uint32_t a;
    asm("{ .reg .u64 t; cvta.to.shared.u64 t, %1; cvt.u32.u64 %0, t; }" : "=r"(a) : "l"(p));
    return a;
}
__device__ __forceinline__ void cp16(uint32_t dst, const void* src) {
    asm volatile("cp.async.cg.shared.global [%0], [%1], 16;" :: "r"(dst), "l"(src));
}
#define CP_COMMIT() asm volatile("cp.async.commit_group;" ::: "memory")
#define CP_WAIT(n)  asm volatile("cp.async.wait_group %0;" :: "n"(n) : "memory")

__device__ __forceinline__ void ldsm4(uint32_t* r, uint32_t addr) {
    asm volatile("ldmatrix.sync.aligned.m8n8.x4.shared.b16 {%0,%1,%2,%3}, [%4];"
        : "=r"(r[0]), "=r"(r[1]), "=r"(r[2]), "=r"(r[3]) : "r"(addr));
}
__device__ __forceinline__ void mma16816(float* c, const uint32_t* a, const uint32_t* b) {
    asm volatile(
        "mma.sync.aligned.m16n8k16.row.col.f32.f16.f16.f32 "
        "{%0,%1,%2,%3}, {%4,%5,%6,%7}, {%8,%9}, {%0,%1,%2,%3};"
        : "+f"(c[0]), "+f"(c[1]), "+f"(c[2]), "+f"(c[3])
        : "r"(a[0]), "r"(a[1]), "r"(a[2]), "r"(a[3]), "r"(b[0]), "r"(b[1]));
}
__device__ __forceinline__ uint32_t swz(uint32_t off) {
    return off ^ ((off >> 3) & 0x70);
}

// -------------------------------------------------------------------------
// prep_all: one launch for weight stacking/fp16 + token MLP.
// blocks [0,1024): W1 rows; [1024,1280): W2 rows; [1280,1312): token batches.
// -------------------------------------------------------------------------
__global__ void __launch_bounds__(256)
prep_all(const float* __restrict__ cf_w1, const float* __restrict__ cf_b1,
         const float* __restrict__ sc_w1, const float* __restrict__ sc_b1,
         const float* __restrict__ cf_w2, const float* __restrict__ cf_b2,
         const float* __restrict__ sc_w2, const float* __restrict__ sc_b2,
         const float* __restrict__ t,
         const float* __restrict__ tw1, const float* __restrict__ tb1,
         const float* __restrict__ tw2, const float* __restrict__ tb2,
         float* __restrict__ out)
{
    const int bx = blockIdx.x;
    const int tid = threadIdx.x;

    if (bx < 1024) {                          // --- W1 row ---
        const int r = bx;
        const float* src = (r < HID_) ? cf_w1 + (size_t)r * C_ : sc_w1 + (size_t)(r - HID_) * C_;
        for (int i = tid; i < C_; i += 256)
            g_W1[(size_t)r * C_ + i] = __float2half_rn(src[i]);
        if (tid == 0)
            g_b1s[r] = (r < HID_) ? cf_b1[r] : sc_b1[r - HID_];
        return;
    }
    if (bx < 1280) {                          // --- W2 row ---
        const int r = bx - 1024;
        const float* src = (r < LDIM_) ? cf_w2 + (size_t)r * HID_
                         : (r < LDIM_ + MCL_) ? sc_w2 + (size_t)(r - LDIM_) * HID_ : nullptr;
        for (int i = tid; i < HID_; i += 256)
            g_W2[(size_t)r * HID_ + i] = __float2half_rn(src ? src[i] : 0.f);
        if (tid == 0)
            g_b2s[r] = (r < LDIM_) ? cf_b2[r] : (r < LDIM_ + MCL_) ? sc_b2[r - LDIM_] : 0.f;
        return;
    }

    // --- token MLP for batch b ---
    const int b = bx - 1280;
    const int warp = tid >> 5, lane = tid & 31;

    __shared__ float ts[C_];
    __shared__ float h[HID_];
    __shared__ float tk[GDIM_];
    __shared__ float red[8];

    for (int i = tid; i < C_; i += 256) ts[i] = t[(size_t)b * C_ + i];
    __syncthreads();

    for (int j = warp; j < HID_; j += 8) {
        const float* wr = tw1 + (size_t)j * C_;
        float s = 0.f;
        for (int k = lane * 4; k < C_; k += 128) {
            float4 w4 = *(const float4*)(wr + k);
            float4 t4 = *(const float4*)(ts + k);
            s += w4.x*t4.x + w4.y*t4.y + w4.z*t4.z + w4.w*t4.w;
        }
        #pragma unroll
        for (int o = 16; o; o >>= 1) s += __shfl_xor_sync(0xffffffffu, s, o);
        if (lane == 0) h[j] = fmaxf(s + tb1[j], 0.f);
    }
    __syncthreads();

    for (int j = warp; j < GDIM_; j += 8) {
        const float* wr = tw2 + (size_t)j * HID_;
        float s = 0.f;
        for (int k = lane * 4; k < HID_; k += 128) {
            float4 w4 = *(const float4*)(wr + k);
            float4 h4 = *(const float4*)(h + k);
            s += w4.x*h4.x + w4.y*h4.y + w4.z*h4.z + w4.w*h4.w;
        }
        #pragma unroll
        for (int o = 16; o; o >>= 1) s += __shfl_xor_sync(0xffffffffu, s, o);
        if (lane == 0) tk[j] = s + tb2[j];
    }
    __syncthreads();

    float v = tk[tid];
    float sq = v * v;
    #pragma unroll
    for (int o = 16; o; o >>= 1) sq += __shfl_xor_sync(0xffffffffu, sq, o);
    if (lane == 0) red[warp] = sq;
    __syncthreads();
    if (warp == 0) {
        float r = (lane < 8) ? red[lane] : 0.f;
        #pragma unroll
        for (int o = 4; o; o >>= 1) r += __shfl_xor_sync(0xffffffffu, r, o);
        if (lane == 0) red[0] = r;
    }
    __syncthreads();
    const float inv = 1.f / fmaxf(sqrtf(red[0]), EPSV);
    out[(size_t)b * OUTD_ + tid] = v * inv;
}

// -------------------------------------------------------------------------
// x [B, C, HW] fp32 -> xT [B, HW, C] fp16. 64ch x 64px tiles.
// -------------------------------------------------------------------------
__global__ void __launch_bounds__(256)
transpose_x(const float* __restrict__ x)
{
    __shared__ float s[64][65];
    const int n0 = blockIdx.x * 64;
    const int c0 = blockIdx.y * 64;
    const int b  = blockIdx.z;
    const int tid = threadIdx.x;

    #pragma unroll
    for (int q = 0; q < 4; q++) {
        int idx = tid + q * 256;             // 1024 float4s = 64 rows x 16
        int row = idx >> 4, p4 = (idx & 15) * 4;
        float4 v = *(const float4*)(x + ((size_t)b * C_ + c0 + row) * HW_ + n0 + p4);
        s[row][p4 + 0] = v.x; s[row][p4 + 1] = v.y;
        s[row][p4 + 2] = v.z; s[row][p4 + 3] = v.w;
    }
    __syncthreads();

    #pragma unroll
    for (int q = 0; q < 2; q++) {
        int idx = tid + q * 256;             // 512 = 64px x 8 ch-groups
        int px = idx >> 3, cgr = (idx & 7) * 8;
        __half h8[8];
        #pragma unroll
        for (int j = 0; j < 8; j++) h8[j] = __float2half_rn(s[cgr + j][px]);
        size_t g = ((size_t)b * HW_ + n0 + px) * C_ + c0 + cgr;
        *(uint4*)(g_xT + g) = *(const uint4*)h8;
    }
}

// -------------------------------------------------------------------------
// Tensor-core GEMM via mma.sync (single-pass fp16, fp32 accum).
// CTA = CTAM x 128 (CTAM in {128,64}), 8 warps @ (CTAM/2)x32, BK=64,
// 3-stage cp.async pipeline, __launch_bounds__(256,2).
// EPI=1: bias+relu -> fp16 -> pixel-major Ht (CTAM=128 only).
// EPI=2: bias -> fp32, contiguous M rows to Out (F or P), channel-major.
// KOFF: column offset into the B operand rows (Ht channel half).
// -------------------------------------------------------------------------
template<int KDIM, int BSTR, int EPI, int CTAM, int KOFF>
__global__ void __launch_bounds__(256, 2)
gemm_mma(const __half* __restrict__ Ag, const __half* __restrict__ Bg,
         const float* __restrict__ bias,
         __half* __restrict__ OutH, float* __restrict__ OutF)
{
    constexpr int NCHUNK  = KDIM / 64;
    constexpr int A_BYTES = CTAM * 128;
    constexpr int STAGE   = A_BYTES + 16384;
    constexpr int MB = CTAM / 32, NB = 4, NBP = 2;  // warp tile (CTAM/2) x 32
    constexpr int AIT = (CTAM * 8) / 256;

    extern __shared__ __align__(1024) char smem[];
    const uint32_t sbase = smem_u32(smem);
    float* bias_s = (float*)smem;

    const int tid  = threadIdx.x;
    const int wid  = tid >> 5, lane = tid & 31;
    const int n0   = blockIdx.x * 128;
    const int m0   = blockIdx.y * CTAM;
    const int bz   = blockIdx.z;

    const int warp_m = (wid >> 2) * (CTAM / 2);
    const int warp_n = (wid & 3) * 32;

    if (tid < CTAM) bias_s[tid] = bias[m0 + tid];

    const size_t bRow = (size_t)bz * HW_ + n0;

    auto load_stage = [&](int c, int stage) {
        const uint32_t base = sbase + 1024 + stage * STAGE;
        #pragma unroll
        for (int q = 0; q < AIT; q++) {
            int idx = tid + q * 256;
            int row = idx >> 3, seg = idx & 7;
            cp16(base + swz(row * 128 + seg * 16),
                 Ag + (size_t)(m0 + row) * KDIM + c * 64 + seg * 8);
        }
        const uint32_t bbuf = base + A_BYTES;
        #pragma unroll
        for (int q = 0; q < 4; q++) {
            int idx = tid + q * 256;
            int row = idx >> 3, seg = idx & 7;
            cp16(bbuf + swz(row * 128 + seg * 16),
                 Bg + (bRow + row) * BSTR + KOFF + c * 64 + seg * 8);
        }
        CP_COMMIT();
    };

    float acc[MB][NB][4];
    #pragma unroll
    for (int i = 0; i < MB; i++)
        #pragma unroll
        for (int j = 0; j < NB; j++)
            #pragma unroll
            for (int r = 0; r < 4; r++) acc[i][j][r] = 0.f;

    load_stage(0, 0);
    if (NCHUNK > 1) load_stage(1, 1);

    #pragma unroll 1
    for (int c = 0; c < NCHUNK; c++) {
        if (c + 1 < NCHUNK) { CP_WAIT(1); }
        else                { CP_WAIT(0); }
        __syncthreads();

        if (c + 2 < NCHUNK) load_stage(c + 2, (c + 2) % 3);

        const uint32_t aBase = sbase + 1024 + (c % 3) * STAGE;
        const uint32_t bBase = aBase + A_BYTES;

        #pragma unroll
        for (int s = 0; s < 4; s++) {
            uint32_t af[MB][4], bf[NB][2];
            #pragma unroll
            for (int mb = 0; mb < MB; mb++) {
                int row = warp_m + mb * 16 + (lane & 15);
                uint32_t off = swz(row * 128 + s * 32 + ((lane >> 4) << 4));
                ldsm4(af[mb], aBase + off);
            }
            #pragma unroll
            for (int nbp = 0; nbp < NBP; nbp++) {
                int grp = lane >> 3;
                int row = warp_n + nbp * 16 + ((grp >> 1) << 3) + (lane & 7);
                uint32_t off = swz(row * 128 + s * 32 + ((grp & 1) << 4));
                uint32_t t[4];
                ldsm4(t, bBase + off);
                bf[nbp*2][0] = t[0]; bf[nbp*2][1] = t[1];
                bf[nbp*2+1][0] = t[2]; bf[nbp*2+1][1] = t[3];
            }
            #pragma unroll
            for (int mb = 0; mb < MB; mb++)
                #pragma unroll
                for (int nb = 0; nb < NB; nb++) mma16816(acc[mb][nb], af[mb], bf[nb]);
        }
    }
    __syncthreads();

    const int qr = lane >> 2, qc = (lane & 3) * 2;

    if (EPI == 1) {
        constexpr int PITCH = CTAM + 4;
        float* sC = (float*)(smem + 1024);
        #pragma unroll
        for (int mb = 0; mb < MB; mb++)
            #pragma unroll
            for (int nb = 0; nb < NB; nb++)
                #pragma unroll
                for (int r = 0; r < 4; r++) {
                    int m = warp_m + mb * 16 + qr + ((r >> 1) << 3);
                    int n = warp_n + nb * 8 + qc + (r & 1);
                    sC[n * PITCH + m] = fmaxf(acc[mb][nb][r] + bias_s[m], 0.f);
                }
        __syncthreads();
        constexpr int SEGS = CTAM / 8;
        #pragma unroll
        for (int q = 0; q < (128 * SEGS) / 256; q++) {
            int idx = tid + q * 256;
            int px = idx / SEGS, sg = idx % SEGS;
            const float* src = sC + px * PITCH + sg * 8;
            __half h8[8];
            #pragma unroll
            for (int j = 0; j < 8; j++) h8[j] = __float2half_rn(src[j]);
            size_t g = ((size_t)bz * HW_ + n0 + px) * 1024 + m0 + sg * 8;
            *(uint4*)(OutH + g) = *(const uint4*)h8;
        }
    } else {
        #pragma unroll
        for (int mb = 0; mb < MB; mb++)
            #pragma unroll
            for (int nb = 0; nb < NB; nb++)
                #pragma unroll
                for (int r = 0; r < 4; r++) {
                    int ml = warp_m + mb * 16 + qr + ((r >> 1) << 3);
                    int n  = warp_n + nb * 8 + qc + (r & 1);
                    OutF[((size_t)bz * CTAM + m0 + ml) * HW_ + n0 + n]
                        = acc[mb][nb][r] + bias_s[ml];
                }
    }
}

#define SMEM_G(CTAM) (1024 + 3 * ((CTAM) * 128 + 16384))

// -------------------------------------------------------------------------
// Cluster Sinkhorn (R11 winner, unchanged)
// -------------------------------------------------------------------------
#define SK_COLS 512
#define SK_SMEM ((64 * SK_COLS + 72 + SK_COLS + 2 * 66 + 2 * 66) * 4)

__global__ void __launch_bounds__(1024) __cluster_dims__(2, 1, 1)
sinkhorn_cluster(float* __restrict__ Pg, const float* __restrict__ dust)
{
    extern __shared__ float sk[];
    float* Zs = sk;
    float* u  = sk + 64 * SK_COLS;
    float* v  = u + 72;
    float* pm = v + SK_COLS;
    float* ps = pm + 2 * 66;

    cg::cluster_group cluster = cg::this_cluster();
    const int rank = blockIdx.x & 1;
    const int b    = blockIdx.x >> 1;
    float* Z = Pg + (size_t)b * MCL_ * HW_ + rank * SK_COLS;
    const int tid = threadIdx.x, warp = tid >> 5, lane = tid & 31;

    const float alpha = dust[0];
    const float norm_c     = -logf((float)(MCL_ + HW_));
    const float log_mu     = norm_c;
    const float log_mu_bin = logf((float)(HW_ - MCL_)) + norm_c;
    const float log_nu     = norm_c;

    for (int idx = tid; idx < 64 * SK_COLS; idx += 1024)
        Zs[idx] = Z[(size_t)(idx >> 9) * HW_ + (idx & 511)];
    if (tid < SK_COLS) v[tid] = 0.f;
    __syncthreads();

    float* peer_pm = cluster.map_shared_rank(pm, rank ^ 1);
    float* peer_ps = cluster.map_shared_rank(ps, rank ^ 1);

    for (int it = 0; it < 3; it++) {
        float* pmx = pm + (it & 1) * 66;
        float* psm = ps + (it & 1) * 66;
        float* qmx = peer_pm + (it & 1) * 66;
        float* qsm = peer_ps + (it & 1) * 66;

        for (int i = warp; i < MCL_; i += 32) {
            const float* zr = Zs + i * SK_COLS;
            float mx = -3.0e38f, s = 0.f;
            for (int j = lane; j < SK_COLS; j += 32) {
                float zv = zr[j] + v[j];
                if (zv > mx) { s = s * __expf(mx - zv) + 1.f; mx = zv; }
                else           s += __expf(zv - mx);
            }
            #pragma unroll
            for (int o = 16; o; o >>= 1) {
                float mo = __shfl_xor_sync(0xffffffffu, mx, o);
                float so = __shfl_xor_sync(0xffffffffu, s,  o);
                float m2 = fmaxf(mx, mo);
                s  = s * __expf(mx - m2) + so * __expf(mo - m2);
                mx = m2;
            }
            if (lane == 0) { pmx[i] = mx; psm[i] = s; }
        }
        if (warp == 0) {
            float mx = -3.0e38f, s = 0.f;
            for (int j = lane; j < SK_COLS; j += 32) {
                float zv = v[j];
                if (zv > mx) { s = s * __expf(mx - zv) + 1.f; mx = zv; }
                else           s += __expf(zv - mx);
            }
            #pragma unroll
            for (int o = 16; o; o >>= 1) {
                float mo = __shfl_xor_sync(0xffffffffu, mx, o);
                float so = __shfl_xor_sync(0xffffffffu, s,  o);
                float m2 = fmaxf(mx, mo);
                s  = s * __expf(mx - m2) + so * __expf(mo - m2);
                mx = m2;
            }
            if (lane == 0) { pmx[MCL_] = mx; psm[MCL_] = s; }
        }
        cluster.sync();

        if (tid <= MCL_) {
            float mA = pmx[tid], sA = psm[tid];
            float mB = qmx[tid], sB = qsm[tid];
            float M = fmaxf(mA, mB);
            float lse = M + __logf(sA * __expf(mA - M) + sB * __expf(mB - M));
            u[tid] = (tid < MCL_) ? (log_mu - lse) : (log_mu_bin - (alpha + lse));
        }
        __syncthreads();

        if (tid < SK_COLS) {
            const int j = tid;
            float mx = alpha + u[MCL_];
            float s  = 1.f;
            #pragma unroll 4
            for (int i = 0; i < MCL_; i++) {
                float zv = Zs[i * SK_COLS + j] + u[i];
                if (zv > mx) { s = s * __expf(mx - zv) + 1.f; mx = zv; }
                else           s += __expf(zv - mx);
            }
            v[j] = log_nu - (mx + __logf(s));
        }
        __syncthreads();
    }

    for (int idx = tid; idx < 64 * SK_COLS; idx += 1024) {
        int i = idx >> 9, j = idx & 511;
        Z[(size_t)i * HW_ + j] = __expf(Zs[idx] + u[i] + v[j] - norm_c);
    }
    cluster.sync();
}

// -------------------------------------------------------------------------
// VLAD aggregation, stage 1: partial agg over an HW quarter.
// -------------------------------------------------------------------------
__global__ void __launch_bounds__(256)
agg_partial(const float* __restrict__ Fg, const float* __restrict__ Pg)
{
    const int sl = blockIdx.x;
    const int b  = blockIdx.y;
    const float* f = Fg + (size_t)b * LDIM_ * HW_;
    const float* p = Pg + (size_t)b * MCL_  * HW_;

    __shared__ __align__(16) float sbuf[32 * 129 + 32 * 65];
    float (*Fs)[129] = (float(*)[129])sbuf;
    float (*Ps)[65]  = (float(*)[65])(sbuf + 32 * 129);

    const int tid = threadIdx.x;
    const int tr = tid >> 4, tc = tid & 15;

    float acc[8][4];
    #pragma unroll
    for (int i = 0; i < 8; i++)
        #pragma unroll
        for (int j = 0; j < 4; j++) acc[i][j] = 0.f;

    const int nbeg = sl * 256, nend = nbeg + 256;
    for (int n0 = nbeg; n0 < nend; n0 += 32) {
        #pragma unroll
        for (int q = 0; q < 16; q++) {
            int idx = tid + q * 256;
            int l = idx >> 5, n = idx & 31;
            Fs[n][l] = f[(size_t)l * HW_ + n0 + n];
        }
        #pragma unroll
        for (int q = 0; q < 8; q++) {
            int idx = tid + q * 256;
            int m = idx >> 5, n = idx & 31;
            Ps[n][m] = p[(size_t)m * HW_ + n0 + n];
        }
        __syncthreads();

        #pragma unroll
        for (int n = 0; n < 32; n++) {
            float rf[8], rp[4];
            #pragma unroll
            for (int i = 0; i < 8; i++) rf[i] = Fs[n][tr*8 + i];
            #pragma unroll
            for (int j = 0; j < 4; j++) rp[j] = Ps[n][tc*4 + j];
            #pragma unroll
            for (int i = 0; i < 8; i++)
                #pragma unroll
                for (int j = 0; j < 4; j++)
                    acc[i][j] = fmaf(rf[i], rp[j], acc[i][j]);
        }
        __syncthreads();
    }

    float* dst = g_aggp + (((size_t)sl * B_ + b) * LDIM_) * MCL_;
    #pragma unroll
    for (int i = 0; i < 8; i++)
        #pragma unroll
        for (int j = 0; j < 4; j++)
            dst[(size_t)(tr*8 + i) * MCL_ + tc*4 + j] = acc[i][j];
}

// -------------------------------------------------------------------------
// agg_final: sum 4 partials, per-cluster L2, THEN full-row L2 (incl. token
// part already in out) — fused agg_norm + rownorm.
// -------------------------------------------------------------------------
__global__ void __launch_bounds__(256)
agg_final(float* __restrict__ out)
{
    const int b = blockIdx.x;
    __shared__ __align__(16) float sbuf[128 * 65 + 64 + 8];
    float (*Cs)[65] = (float(*)[65])sbuf;
    float* nrm = sbuf + 128 * 65;
    float* red = nrm + 64;
    const int tid = threadIdx.x, warp = tid >> 5, lane = tid & 31;
    float* row = out + (size_t)b * OUTD_;

    #pragma unroll
    for (int q = 0; q < 32; q++) {
        int idx = tid + q * 256;
        int l = idx >> 6, m = idx & 63;
        float s = 0.f;
        #pragma unroll
        for (int sl = 0; sl < 4; sl++)
            s += g_aggp[(((size_t)sl * B_ + b) * LDIM_ + l) * MCL_ + m];
        Cs[l][m] = s;
    }
    __syncthreads();
    if (tid < MCL_) {
        float s = 0.f;
        for (int l = 0; l < LDIM_; l++) { float c = Cs[l][tid]; s += c * c; }
        nrm[tid] = 1.f / fmaxf(sqrtf(s), EPSV);
    }
    __syncthreads();

    // row sumsq: token part (one value per thread) + agg part (scaled)
    const float vtok = row[tid];
    float sq = vtok * vtok;
    #pragma unroll
    for (int q = 0; q < 32; q++) {
        int idx = tid + q * 256;
        int l = idx >> 6, m = idx & 63;
        float val = Cs[l][m] * nrm[m];
        sq += val * val;
    }
    #pragma unroll
    for (int o = 16; o; o >>= 1) sq += __shfl_xor_sync(0xffffffffu, sq, o);
    if (lane == 0) red[warp] = sq;
    __syncthreads();
    if (warp == 0) {
        float r = (lane < 8) ? red[lane] : 0.f;
        #pragma unroll
        for (int o = 4; o; o >>= 1) r += __shfl_xor_sync(0xffffffffu, r, o);
        if (lane == 0) red[0] = r;
    }
    __syncthreads();
    const float inv = 1.f / fmaxf(sqrtf(red[0]), EPSV);

    row[tid] = vtok * inv;
    #pragma unroll
    for (int q = 0; q < 32; q++) {
        int idx = tid + q * 256;
        int l = idx >> 6, m = idx & 63;
        row[GDIM_ + idx] = Cs[l][m] * nrm[m] * inv;
    }
}

// -------------------------------------------------------------------------
// Launch
// -------------------------------------------------------------------------
extern "C" void kernel_launch(void* const* d_in, const int* in_sizes, int n_in,
                              void* d_out, int out_size)
{
    const float* x     = (const float*)d_in[0];
    const float* t     = (const float*)d_in[1];
    const float* cf_w1 = (const float*)d_in[2];
    const float* cf_b1 = (const float*)d_in[3];
    const float* cf_w2 = (const float*)d_in[4];
    const float* cf_b2 = (const float*)d_in[5];
    const float* sc_w1 = (const float*)d_in[6];
    const float* sc_b1 = (const float*)d_in[7];
    const float* sc_w2 = (const float*)d_in[8];
    const float* sc_b2 = (const float*)d_in[9];
    const float* tk_w1 = (const float*)d_in[10];
    const float* tk_b1 = (const float*)d_in[11];
    const float* tk_w2 = (const float*)d_in[12];
    const float* tk_b2 = (const float*)d_in[13];
    const float* dust  = (const float*)d_in[14];
    float* out = (float*)d_out;

    __half *xT, *W1, *W2, *Ht;
    float *b1s, *b2s, *F, *P;
    cudaGetSymbolAddress((void**)&xT,  g_xT);
    cudaGetSymbolAddress((void**)&W1,  g_W1);
    cudaGetSymbolAddress((void**)&W2,  g_W2);
    cudaGetSymbolAddress((void**)&Ht,  g_Ht);
    cudaGetSymbolAddress((void**)&b1s, g_b1s);
    cudaGetSymbolAddress((void**)&b2s, g_b2s);
    cudaGetSymbolAddress((void**)&F,   g_F);
    cudaGetSymbolAddress((void**)&P,   g_P);

    cudaFuncSetAttribute((gemm_mma<1536, 1536, 1, 128, 0>),
                         cudaFuncAttributeMaxDynamicSharedMemorySize, SMEM_G(128));
    cudaFuncSetAttribute((gemm_mma<512, 1024, 2, 128, 0>),
                         cudaFuncAttributeMaxDynamicSharedMemorySize, SMEM_G(128));
    cudaFuncSetAttribute((gemm_mma<512, 1024, 2, 64, 512>),
                         cudaFuncAttributeMaxDynamicSharedMemorySize, SMEM_G(64));
    cudaFuncSetAttribute(sinkhorn_cluster,
                         cudaFuncAttributeMaxDynamicSharedMemorySize, SK_SMEM);

    // Prep (weights fp16 + token MLP) + x transpose
    prep_all<<<1312, 256>>>(cf_w1, cf_b1, sc_w1, sc_b1,
                            cf_w2, cf_b2, sc_w2, sc_b2,
                            t, tk_w1, tk_b1, tk_w2, tk_b2, out);
    transpose_x<<<dim3(HW_/64, C_/64, B_), 256>>>(x);

    // Layer 1 (fused cf+sc): Ht = relu(W1 @ x + b1), fp16 pixel-major
    gemm_mma<1536, 1536, 1, 128, 0><<<dim3(HW_/128, 8, B_), 256, SMEM_G(128)>>>(
        W1, xT, b1s, Ht, nullptr);

    // Layer 2, exact-size: F (M=128, cf half) and P (M=64, sc half)
    gemm_mma<512, 1024, 2, 128, 0><<<dim3(HW_/128, 1, B_), 256, SMEM_G(128)>>>(
        W2, Ht, b2s, nullptr, F);
    gemm_mma<512, 1024, 2, 64, 512><<<dim3(HW_/128, 1, B_), 256, SMEM_G(64)>>>(
        W2 + (size_t)LDIM_ * HID_, Ht, b2s + LDIM_, nullptr, P);

    // Cluster Sinkhorn + VLAD agg + fused final norms
    sinkhorn_cluster<<<2 * B_, 1024, SK_SMEM>>>(P, dust);
    agg_partial<<<dim3(4, B_), 256>>>(F, P);
    agg_final<<<B_, 256>>>(out);
}